// round 6
// baseline (speedup 1.0000x reference)
#include <cuda_runtime.h>
#include <cuda_bf16.h>
#include <cstdint>
#include <math.h>

#define HID 2048
#define SEQ 2048
#define NH  16
#define HD  128
#define BATCH 2
#define M_ROWS (BATCH*SEQ)   // 4096

// ---------------------------------------------------------------------------
// Scratch (__device__ globals; no allocation allowed)
// ---------------------------------------------------------------------------
__device__ __nv_bfloat16 g_xh[(size_t)M_ROWS * HID];
__device__ __nv_bfloat16 g_xl[(size_t)M_ROWS * HID];
__device__ __nv_bfloat16 g_wqh[(size_t)HID * HID];
__device__ __nv_bfloat16 g_wql[(size_t)HID * HID];
__device__ __nv_bfloat16 g_wkh[(size_t)HID * HID];
__device__ __nv_bfloat16 g_wkl[(size_t)HID * HID];
__device__ __nv_bfloat16 g_wvh[(size_t)HID * HID];
__device__ __nv_bfloat16 g_wvl[(size_t)HID * HID];
__device__ __nv_bfloat16 g_woh[(size_t)HID * HID];
__device__ __nv_bfloat16 g_wol[(size_t)HID * HID];
__device__ __nv_bfloat16 g_qh[(size_t)M_ROWS * HID];
__device__ __nv_bfloat16 g_ql[(size_t)M_ROWS * HID];
__device__ __nv_bfloat16 g_kh[(size_t)M_ROWS * HID];
__device__ __nv_bfloat16 g_kl[(size_t)M_ROWS * HID];
__device__ __nv_bfloat16 g_vh[(size_t)M_ROWS * HID];
__device__ __nv_bfloat16 g_vl[(size_t)M_ROWS * HID];
__device__ __nv_bfloat16 g_cxh[(size_t)M_ROWS * HID];
__device__ __nv_bfloat16 g_cxl[(size_t)M_ROWS * HID];
__device__ float g_sin[SEQ * (HD/2)];
__device__ float g_cos[SEQ * (HD/2)];

// ---------------------------------------------------------------------------
// helpers
// ---------------------------------------------------------------------------
__device__ __forceinline__ uint32_t smem_to_u32(const void* p) {
    uint32_t a;
    asm("{ .reg .u64 t; cvta.to.shared.u64 t, %1; cvt.u32.u64 %0, t; }"
        : "=r"(a) : "l"(p));
    return a;
}

__device__ __forceinline__ void cp16(uint32_t dst, const void* src) {
    asm volatile("cp.async.cg.shared.global [%0], [%1], 16;"
                 :: "r"(dst), "l"(src) : "memory");
}

__device__ __forceinline__ void ldsm_x4(uint32_t* r, uint32_t addr) {
    asm volatile("ldmatrix.sync.aligned.m8n8.x4.shared.b16 {%0,%1,%2,%3}, [%4];"
                 : "=r"(r[0]), "=r"(r[1]), "=r"(r[2]), "=r"(r[3]) : "r"(addr));
}

__device__ __forceinline__ void ldsm_x4_t(uint32_t* r, uint32_t addr) {
    asm volatile("ldmatrix.sync.aligned.m8n8.x4.trans.shared.b16 {%0,%1,%2,%3}, [%4];"
                 : "=r"(r[0]), "=r"(r[1]), "=r"(r[2]), "=r"(r[3]) : "r"(addr));
}

__device__ __forceinline__ void mma_bf16(float* c, const uint32_t* a,
                                         uint32_t b0, uint32_t b1) {
    asm volatile(
        "mma.sync.aligned.m16n8k16.row.col.f32.bf16.bf16.f32 "
        "{%0,%1,%2,%3}, {%4,%5,%6,%7}, {%8,%9}, {%0,%1,%2,%3};"
        : "+f"(c[0]), "+f"(c[1]), "+f"(c[2]), "+f"(c[3])
        : "r"(a[0]), "r"(a[1]), "r"(a[2]), "r"(a[3]), "r"(b0), "r"(b1));
}

__device__ __forceinline__ void splitf(float v, __nv_bfloat16& h, __nv_bfloat16& l) {
    h = __float2bfloat16_rn(v);
    l = __float2bfloat16_rn(v - __bfloat162float(h));
}
__device__ __forceinline__ uint32_t pk2(__nv_bfloat16 a, __nv_bfloat16 b) {
    __nv_bfloat162 t = __halves2bfloat162(a, b);
    return *reinterpret_cast<uint32_t*>(&t);
}

// fast 2^t on the FMA pipe. t <= 0 expected; clamped at -30.
__device__ __forceinline__ float fexp2(float t) {
    t = fmaxf(t, -30.0f);
    const float fi = t + 12582912.0f;          // 1.5*2^23 round-to-int
    const float r  = fi - 12582912.0f;
    const float f  = t - r;
    float p = 1.3333558146e-3f;
    p = fmaf(p, f, 9.6181291076e-3f);
    p = fmaf(p, f, 5.5504108665e-2f);
    p = fmaf(p, f, 2.4022650696e-1f);
    p = fmaf(p, f, 6.9314718056e-1f);
    p = fmaf(p, f, 1.0f);
    const int e = __float_as_int(fi) - 0x4B400000;
    return __int_as_float(__float_as_int(p) + (e << 23));
}

// ---------------------------------------------------------------------------
// Prep kernels
// ---------------------------------------------------------------------------
__global__ void rope_table_kernel(float* __restrict__ st, float* __restrict__ ct) {
    int idx = blockIdx.x * blockDim.x + threadIdx.x;   // SEQ*64
    int s = idx >> 6, j = idx & 63;
    double f = exp(-0.14391156831212787 * (double)j);  // 10000^(-2j/128)
    double sn, cs;
    sincos((double)s * f, &sn, &cs);
    st[idx] = (float)sn;
    ct[idx] = (float)cs;
}

__global__ void __launch_bounds__(256) split_x_kernel(
    const float4* __restrict__ X, uint2* __restrict__ H, uint2* __restrict__ L)
{
    size_t i = (size_t)blockIdx.x * blockDim.x + threadIdx.x;
    float4 v = X[i];
    __nv_bfloat16 h0, l0, h1, l1, h2, l2, h3, l3;
    splitf(v.x, h0, l0); splitf(v.y, h1, l1);
    splitf(v.z, h2, l2); splitf(v.w, h3, l3);
    H[i] = make_uint2(pk2(h0, h1), pk2(h2, h3));
    L[i] = make_uint2(pk2(l0, l1), pk2(l2, l3));
}

// W [K][N] fp32 -> Wt [N][K] bf16 hi/lo (transpose + split)
__global__ void __launch_bounds__(256) wtrans_kernel(
    const float* __restrict__ W, __nv_bfloat16* __restrict__ Th,
    __nv_bfloat16* __restrict__ Tl)
{
    __shared__ float t[32][33];
    const int n0 = blockIdx.x * 32, k0 = blockIdx.y * 32;
    const int tx = threadIdx.x, ty = threadIdx.y;   // (32, 8)
#pragma unroll
    for (int i = 0; i < 4; i++)
        t[ty + 8 * i][tx] = W[(size_t)(k0 + ty + 8 * i) * HID + n0 + tx];
    __syncthreads();
#pragma unroll
    for (int i = 0; i < 4; i++) {
        float v = t[tx][ty + 8 * i];
        __nv_bfloat16 h, l;
        splitf(v, h, l);
        const size_t o = (size_t)(n0 + ty + 8 * i) * HID + k0 + tx;
        Th[o] = h;
        Tl[o] = l;
    }
}

// ---------------------------------------------------------------------------
// mma.sync split-bf16 GEMM.  BM=256, BN=128, BK=32, 8 warps (warp 64x64).
// Per k-chunk: load Ah/Al/Bh/Bl ONCE, run all 3 products from same stage.
// 3-stage cp.async pipeline; 60KB/stage.
// mode 0: fp32 out (+bias); mode 1: bias+RoPE, scaled, split-bf16 out;
// mode 2: bias only, split-bf16 out.
// ---------------------------------------------------------------------------
#define AT 20480                       // A tile padded: 256 rows x 80B
#define BT 10240                       // B tile padded: 128 rows x 80B
#define STAGE_BYTES (2*AT + 2*BT)      // 61440: [Ah][Al][Bh][Bl]
#define STAGES 3
#define GSMEM (STAGES * STAGE_BYTES)   // 184320
#define NKCHUNK (HID / 32)             // 64

__device__ __forceinline__ void gemm_mma_body(
    const __nv_bfloat16* __restrict__ Ah, const __nv_bfloat16* __restrict__ Al,
    const __nv_bfloat16* __restrict__ Bh, const __nv_bfloat16* __restrict__ Bl,
    const float* __restrict__ bias,
    float* __restrict__ Yf, __nv_bfloat16* __restrict__ Yh,
    __nv_bfloat16* __restrict__ Yl, float oscale,
    const float* __restrict__ stab, const float* __restrict__ ctab, int mode)
{
    extern __shared__ __align__(128) char smem[];
    const uint32_t sb = smem_to_u32(smem);
    const int tid = threadIdx.x;
    const int wid = tid >> 5, lane = tid & 31;
    const int warp_m = wid & 3, warp_n = wid >> 2;   // 4 x 2 warps
    const int bm = blockIdx.y * 256, bn = blockIdx.x * 128;

    // ldmatrix base offsets (within a stage)
    const uint32_t aoff =
        (warp_m * 64 + ((lane >> 3) & 1) * 8 + (lane & 7)) * 80 +
        ((lane >> 4) * 8) * 2;
    const uint32_t boff =
        (warp_n * 64 + ((lane >> 4) & 1) * 8 + (lane & 7)) * 80 +
        (((lane >> 3) & 1) * 8) * 2;
    const uint32_t aBase = sb + aoff;             // Ah; +AT for Al
    const uint32_t bBase = sb + 2 * AT + boff;    // Bh; +BT for Bl

    float acc[4][8][4];
#pragma unroll
    for (int mt = 0; mt < 4; mt++)
#pragma unroll
        for (int nt = 0; nt < 8; nt++)
#pragma unroll
            for (int e = 0; e < 4; e++) acc[mt][nt][e] = 0.0f;

    const int brow = tid >> 1, bh2 = (tid & 1) * 2;

    auto issue = [&](int c, int stg) {
        const int k0 = c << 5;
        const uint32_t so = sb + stg * STAGE_BYTES;
        const __nv_bfloat16* ahp = Ah + (size_t)(bm + tid) * HID + k0;
        const __nv_bfloat16* alp = Al + (size_t)(bm + tid) * HID + k0;
#pragma unroll
        for (int i = 0; i < 4; i++) {
            cp16(so + tid * 80 + i * 16, ahp + i * 8);
            cp16(so + AT + tid * 80 + i * 16, alp + i * 8);
        }
        const __nv_bfloat16* bhp = Bh + (size_t)(bn + brow) * HID + k0 + bh2 * 8;
        const __nv_bfloat16* blp = Bl + (size_t)(bn + brow) * HID + k0 + bh2 * 8;
#pragma unroll
        for (int j = 0; j < 2; j++) {
            cp16(so + 2 * AT + brow * 80 + (bh2 + j) * 16, bhp + j * 8);
            cp16(so + 2 * AT + BT + brow * 80 + (bh2 + j) * 16, blp + j * 8);
        }
    };

#pragma unroll
    for (int s = 0; s < STAGES; s++) {
        issue(s, s);
        asm volatile("cp.async.commit_group;" ::: "memory");
    }

    int stg = 0;
    for (int c = 0; c < NKCHUNK; c++) {
        asm volatile("cp.async.wait_group 2;" ::: "memory");
        __syncthreads();
        const uint32_t so = stg * STAGE_BYTES;
#pragma unroll
        for (int ks = 0; ks < 2; ks++) {
            uint32_t ah[4][4], al[4][4], bh[4][4], bl[4][4];
#pragma unroll
            for (int mt = 0; mt < 4; mt++) {
                ldsm_x4(ah[mt], aBase + so + mt * 1280 + ks * 32);
                ldsm_x4(al[mt], aBase + so + AT + mt * 1280 + ks * 32);
            }
#pragma unroll
            for (int ng = 0; ng < 4; ng++) {
                ldsm_x4(bh[ng], bBase + so + ng * 1280 + ks * 32);
                ldsm_x4(bl[ng], bBase + so + BT + ng * 1280 + ks * 32);
            }
#pragma unroll
            for (int mt = 0; mt < 4; mt++)
#pragma unroll
                for (int ng = 0; ng < 4; ng++) {
                    mma_bf16(acc[mt][2 * ng],     ah[mt], bh[ng][0], bh[ng][1]);
                    mma_bf16(acc[mt][2 * ng],     al[mt], bh[ng][0], bh[ng][1]);
                    mma_bf16(acc[mt][2 * ng],     ah[mt], bl[ng][0], bl[ng][1]);
                    mma_bf16(acc[mt][2 * ng + 1], ah[mt], bh[ng][2], bh[ng][3]);
                    mma_bf16(acc[mt][2 * ng + 1], al[mt], bh[ng][2], bh[ng][3]);
                    mma_bf16(acc[mt][2 * ng + 1], ah[mt], bl[ng][2], bl[ng][3]);
                }
        }
        __syncthreads();
        if (c + STAGES < NKCHUNK) issue(c + STAGES, stg);
        asm volatile("cp.async.commit_group;" ::: "memory");
        stg = (stg == STAGES - 1) ? 0 : stg + 1;
    }

    // epilogue
    const int r0 = bm + warp_m * 64 + (lane >> 2);
    const int c0 = bn + warp_n * 64 + (lane & 3) * 2;
#pragma unroll
    for (int mt = 0; mt < 4; mt++) {
#pragma unroll
        for (int half = 0; half < 2; half++) {
            const int row = r0 + mt * 16 + half * 8;
            const int s = row & (SEQ - 1);
#pragma unroll
            for (int nt = 0; nt < 8; nt++) {
                const int col = c0 + nt * 8;
                float e  = acc[mt][nt][half * 2 + 0] + bias[col];
                float od = acc[mt][nt][half * 2 + 1] + bias[col + 1];
                if (mode == 1) {
                    const int j = (col & (HD - 1)) >> 1;
                    const float sn = stab[(s << 6) + j];
                    const float cs = ctab[(s << 6) + j];
                    float re = e * cs - od * sn;
                    float ro = od * cs + e * sn;
                    e = re * oscale;
                    od = ro * oscale;
                }
                if (mode == 0) {
                    float2 r;
                    r.x = e; r.y = od;
                    *(float2*)(Yf + (size_t)row * HID + col) = r;
                } else {
                    __nv_bfloat16 h0, l0, h1, l1;
                    splitf(e, h0, l0);
                    splitf(od, h1, l1);
                    *(uint32_t*)(Yh + (size_t)row * HID + col) = pk2(h0, h1);
                    *(uint32_t*)(Yl + (size_t)row * HID + col) = pk2(l0, l1);
                }
            }
        }
    }
}

// Q scale folds softmax 1/sqrt(128) AND log2(e) (base-2 softmax)
#define QSCALE (0.08838834764831843f * 1.4426950408889634f)

__global__ void __launch_bounds__(256, 1) mma_gemm_qkv_kernel(
    const __nv_bfloat16* xh, const __nv_bfloat16* xl,
    const __nv_bfloat16* wqh, const __nv_bfloat16* wql,
    const __nv_bfloat16* wkh, const __nv_bfloat16* wkl,
    const __nv_bfloat16* wvh, const __nv_bfloat16* wvl,
    const float* bq, const float* bk, const float* bv,
    __nv_bfloat16* qh, __nv_bfloat16* ql,
    __nv_bfloat16* kh, __nv_bfloat16* kl,
    __nv_bfloat16* vh, __nv_bfloat16* vl,
    const float* stab, const float* ctab)
{
    if (blockIdx.z == 0)
        gemm_mma_body(xh, xl, wqh, wql, bq, nullptr, qh, ql,
                      QSCALE, stab, ctab, 1);
    else if (blockIdx.z == 1)
        gemm_mma_body(xh, xl, wkh, wkl, bk, nullptr, kh, kl, 1.0f, stab, ctab, 1);
    else
        gemm_mma_body(xh, xl, wvh, wvl, bv, nullptr, vh, vl, 1.0f, nullptr, nullptr, 2);
}

__global__ void __launch_bounds__(256, 1) mma_gemm_out_kernel(
    const __nv_bfloat16* ah, const __nv_bfloat16* al,
    const __nv_bfloat16* wh, const __nv_bfloat16* wl,
    const float* bo, float* Y)
{
    gemm_mma_body(ah, al, wh, wl, bo, Y, nullptr, nullptr, 1.0f, nullptr, nullptr, 0);
}

// ---------------------------------------------------------------------------
// Flash attention v2: tensor-core split-bf16, base-2 softmax on the FMA pipe.
// Br=128, Bc=64, 8 warps. Warp w owns Q rows [16w, 16w+16).
// ---------------------------------------------------------------------------
#define BR 128
#define BC 64
#define RQ 136
#define RB (RQ*2)
#define QBYTES (BR*RB)          // 34816
#define QTOT (2*QBYTES)         // 69632
#define KVSTG (4*BC*RB)         // 69632
#define FL2_SMEM (QTOT + 2*KVSTG)   // 208896
#define NKT (SEQ/BC)            // 32

__global__ void __launch_bounds__(256, 1) flash2_kernel(
    const __nv_bfloat16* __restrict__ Qh, const __nv_bfloat16* __restrict__ Ql,
    const __nv_bfloat16* __restrict__ Kh, const __nv_bfloat16* __restrict__ Kl,
    const __nv_bfloat16* __restrict__ Vh, const __nv_bfloat16* __restrict__ Vl,
    __nv_bfloat16* __restrict__ CtxH, __nv_bfloat16* __restrict__ CtxL)
{
    extern __shared__ __align__(128) char smem[];
    const uint32_t sb = smem_to_u32(smem);
    const int tid = threadIdx.x;
    const int wid = tid >> 5, lane = tid & 31;
    const int bh = blockIdx.y;
    const int b = bh >> 4, h = bh & 15;
    const int q0 = blockIdx.x * BR;
    const size_t rowbase = (size_t)b * SEQ;
    const int coff = h * HD;

    {
        const int row = tid >> 1;
        const int ch0 = (tid & 1) * 8;
        const size_t gq = (rowbase + q0 + row) * HID + coff;
        const __nv_bfloat16* sh = Qh + gq;
        const __nv_bfloat16* sl = Ql + gq;
#pragma unroll
        for (int c = 0; c < 8; c++) {
            const int ch = ch0 + c;
            cp16(sb + row * RB + ch * 16, sh + ch * 8);
            cp16(sb + QBYTES + row * RB + ch * 16, sl + ch * 8);
        }
    }

    auto issue_kv = [&](int kt, int stg) {
        const int row = tid >> 2;
        const int cq = tid & 3;
        const size_t g = (rowbase + (size_t)kt * BC + row) * HID + coff;
        const uint32_t base = sb + QTOT + stg * KVSTG + row * RB;
#pragma unroll
        for (int c = 0; c < 4; c++) {
            const int ch = cq + c * 4;
            cp16(base + ch * 16,         Kh + g + ch * 8);
            cp16(base + 17408 + ch * 16, Kl + g + ch * 8);
            cp16(base + 34816 + ch * 16, Vh + g + ch * 8);
            cp16(base + 52224 + ch * 16, Vl + g + ch * 8);
        }
    };

    issue_kv(0, 0);
    asm volatile("cp.async.commit_group;" ::: "memory");

    float m0 = -1e30f, m1 = -1e30f, l0 = 0.0f, l1 = 0.0f;
    float oacc[16][4];
#pragma unroll
    for (int nt = 0; nt < 16; nt++)
#pragma unroll
        for (int e = 0; e < 4; e++) oacc[nt][e] = 0.0f;

    const uint32_t qBh = sb + (wid * 16 + (lane & 15)) * RB + ((lane >> 4) * 8) * 2;
    const uint32_t qBl = qBh + QBYTES;
    const uint32_t kRel = (((lane >> 4) & 1) * 8 + (lane & 7)) * RB +
                          (((lane >> 3) & 1) * 8) * 2;
    const uint32_t vRel = (lane & 15) * RB + ((lane >> 4) * 8) * 2;

    for (int kt = 0; kt < NKT; kt++) {
        if (kt + 1 < NKT) {
            issue_kv(kt + 1, (kt + 1) & 1);
            asm volatile("cp.async.commit_group;" ::: "memory");
            asm volatile("cp.async.wait_group 1;" ::: "memory");
        } else {
            asm volatile("cp.async.wait_group 0;" ::: "memory");
        }
        __syncthreads();

        const uint32_t kb = sb + QTOT + (kt & 1) * KVSTG;

        float sacc[8][4];
#pragma unroll
        for (int nt = 0; nt < 8; nt++)
#pragma unroll
            for (int e = 0; e < 4; e++) sacc[nt][e] = 0.0f;

#pragma unroll
        for (int ks = 0; ks < 8; ks++) {
            uint32_t qa[4], ql4[4];
            ldsm_x4(qa, qBh + ks * 32);
            ldsm_x4(ql4, qBl + ks * 32);
#pragma unroll
            for (int ng = 0; ng < 4; ng++) {
                uint32_t bh4[4], bl4[4];
                const uint32_t ka = kb + kRel + ng * (16 * RB) + ks * 32;
                ldsm_x4(bh4, ka);
                ldsm_x4(bl4, ka + 17408);
                mma_bf16(sacc[2 * ng],     qa,  bh4[0], bh4[1]);
                mma_bf16(sacc[2 * ng],     ql4, bh4[0], bh4[1]);
                mma_bf16(sacc[2 * ng],     qa,  bl4[0], bl4[1]);
                mma_bf16(sacc[2 * ng + 1], qa,  bh4[2], bh4[3]);
                mma_bf16(sacc[2 * ng + 1], ql4, bh4[2], bh4[3]);
                mma_bf16(sacc[2 * ng + 1], qa,  bl4[2], bl4[3]);
            }
        }

        float mx0 = -1e30f, mx1 = -1e30f;
#pragma unroll
        for (int nt = 0; nt < 8; nt++) {
            mx0 = fmaxf(mx0, fmaxf(sacc[nt][0], sacc[nt][1]));
            mx1 = fmaxf(mx1, fmaxf(sacc[nt][2], sacc[nt][3]));
        }
        mx0 = fmaxf(mx0, __shfl_xor_sync(0xffffffffu, mx0, 1));
        mx0 = fmaxf(mx0, __shfl_xor_sync(0xffffffffu, mx0, 2));
        mx1 = fmaxf(mx1, __shfl_xor_sync(0xffffffffu, mx1, 1));
        mx1 = fmaxf(mx1, __shfl_xor_sync(0xffffffffu, mx1, 2));

        const float mn0 = fmaxf(m0, mx0);
        const float mn1 = fmaxf(m1, mx1);
        const float corr0 = fexp2(m0 - mn0);
        const float corr1 = fexp2(m1 - mn1);
        m0 = mn0;
        m1 = mn1;

        uint32_t ph0[8], ph1[8], pl0[8], pl1[8];
        float rs0 = 0.0f, rs1 = 0.0f;
#pragma unroll
        for (int nt = 0; nt < 8; nt++) {
            float p00 = fexp2(sacc[nt][0] - mn0);
            float p01 = fexp2(sacc[nt][1] - mn0);
            float p10 = fexp2(sacc[nt][2] - mn1);
            float p11 = fexp2(sacc[nt][3] - mn1);
            rs0 += p00 + p01;
            rs1 += p10 + p11;
            __nv_bfloat16 a, bb, c, d;
            splitf(p00, a, bb); splitf(p01, c, d);
            ph0[nt] = pk2(a, c); pl0[nt] = pk2(bb, d);
            splitf(p10, a, bb); splitf(p11, c, d);
            ph1[nt] = pk2(a, c); pl1[nt] = pk2(bb, d);
        }
        rs0 += __shfl_xor_sync(0xffffffffu, rs0, 1);
        rs0 += __shfl_xor_sync(0xffffffffu, rs0, 2);
        rs1 += __shfl_xor_sync(0xffffffffu, rs1, 1);
        rs1 += __shfl_xor_sync(0xffffffffu, rs1, 2);
        l0 = l0 * corr0 + rs0;
        l1 = l1 * corr1 + rs1;

#pragma unroll
        for (int nt = 0; nt < 16; nt++) {
            oacc[nt][0] *= corr0;
            oacc[nt][1] *= corr0;
            oacc[nt][2] *= corr1;
            oacc[nt][3] *= corr1;
        }

        const uint32_t vb = kb + 34816;
#pragma unroll
        for (int ks2 = 0; ks2 < 4; ks2++) {
            uint32_t ah[4] = {ph0[2 * ks2], ph1[2 * ks2],
                              ph0[2 * ks2 + 1], ph1[2 * ks2 + 1]};
            uint32_t al[4] = {pl0[2 * ks2], pl1[2 * ks2],
                              pl0[2 * ks2 + 1], pl1[2 * ks2 + 1]};
#pragma unroll
            for (int ng = 0; ng < 8; ng++) {
                uint32_t vh4[4], vl4[4];
                const uint32_t va = vb + vRel + ks2 * (16 * RB) + ng * 32;
                ldsm_x4_t(vh4, va);
                ldsm_x4_t(vl4, va + 17408);
                mma_bf16(oacc[2 * ng],     ah, vh4[0], vh4[1]);
                mma_bf16(oacc[2 * ng],     al, vh4[0], vh4[1]);
                mma_bf16(oacc[2 * ng],     ah, vl4[0], vl4[1]);
                mma_bf16(oacc[2 * ng + 1], ah, vh4[2], vh4[3]);
                mma_bf16(oacc[2 * ng + 1], al, vh4[2], vh4[3]);
                mma_bf16(oacc[2 * ng + 1], ah, vl4[2], vl4[3]);
            }
        }
        __syncthreads();
    }

    const float inv0 = 1.0f / l0;
    const float inv1 = 1.0f / l1;
    const size_t row0 = rowbase + q0 + wid * 16 + (lane >> 2);
    const size_t row1 = row0 + 8;
    const int cb = coff + (lane & 3) * 2;
#pragma unroll
    for (int nt = 0; nt < 16; nt++) {
        const int col = cb + nt * 8;
        __nv_bfloat16 h0, lo0, h1, lo1;
        splitf(oacc[nt][0] * inv0, h0, lo0);
        splitf(oacc[nt][1] * inv0, h1, lo1);
        *(uint32_t*)(CtxH + row0 * HID + col) = pk2(h0, h1);
        *(uint32_t*)(CtxL + row0 * HID + col) = pk2(lo0, lo1);
        splitf(oacc[nt][2] * inv1, h0, lo0);
        splitf(oacc[nt][3] * inv1, h1, lo1);
        *(uint32_t*)(CtxH + row1 * HID + col) = pk2(h0, h1);
        *(uint32_t*)(CtxL + row1 * HID + col) = pk2(lo0, lo1);
    }
}

// ---------------------------------------------------------------------------
extern "C" void kernel_launch(void* const* d_in, const int* in_sizes, int n_in,
                              void* d_out, int out_size)
{
    const float* X  = (const float*)d_in[0];
    const float* Wq = (const float*)d_in[1];
    const float* bq = (const float*)d_in[2];
    const float* Wk = (const float*)d_in[3];
    const float* bk = (const float*)d_in[4];
    const float* Wv = (const float*)d_in[5];
    const float* bv = (const float*)d_in[6];
    const float* Wo = (const float*)d_in[7];
    const float* bo = (const float*)d_in[8];
    float* out = (float*)d_out;

    __nv_bfloat16 *xh, *xl, *wqh, *wql, *wkh, *wkl, *wvh, *wvl, *woh, *wol;
    __nv_bfloat16 *qh, *ql, *kh, *kl, *vh, *vl, *cxh, *cxl;
    float *stab, *ctab;
    cudaGetSymbolAddress((void**)&xh,  g_xh);
    cudaGetSymbolAddress((void**)&xl,  g_xl);
    cudaGetSymbolAddress((void**)&wqh, g_wqh);
    cudaGetSymbolAddress((void**)&wql, g_wql);
    cudaGetSymbolAddress((void**)&wkh, g_wkh);
    cudaGetSymbolAddress((void**)&wkl, g_wkl);
    cudaGetSymbolAddress((void**)&wvh, g_wvh);
    cudaGetSymbolAddress((void**)&wvl, g_wvl);
    cudaGetSymbolAddress((void**)&woh, g_woh);
    cudaGetSymbolAddress((void**)&wol, g_wol);
    cudaGetSymbolAddress((void**)&qh,  g_qh);
    cudaGetSymbolAddress((void**)&ql,  g_ql);
    cudaGetSymbolAddress((void**)&kh,  g_kh);
    cudaGetSymbolAddress((void**)&kl,  g_kl);
    cudaGetSymbolAddress((void**)&vh,  g_vh);
    cudaGetSymbolAddress((void**)&vl,  g_vl);
    cudaGetSymbolAddress((void**)&cxh, g_cxh);
    cudaGetSymbolAddress((void**)&cxl, g_cxl);
    cudaGetSymbolAddress((void**)&stab, g_sin);
    cudaGetSymbolAddress((void**)&ctab, g_cos);

    cudaFuncSetAttribute(mma_gemm_qkv_kernel,
                         cudaFuncAttributeMaxDynamicSharedMemorySize, GSMEM);
    cudaFuncSetAttribute(mma_gemm_out_kernel,
                         cudaFuncAttributeMaxDynamicSharedMemorySize, GSMEM);
    cudaFuncSetAttribute(flash2_kernel,
                         cudaFuncAttributeMaxDynamicSharedMemorySize, FL2_SMEM);

    // 0) RoPE sin/cos table
    rope_table_kernel<<<SEQ * 64 / 256, 256>>>(stab, ctab);

    // 1) split X into bf16 hi/lo
    split_x_kernel<<<(int)(((size_t)M_ROWS * HID / 4) / 256), 256>>>(
        (const float4*)X, (uint2*)xh, (uint2*)xl);

    // 2) transpose + split weights
    {
        dim3 g(HID / 32, HID / 32), blk(32, 8);
        wtrans_kernel<<<g, blk>>>(Wq, wqh, wql);
        wtrans_kernel<<<g, blk>>>(Wk, wkh, wkl);
        wtrans_kernel<<<g, blk>>>(Wv, wvh, wvl);
        wtrans_kernel<<<g, blk>>>(Wo, woh, wol);
    }

    // 3) QKV projections + bias + RoPE -> split-bf16 q/k/v
    {
        dim3 grid(HID / 128, M_ROWS / 256, 3);
        mma_gemm_qkv_kernel<<<grid, 256, GSMEM>>>(
            xh, xl, wqh, wql, wkh, wkl, wvh, wvl, bq, bk, bv,
            qh, ql, kh, kl, vh, vl, stab, ctab);
    }

    // 4) flash attention (tensor cores, base-2 softmax) -> split-bf16 context
    {
        dim3 grid(SEQ / BR, BATCH * NH);
        flash2_kernel<<<grid, 256, FL2_SMEM>>>(qh, ql, kh, kl, vh, vl, cxh, cxl);
    }

    // 5) output projection + bias -> out
    {
        dim3 grid(HID / 128, M_ROWS / 256);
        mma_gemm_out_kernel<<<grid, 256, GSMEM>>>(cxh, cxl, woh, wol, bo, out);
    }
}

// round 7
// speedup vs baseline: 1.1355x; 1.1355x over previous
#include <cuda_runtime.h>
#include <cuda_bf16.h>
#include <cstdint>
#include <math.h>

#define HID 2048
#define SEQ 2048
#define NH  16
#define HD  128
#define BATCH 2
#define M_ROWS (BATCH*SEQ)   // 4096

// ---------------------------------------------------------------------------
// Scratch (__device__ globals; no allocation allowed)
// ---------------------------------------------------------------------------
__device__ __nv_bfloat16 g_xh[(size_t)M_ROWS * HID];
__device__ __nv_bfloat16 g_xl[(size_t)M_ROWS * HID];
__device__ __nv_bfloat16 g_wqh[(size_t)HID * HID];
__device__ __nv_bfloat16 g_wql[(size_t)HID * HID];
__device__ __nv_bfloat16 g_wkh[(size_t)HID * HID];
__device__ __nv_bfloat16 g_wkl[(size_t)HID * HID];
__device__ __nv_bfloat16 g_wvh[(size_t)HID * HID];
__device__ __nv_bfloat16 g_wvl[(size_t)HID * HID];
__device__ __nv_bfloat16 g_woh[(size_t)HID * HID];
__device__ __nv_bfloat16 g_wol[(size_t)HID * HID];
__device__ __nv_bfloat16 g_qh[(size_t)M_ROWS * HID];
__device__ __nv_bfloat16 g_ql[(size_t)M_ROWS * HID];
__device__ __nv_bfloat16 g_kh[(size_t)M_ROWS * HID];
__device__ __nv_bfloat16 g_kl[(size_t)M_ROWS * HID];
__device__ __nv_bfloat16 g_vh[(size_t)M_ROWS * HID];
__device__ __nv_bfloat16 g_vl[(size_t)M_ROWS * HID];
__device__ __nv_bfloat16 g_cxh[(size_t)M_ROWS * HID];
__device__ __nv_bfloat16 g_cxl[(size_t)M_ROWS * HID];
__device__ float g_sin[SEQ * (HD/2)];
__device__ float g_cos[SEQ * (HD/2)];

// ---------------------------------------------------------------------------
// helpers
// ---------------------------------------------------------------------------
__device__ __forceinline__ uint32_t smem_to_u32(const void* p) {
    uint32_t a;
    asm("{ .reg .u64 t; cvta.to.shared.u64 t, %1; cvt.u32.u64 %0, t; }"
        : "=r"(a) : "l"(p));
    return a;
}

__device__ __forceinline__ void cp16(uint32_t dst, const void* src) {
    asm volatile("cp.async.cg.shared.global [%0], [%1], 16;"
                 :: "r"(dst), "l"(src) : "memory");
}

__device__ __forceinline__ void ldsm_x4(uint32_t* r, uint32_t addr) {
    asm volatile("ldmatrix.sync.aligned.m8n8.x4.shared.b16 {%0,%1,%2,%3}, [%4];"
                 : "=r"(r[0]), "=r"(r[1]), "=r"(r[2]), "=r"(r[3]) : "r"(addr));
}

__device__ __forceinline__ void ldsm_x4_t(uint32_t* r, uint32_t addr) {
    asm volatile("ldmatrix.sync.aligned.m8n8.x4.trans.shared.b16 {%0,%1,%2,%3}, [%4];"
                 : "=r"(r[0]), "=r"(r[1]), "=r"(r[2]), "=r"(r[3]) : "r"(addr));
}

__device__ __forceinline__ void mma_bf16(float* c, const uint32_t* a,
                                         uint32_t b0, uint32_t b1) {
    asm volatile(
        "mma.sync.aligned.m16n8k16.row.col.f32.bf16.bf16.f32 "
        "{%0,%1,%2,%3}, {%4,%5,%6,%7}, {%8,%9}, {%0,%1,%2,%3};"
        : "+f"(c[0]), "+f"(c[1]), "+f"(c[2]), "+f"(c[3])
        : "r"(a[0]), "r"(a[1]), "r"(a[2]), "r"(a[3]), "r"(b0), "r"(b1));
}

__device__ __forceinline__ void splitf(float v, __nv_bfloat16& h, __nv_bfloat16& l) {
    h = __float2bfloat16_rn(v);
    l = __float2bfloat16_rn(v - __bfloat162float(h));
}
__device__ __forceinline__ uint32_t pk2(__nv_bfloat16 a, __nv_bfloat16 b) {
    __nv_bfloat162 t = __halves2bfloat162(a, b);
    return *reinterpret_cast<uint32_t*>(&t);
}

// fast 2^t on the FMA pipe. t <= 0 expected; clamped at -30.
__device__ __forceinline__ float fexp2(float t) {
    t = fmaxf(t, -30.0f);
    const float fi = t + 12582912.0f;          // 1.5*2^23 round-to-int
    const float r  = fi - 12582912.0f;
    const float f  = t - r;
    float p = 1.3333558146e-3f;
    p = fmaf(p, f, 9.6181291076e-3f);
    p = fmaf(p, f, 5.5504108665e-2f);
    p = fmaf(p, f, 2.4022650696e-1f);
    p = fmaf(p, f, 6.9314718056e-1f);
    p = fmaf(p, f, 1.0f);
    const int e = __float_as_int(fi) - 0x4B400000;
    return __int_as_float(__float_as_int(p) + (e << 23));
}

// ---------------------------------------------------------------------------
// Prep kernels
// ---------------------------------------------------------------------------
__global__ void rope_table_kernel(float* __restrict__ st, float* __restrict__ ct) {
    int idx = blockIdx.x * blockDim.x + threadIdx.x;   // SEQ*64
    int s = idx >> 6, j = idx & 63;
    double f = exp(-0.14391156831212787 * (double)j);  // 10000^(-2j/128)
    double sn, cs;
    sincos((double)s * f, &sn, &cs);
    st[idx] = (float)sn;
    ct[idx] = (float)cs;
}

__global__ void __launch_bounds__(256) split_x_kernel(
    const float4* __restrict__ X, uint2* __restrict__ H, uint2* __restrict__ L)
{
    size_t i = (size_t)blockIdx.x * blockDim.x + threadIdx.x;
    float4 v = X[i];
    __nv_bfloat16 h0, l0, h1, l1, h2, l2, h3, l3;
    splitf(v.x, h0, l0); splitf(v.y, h1, l1);
    splitf(v.z, h2, l2); splitf(v.w, h3, l3);
    H[i] = make_uint2(pk2(h0, h1), pk2(h2, h3));
    L[i] = make_uint2(pk2(l0, l1), pk2(l2, l3));
}

// Two W [K][N] fp32 -> Wt [N][K] bf16 hi/lo (transpose + split); z selects.
__global__ void __launch_bounds__(256) wtrans2_kernel(
    const float* __restrict__ W0, __nv_bfloat16* __restrict__ Th0,
    __nv_bfloat16* __restrict__ Tl0,
    const float* __restrict__ W1, __nv_bfloat16* __restrict__ Th1,
    __nv_bfloat16* __restrict__ Tl1)
{
    const float* W = blockIdx.z ? W1 : W0;
    __nv_bfloat16* Th = blockIdx.z ? Th1 : Th0;
    __nv_bfloat16* Tl = blockIdx.z ? Tl1 : Tl0;
    __shared__ float t[32][33];
    const int n0 = blockIdx.x * 32, k0 = blockIdx.y * 32;
    const int tx = threadIdx.x, ty = threadIdx.y;   // (32, 8)
#pragma unroll
    for (int i = 0; i < 4; i++)
        t[ty + 8 * i][tx] = W[(size_t)(k0 + ty + 8 * i) * HID + n0 + tx];
    __syncthreads();
#pragma unroll
    for (int i = 0; i < 4; i++) {
        float v = t[tx][ty + 8 * i];
        __nv_bfloat16 h, l;
        splitf(v, h, l);
        const size_t o = (size_t)(n0 + ty + 8 * i) * HID + k0 + tx;
        Th[o] = h;
        Tl[o] = l;
    }
}

// ---------------------------------------------------------------------------
// mma.sync split-bf16 GEMM. 512 threads / 16 warps, BM=128, BN=256, BK=32.
// Warp tile 32x64 (warp_m = wid&3, warp_n = wid>>2). All 4 tiles per chunk
// loaded once; 3 products fused. 3-stage pipeline, ONE __syncthreads/chunk.
// mode 0: fp32 out (+bias); mode 1: bias+RoPE, scaled, split-bf16 out;
// mode 2: bias only, split-bf16 out.
// ---------------------------------------------------------------------------
#define AT2 10240                       // 128 rows x 80B
#define BT2 20480                       // 256 rows x 80B
#define STG_B (2*AT2 + 2*BT2)           // 61440: [Ah][Al][Bh][Bl]
#define GSTAGES 3
#define GSMEM (GSTAGES * STG_B)         // 184320
#define NKCHUNK (HID / 32)              // 64

__device__ __forceinline__ void gemm_mma_body(
    const __nv_bfloat16* __restrict__ Ah, const __nv_bfloat16* __restrict__ Al,
    const __nv_bfloat16* __restrict__ Bh, const __nv_bfloat16* __restrict__ Bl,
    const float* __restrict__ bias,
    float* __restrict__ Yf, __nv_bfloat16* __restrict__ Yh,
    __nv_bfloat16* __restrict__ Yl, float oscale,
    const float* __restrict__ stab, const float* __restrict__ ctab, int mode)
{
    extern __shared__ __align__(128) char smem[];
    const uint32_t sb = smem_to_u32(smem);
    const int tid = threadIdx.x;
    const int wid = tid >> 5, lane = tid & 31;
    const int warp_m = wid & 3, warp_n = wid >> 2;   // 4 x 4 warps
    const int bm = blockIdx.y * 128, bn = blockIdx.x * 256;

    // loaders: A row = tid>>2 (128 rows), seg = tid&3; B row = tid>>1, segs
    const int ar = tid >> 2, aseg = tid & 3;
    const int br = tid >> 1, bseg = (tid & 1) * 2;

    // ldmatrix bases within a stage
    const uint32_t aoff =
        (warp_m * 32 + ((lane >> 3) & 1) * 8 + (lane & 7)) * 80 +
        ((lane >> 4) * 8) * 2;
    const uint32_t boff =
        (warp_n * 64 + ((lane >> 4) & 1) * 8 + (lane & 7)) * 80 +
        (((lane >> 3) & 1) * 8) * 2;

    float acc[2][8][4];
#pragma unroll
    for (int mt = 0; mt < 2; mt++)
#pragma unroll
        for (int nt = 0; nt < 8; nt++)
#pragma unroll
            for (int e = 0; e < 4; e++) acc[mt][nt][e] = 0.0f;

    auto issue = [&](int c, int stg) {
        const int k0 = c << 5;
        const uint32_t so = sb + stg * STG_B;
        const __nv_bfloat16* ahp = Ah + (size_t)(bm + ar) * HID + k0 + aseg * 8;
        const __nv_bfloat16* alp = Al + (size_t)(bm + ar) * HID + k0 + aseg * 8;
        cp16(so + ar * 80 + aseg * 16, ahp);
        cp16(so + AT2 + ar * 80 + aseg * 16, alp);
        const __nv_bfloat16* bhp = Bh + (size_t)(bn + br) * HID + k0 + bseg * 8;
        const __nv_bfloat16* blp = Bl + (size_t)(bn + br) * HID + k0 + bseg * 8;
#pragma unroll
        for (int j = 0; j < 2; j++) {
            cp16(so + 2 * AT2 + br * 80 + (bseg + j) * 16, bhp + j * 8);
            cp16(so + 2 * AT2 + BT2 + br * 80 + (bseg + j) * 16, blp + j * 8);
        }
    };

    issue(0, 0);
    asm volatile("cp.async.commit_group;" ::: "memory");
    issue(1, 1);
    asm volatile("cp.async.commit_group;" ::: "memory");

    for (int c = 0; c < NKCHUNK; c++) {
        asm volatile("cp.async.wait_group 1;" ::: "memory");
        __syncthreads();
        // issue chunk c+2 into stage (c+2)%3 (read finished at iter c-1)
        if (c + 2 < NKCHUNK) {
            int stg = c + 2;
            stg -= (stg / GSTAGES) * GSTAGES;
            issue(c + 2, stg);
        }
        asm volatile("cp.async.commit_group;" ::: "memory");

        int stgc = c;
        stgc -= (stgc / GSTAGES) * GSTAGES;
        const uint32_t so = stgc * STG_B;
        const uint32_t aB = sb + so + aoff;
        const uint32_t bB = sb + so + 2 * AT2 + boff;
#pragma unroll
        for (int ks = 0; ks < 2; ks++) {
            uint32_t ah[2][4], al[2][4];
#pragma unroll
            for (int mt = 0; mt < 2; mt++) {
                ldsm_x4(ah[mt], aB + mt * 1280 + ks * 32);
                ldsm_x4(al[mt], aB + AT2 + mt * 1280 + ks * 32);
            }
#pragma unroll
            for (int ng = 0; ng < 4; ng++) {
                uint32_t bh4[4], bl4[4];
                ldsm_x4(bh4, bB + ng * 1280 + ks * 32);
                ldsm_x4(bl4, bB + BT2 + ng * 1280 + ks * 32);
#pragma unroll
                for (int mt = 0; mt < 2; mt++) {
                    mma_bf16(acc[mt][2 * ng],     ah[mt], bh4[0], bh4[1]);
                    mma_bf16(acc[mt][2 * ng],     al[mt], bh4[0], bh4[1]);
                    mma_bf16(acc[mt][2 * ng],     ah[mt], bl4[0], bl4[1]);
                    mma_bf16(acc[mt][2 * ng + 1], ah[mt], bh4[2], bh4[3]);
                    mma_bf16(acc[mt][2 * ng + 1], al[mt], bh4[2], bh4[3]);
                    mma_bf16(acc[mt][2 * ng + 1], ah[mt], bl4[2], bl4[3]);
                }
            }
        }
    }

    // epilogue
    const int r0 = bm + warp_m * 32 + (lane >> 2);
    const int c0 = bn + warp_n * 64 + (lane & 3) * 2;
#pragma unroll
    for (int mt = 0; mt < 2; mt++) {
#pragma unroll
        for (int half = 0; half < 2; half++) {
            const int row = r0 + mt * 16 + half * 8;
            const int s = row & (SEQ - 1);
#pragma unroll
            for (int nt = 0; nt < 8; nt++) {
                const int col = c0 + nt * 8;
                float e  = acc[mt][nt][half * 2 + 0] + bias[col];
                float od = acc[mt][nt][half * 2 + 1] + bias[col + 1];
                if (mode == 1) {
                    const int j = (col & (HD - 1)) >> 1;
                    const float sn = stab[(s << 6) + j];
                    const float cs = ctab[(s << 6) + j];
                    float re = e * cs - od * sn;
                    float ro = od * cs + e * sn;
                    e = re * oscale;
                    od = ro * oscale;
                }
                if (mode == 0) {
                    float2 r;
                    r.x = e; r.y = od;
                    *(float2*)(Yf + (size_t)row * HID + col) = r;
                } else {
                    __nv_bfloat16 h0, l0, h1, l1;
                    splitf(e, h0, l0);
                    splitf(od, h1, l1);
                    *(uint32_t*)(Yh + (size_t)row * HID + col) = pk2(h0, h1);
                    *(uint32_t*)(Yl + (size_t)row * HID + col) = pk2(l0, l1);
                }
            }
        }
    }
}

// Q scale folds softmax 1/sqrt(128) AND log2(e) (base-2 softmax)
#define QSCALE (0.08838834764831843f * 1.4426950408889634f)

__global__ void __launch_bounds__(512, 1) mma_gemm_qkv_kernel(
    const __nv_bfloat16* xh, const __nv_bfloat16* xl,
    const __nv_bfloat16* wqh, const __nv_bfloat16* wql,
    const __nv_bfloat16* wkh, const __nv_bfloat16* wkl,
    const __nv_bfloat16* wvh, const __nv_bfloat16* wvl,
    const float* bq, const float* bk, const float* bv,
    __nv_bfloat16* qh, __nv_bfloat16* ql,
    __nv_bfloat16* kh, __nv_bfloat16* kl,
    __nv_bfloat16* vh, __nv_bfloat16* vl,
    const float* stab, const float* ctab)
{
    if (blockIdx.z == 0)
        gemm_mma_body(xh, xl, wqh, wql, bq, nullptr, qh, ql,
                      QSCALE, stab, ctab, 1);
    else if (blockIdx.z == 1)
        gemm_mma_body(xh, xl, wkh, wkl, bk, nullptr, kh, kl, 1.0f, stab, ctab, 1);
    else
        gemm_mma_body(xh, xl, wvh, wvl, bv, nullptr, vh, vl, 1.0f, nullptr, nullptr, 2);
}

__global__ void __launch_bounds__(512, 1) mma_gemm_out_kernel(
    const __nv_bfloat16* ah, const __nv_bfloat16* al,
    const __nv_bfloat16* wh, const __nv_bfloat16* wl,
    const float* bo, float* Y)
{
    gemm_mma_body(ah, al, wh, wl, bo, Y, nullptr, nullptr, 1.0f, nullptr, nullptr, 0);
}

// ---------------------------------------------------------------------------
// Flash attention v2 (unchanged from R4): tensor-core split-bf16,
// base-2 softmax on the FMA pipe. Br=128, Bc=64, 8 warps.
// ---------------------------------------------------------------------------
#define BR 128
#define BC 64
#define RQ 136
#define RB (RQ*2)
#define QBYTES (BR*RB)          // 34816
#define QTOT (2*QBYTES)         // 69632
#define KVSTG (4*BC*RB)         // 69632
#define FL2_SMEM (QTOT + 2*KVSTG)   // 208896
#define NKT (SEQ/BC)            // 32

__global__ void __launch_bounds__(256, 1) flash2_kernel(
    const __nv_bfloat16* __restrict__ Qh, const __nv_bfloat16* __restrict__ Ql,
    const __nv_bfloat16* __restrict__ Kh, const __nv_bfloat16* __restrict__ Kl,
    const __nv_bfloat16* __restrict__ Vh, const __nv_bfloat16* __restrict__ Vl,
    __nv_bfloat16* __restrict__ CtxH, __nv_bfloat16* __restrict__ CtxL)
{
    extern __shared__ __align__(128) char smem[];
    const uint32_t sb = smem_to_u32(smem);
    const int tid = threadIdx.x;
    const int wid = tid >> 5, lane = tid & 31;
    const int bh = blockIdx.y;
    const int b = bh >> 4, h = bh & 15;
    const int q0 = blockIdx.x * BR;
    const size_t rowbase = (size_t)b * SEQ;
    const int coff = h * HD;

    {
        const int row = tid >> 1;
        const int ch0 = (tid & 1) * 8;
        const size_t gq = (rowbase + q0 + row) * HID + coff;
        const __nv_bfloat16* sh = Qh + gq;
        const __nv_bfloat16* sl = Ql + gq;
#pragma unroll
        for (int c = 0; c < 8; c++) {
            const int ch = ch0 + c;
            cp16(sb + row * RB + ch * 16, sh + ch * 8);
            cp16(sb + QBYTES + row * RB + ch * 16, sl + ch * 8);
        }
    }

    auto issue_kv = [&](int kt, int stg) {
        const int row = tid >> 2;
        const int cq = tid & 3;
        const size_t g = (rowbase + (size_t)kt * BC + row) * HID + coff;
        const uint32_t base = sb + QTOT + stg * KVSTG + row * RB;
#pragma unroll
        for (int c = 0; c < 4; c++) {
            const int ch = cq + c * 4;
            cp16(base + ch * 16,         Kh + g + ch * 8);
            cp16(base + 17408 + ch * 16, Kl + g + ch * 8);
            cp16(base + 34816 + ch * 16, Vh + g + ch * 8);
            cp16(base + 52224 + ch * 16, Vl + g + ch * 8);
        }
    };

    issue_kv(0, 0);
    asm volatile("cp.async.commit_group;" ::: "memory");

    float m0 = -1e30f, m1 = -1e30f, l0 = 0.0f, l1 = 0.0f;
    float oacc[16][4];
#pragma unroll
    for (int nt = 0; nt < 16; nt++)
#pragma unroll
        for (int e = 0; e < 4; e++) oacc[nt][e] = 0.0f;

    const uint32_t qBh = sb + (wid * 16 + (lane & 15)) * RB + ((lane >> 4) * 8) * 2;
    const uint32_t qBl = qBh + QBYTES;
    const uint32_t kRel = (((lane >> 4) & 1) * 8 + (lane & 7)) * RB +
                          (((lane >> 3) & 1) * 8) * 2;
    const uint32_t vRel = (lane & 15) * RB + ((lane >> 4) * 8) * 2;

    for (int kt = 0; kt < NKT; kt++) {
        if (kt + 1 < NKT) {
            issue_kv(kt + 1, (kt + 1) & 1);
            asm volatile("cp.async.commit_group;" ::: "memory");
            asm volatile("cp.async.wait_group 1;" ::: "memory");
        } else {
            asm volatile("cp.async.wait_group 0;" ::: "memory");
        }
        __syncthreads();

        const uint32_t kb = sb + QTOT + (kt & 1) * KVSTG;

        float sacc[8][4];
#pragma unroll
        for (int nt = 0; nt < 8; nt++)
#pragma unroll
            for (int e = 0; e < 4; e++) sacc[nt][e] = 0.0f;

#pragma unroll
        for (int ks = 0; ks < 8; ks++) {
            uint32_t qa[4], ql4[4];
            ldsm_x4(qa, qBh + ks * 32);
            ldsm_x4(ql4, qBl + ks * 32);
#pragma unroll
            for (int ng = 0; ng < 4; ng++) {
                uint32_t bh4[4], bl4[4];
                const uint32_t ka = kb + kRel + ng * (16 * RB) + ks * 32;
                ldsm_x4(bh4, ka);
                ldsm_x4(bl4, ka + 17408);
                mma_bf16(sacc[2 * ng],     qa,  bh4[0], bh4[1]);
                mma_bf16(sacc[2 * ng],     ql4, bh4[0], bh4[1]);
                mma_bf16(sacc[2 * ng],     qa,  bl4[0], bl4[1]);
                mma_bf16(sacc[2 * ng + 1], qa,  bh4[2], bh4[3]);
                mma_bf16(sacc[2 * ng + 1], ql4, bh4[2], bh4[3]);
                mma_bf16(sacc[2 * ng + 1], qa,  bl4[2], bl4[3]);
            }
        }

        float mx0 = -1e30f, mx1 = -1e30f;
#pragma unroll
        for (int nt = 0; nt < 8; nt++) {
            mx0 = fmaxf(mx0, fmaxf(sacc[nt][0], sacc[nt][1]));
            mx1 = fmaxf(mx1, fmaxf(sacc[nt][2], sacc[nt][3]));
        }
        mx0 = fmaxf(mx0, __shfl_xor_sync(0xffffffffu, mx0, 1));
        mx0 = fmaxf(mx0, __shfl_xor_sync(0xffffffffu, mx0, 2));
        mx1 = fmaxf(mx1, __shfl_xor_sync(0xffffffffu, mx1, 1));
        mx1 = fmaxf(mx1, __shfl_xor_sync(0xffffffffu, mx1, 2));

        const float mn0 = fmaxf(m0, mx0);
        const float mn1 = fmaxf(m1, mx1);
        const float corr0 = fexp2(m0 - mn0);
        const float corr1 = fexp2(m1 - mn1);
        m0 = mn0;
        m1 = mn1;

        uint32_t ph0[8], ph1[8], pl0[8], pl1[8];
        float rs0 = 0.0f, rs1 = 0.0f;
#pragma unroll
        for (int nt = 0; nt < 8; nt++) {
            float p00 = fexp2(sacc[nt][0] - mn0);
            float p01 = fexp2(sacc[nt][1] - mn0);
            float p10 = fexp2(sacc[nt][2] - mn1);
            float p11 = fexp2(sacc[nt][3] - mn1);
            rs0 += p00 + p01;
            rs1 += p10 + p11;
            __nv_bfloat16 a, bb, c, d;
            splitf(p00, a, bb); splitf(p01, c, d);
            ph0[nt] = pk2(a, c); pl0[nt] = pk2(bb, d);
            splitf(p10, a, bb); splitf(p11, c, d);
            ph1[nt] = pk2(a, c); pl1[nt] = pk2(bb, d);
        }
        rs0 += __shfl_xor_sync(0xffffffffu, rs0, 1);
        rs0 += __shfl_xor_sync(0xffffffffu, rs0, 2);
        rs1 += __shfl_xor_sync(0xffffffffu, rs1, 1);
        rs1 += __shfl_xor_sync(0xffffffffu, rs1, 2);
        l0 = l0 * corr0 + rs0;
        l1 = l1 * corr1 + rs1;

#pragma unroll
        for (int nt = 0; nt < 16; nt++) {
            oacc[nt][0] *= corr0;
            oacc[nt][1] *= corr0;
            oacc[nt][2] *= corr1;
            oacc[nt][3] *= corr1;
        }

        const uint32_t vb = kb + 34816;
#pragma unroll
        for (int ks2 = 0; ks2 < 4; ks2++) {
            uint32_t ah[4] = {ph0[2 * ks2], ph1[2 * ks2],
                              ph0[2 * ks2 + 1], ph1[2 * ks2 + 1]};
            uint32_t al[4] = {pl0[2 * ks2], pl1[2 * ks2],
                              pl0[2 * ks2 + 1], pl1[2 * ks2 + 1]};
#pragma unroll
            for (int ng = 0; ng < 8; ng++) {
                uint32_t vh4[4], vl4[4];
                const uint32_t va = vb + vRel + ks2 * (16 * RB) + ng * 32;
                ldsm_x4_t(vh4, va);
                ldsm_x4_t(vl4, va + 17408);
                mma_bf16(oacc[2 * ng],     ah, vh4[0], vh4[1]);
                mma_bf16(oacc[2 * ng],     al, vh4[0], vh4[1]);
                mma_bf16(oacc[2 * ng],     ah, vl4[0], vl4[1]);
                mma_bf16(oacc[2 * ng + 1], ah, vh4[2], vh4[3]);
                mma_bf16(oacc[2 * ng + 1], al, vh4[2], vh4[3]);
                mma_bf16(oacc[2 * ng + 1], ah, vl4[2], vl4[3]);
            }
        }
        __syncthreads();
    }

    const float inv0 = 1.0f / l0;
    const float inv1 = 1.0f / l1;
    const size_t row0 = rowbase + q0 + wid * 16 + (lane >> 2);
    const size_t row1 = row0 + 8;
    const int cb = coff + (lane & 3) * 2;
#pragma unroll
    for (int nt = 0; nt < 16; nt++) {
        const int col = cb + nt * 8;
        __nv_bfloat16 h0, lo0, h1, lo1;
        splitf(oacc[nt][0] * inv0, h0, lo0);
        splitf(oacc[nt][1] * inv0, h1, lo1);
        *(uint32_t*)(CtxH + row0 * HID + col) = pk2(h0, h1);
        *(uint32_t*)(CtxL + row0 * HID + col) = pk2(lo0, lo1);
        splitf(oacc[nt][2] * inv1, h0, lo0);
        splitf(oacc[nt][3] * inv1, h1, lo1);
        *(uint32_t*)(CtxH + row1 * HID + col) = pk2(h0, h1);
        *(uint32_t*)(CtxL + row1 * HID + col) = pk2(lo0, lo1);
    }
}

// ---------------------------------------------------------------------------
extern "C" void kernel_launch(void* const* d_in, const int* in_sizes, int n_in,
                              void* d_out, int out_size)
{
    const float* X  = (const float*)d_in[0];
    const float* Wq = (const float*)d_in[1];
    const float* bq = (const float*)d_in[2];
    const float* Wk = (const float*)d_in[3];
    const float* bk = (const float*)d_in[4];
    const float* Wv = (const float*)d_in[5];
    const float* bv = (const float*)d_in[6];
    const float* Wo = (const float*)d_in[7];
    const float* bo = (const float*)d_in[8];
    float* out = (float*)d_out;

    __nv_bfloat16 *xh, *xl, *wqh, *wql, *wkh, *wkl, *wvh, *wvl, *woh, *wol;
    __nv_bfloat16 *qh, *ql, *kh, *kl, *vh, *vl, *cxh, *cxl;
    float *stab, *ctab;
    cudaGetSymbolAddress((void**)&xh,  g_xh);
    cudaGetSymbolAddress((void**)&xl,  g_xl);
    cudaGetSymbolAddress((void**)&wqh, g_wqh);
    cudaGetSymbolAddress((void**)&wql, g_wql);
    cudaGetSymbolAddress((void**)&wkh, g_wkh);
    cudaGetSymbolAddress((void**)&wkl, g_wkl);
    cudaGetSymbolAddress((void**)&wvh, g_wvh);
    cudaGetSymbolAddress((void**)&wvl, g_wvl);
    cudaGetSymbolAddress((void**)&woh, g_woh);
    cudaGetSymbolAddress((void**)&wol, g_wol);
    cudaGetSymbolAddress((void**)&qh,  g_qh);
    cudaGetSymbolAddress((void**)&ql,  g_ql);
    cudaGetSymbolAddress((void**)&kh,  g_kh);
    cudaGetSymbolAddress((void**)&kl,  g_kl);
    cudaGetSymbolAddress((void**)&vh,  g_vh);
    cudaGetSymbolAddress((void**)&vl,  g_vl);
    cudaGetSymbolAddress((void**)&cxh, g_cxh);
    cudaGetSymbolAddress((void**)&cxl, g_cxl);
    cudaGetSymbolAddress((void**)&stab, g_sin);
    cudaGetSymbolAddress((void**)&ctab, g_cos);

    cudaFuncSetAttribute(mma_gemm_qkv_kernel,
                         cudaFuncAttributeMaxDynamicSharedMemorySize, GSMEM);
    cudaFuncSetAttribute(mma_gemm_out_kernel,
                         cudaFuncAttributeMaxDynamicSharedMemorySize, GSMEM);
    cudaFuncSetAttribute(flash2_kernel,
                         cudaFuncAttributeMaxDynamicSharedMemorySize, FL2_SMEM);

    // launch 0: RoPE sin/cos table
    rope_table_kernel<<<SEQ * 64 / 256, 256>>>(stab, ctab);

    // launch 1: split X into bf16 hi/lo
    split_x_kernel<<<(int)(((size_t)M_ROWS * HID / 4) / 256), 256>>>(
        (const float4*)X, (uint2*)xh, (uint2*)xl);

    // launches 2,3: transpose + split weights (2 matrices per launch)
    {
        dim3 g(HID / 32, HID / 32, 2), blk(32, 8);
        wtrans2_kernel<<<g, blk>>>(Wq, wqh, wql, Wk, wkh, wkl);
        wtrans2_kernel<<<g, blk>>>(Wv, wvh, wvl, Wo, woh, wol);
    }

    // launch 4: QKV projections + bias + RoPE -> split-bf16 q/k/v
    {
        dim3 grid(HID / 256, M_ROWS / 128, 3);
        mma_gemm_qkv_kernel<<<grid, 512, GSMEM>>>(
            xh, xl, wqh, wql, wkh, wkl, wvh, wvl, bq, bk, bv,
            qh, ql, kh, kl, vh, vl, stab, ctab);
    }

    // launch 5 (ncu -s 5 -c 1 captures this): flash attention
    {
        dim3 grid(SEQ / BR, BATCH * NH);
        flash2_kernel<<<grid, 256, FL2_SMEM>>>(qh, ql, kh, kl, vh, vl, cxh, cxl);
    }

    // launch 6: output projection + bias -> out
    {
        dim3 grid(HID / 256, M_ROWS / 128);
        mma_gemm_out_kernel<<<grid, 512, GSMEM>>>(cxh, cxl, woh, wol, bo, out);
    }
}

// round 8
// speedup vs baseline: 1.1392x; 1.0033x over previous
#include <cuda_runtime.h>
#include <cuda_bf16.h>
#include <cstdint>
#include <math.h>

#define HID 2048
#define SEQ 2048
#define NH  16
#define HD  128
#define BATCH 2
#define M_ROWS (BATCH*SEQ)   // 4096

// ---------------------------------------------------------------------------
// Scratch (__device__ globals; no allocation allowed)
// ---------------------------------------------------------------------------
__device__ __nv_bfloat16 g_xh[(size_t)M_ROWS * HID];
__device__ __nv_bfloat16 g_xl[(size_t)M_ROWS * HID];
__device__ __nv_bfloat16 g_wqh[(size_t)HID * HID];
__device__ __nv_bfloat16 g_wql[(size_t)HID * HID];
__device__ __nv_bfloat16 g_wkh[(size_t)HID * HID];
__device__ __nv_bfloat16 g_wkl[(size_t)HID * HID];
__device__ __nv_bfloat16 g_wvh[(size_t)HID * HID];
__device__ __nv_bfloat16 g_wvl[(size_t)HID * HID];
__device__ __nv_bfloat16 g_woh[(size_t)HID * HID];
__device__ __nv_bfloat16 g_wol[(size_t)HID * HID];
__device__ __nv_bfloat16 g_qh[(size_t)M_ROWS * HID];
__device__ __nv_bfloat16 g_ql[(size_t)M_ROWS * HID];
__device__ __nv_bfloat16 g_kh[(size_t)M_ROWS * HID];
__device__ __nv_bfloat16 g_kl[(size_t)M_ROWS * HID];
__device__ __nv_bfloat16 g_vh[(size_t)M_ROWS * HID];
__device__ __nv_bfloat16 g_vl[(size_t)M_ROWS * HID];
__device__ __nv_bfloat16 g_cxh[(size_t)M_ROWS * HID];
__device__ __nv_bfloat16 g_cxl[(size_t)M_ROWS * HID];
__device__ float g_sin[SEQ * (HD/2)];
__device__ float g_cos[SEQ * (HD/2)];

// ---------------------------------------------------------------------------
// helpers
// ---------------------------------------------------------------------------
__device__ __forceinline__ uint32_t smem_to_u32(const void* p) {
    uint32_t a;
    asm("{ .reg .u64 t; cvta.to.shared.u64 t, %1; cvt.u32.u64 %0, t; }"
        : "=r"(a) : "l"(p));
    return a;
}

__device__ __forceinline__ void cp16(uint32_t dst, const void* src) {
    asm volatile("cp.async.cg.shared.global [%0], [%1], 16;"
                 :: "r"(dst), "l"(src) : "memory");
}

__device__ __forceinline__ void ldsm_x4(uint32_t* r, uint32_t addr) {
    asm volatile("ldmatrix.sync.aligned.m8n8.x4.shared.b16 {%0,%1,%2,%3}, [%4];"
                 : "=r"(r[0]), "=r"(r[1]), "=r"(r[2]), "=r"(r[3]) : "r"(addr));
}

__device__ __forceinline__ void ldsm_x4_t(uint32_t* r, uint32_t addr) {
    asm volatile("ldmatrix.sync.aligned.m8n8.x4.trans.shared.b16 {%0,%1,%2,%3}, [%4];"
                 : "=r"(r[0]), "=r"(r[1]), "=r"(r[2]), "=r"(r[3]) : "r"(addr));
}

__device__ __forceinline__ void mma_bf16(float* c, const uint32_t* a,
                                         uint32_t b0, uint32_t b1) {
    asm volatile(
        "mma.sync.aligned.m16n8k16.row.col.f32.bf16.bf16.f32 "
        "{%0,%1,%2,%3}, {%4,%5,%6,%7}, {%8,%9}, {%0,%1,%2,%3};"
        : "+f"(c[0]), "+f"(c[1]), "+f"(c[2]), "+f"(c[3])
        : "r"(a[0]), "r"(a[1]), "r"(a[2]), "r"(a[3]), "r"(b0), "r"(b1));
}

__device__ __forceinline__ void splitf(float v, __nv_bfloat16& h, __nv_bfloat16& l) {
    h = __float2bfloat16_rn(v);
    l = __float2bfloat16_rn(v - __bfloat162float(h));
}
__device__ __forceinline__ uint32_t pk2(__nv_bfloat16 a, __nv_bfloat16 b) {
    __nv_bfloat162 t = __halves2bfloat162(a, b);
    return *reinterpret_cast<uint32_t*>(&t);
}

// fast 2^t on the FMA pipe. t <= 0 expected; clamped at -30.
__device__ __forceinline__ float fexp2(float t) {
    t = fmaxf(t, -30.0f);
    const float fi = t + 12582912.0f;          // 1.5*2^23 round-to-int
    const float r  = fi - 12582912.0f;
    const float f  = t - r;
    float p = 1.3333558146e-3f;
    p = fmaf(p, f, 9.6181291076e-3f);
    p = fmaf(p, f, 5.5504108665e-2f);
    p = fmaf(p, f, 2.4022650696e-1f);
    p = fmaf(p, f, 6.9314718056e-1f);
    p = fmaf(p, f, 1.0f);
    const int e = __float_as_int(fi) - 0x4B400000;
    return __int_as_float(__float_as_int(p) + (e << 23));
}

// ---------------------------------------------------------------------------
// Prep kernels
// ---------------------------------------------------------------------------
__global__ void rope_table_kernel(float* __restrict__ st, float* __restrict__ ct) {
    int idx = blockIdx.x * blockDim.x + threadIdx.x;   // SEQ*64
    int s = idx >> 6, j = idx & 63;
    double f = exp(-0.14391156831212787 * (double)j);  // 10000^(-2j/128)
    double sn, cs;
    sincos((double)s * f, &sn, &cs);
    st[idx] = (float)sn;
    ct[idx] = (float)cs;
}

__global__ void __launch_bounds__(256) split_x_kernel(
    const float4* __restrict__ X, uint2* __restrict__ H, uint2* __restrict__ L)
{
    size_t i = (size_t)blockIdx.x * blockDim.x + threadIdx.x;
    float4 v = X[i];
    __nv_bfloat16 h0, l0, h1, l1, h2, l2, h3, l3;
    splitf(v.x, h0, l0); splitf(v.y, h1, l1);
    splitf(v.z, h2, l2); splitf(v.w, h3, l3);
    H[i] = make_uint2(pk2(h0, h1), pk2(h2, h3));
    L[i] = make_uint2(pk2(l0, l1), pk2(l2, l3));
}

// Two W [K][N] fp32 -> Wt [N][K] bf16 hi/lo (transpose + split); z selects.
__global__ void __launch_bounds__(256) wtrans2_kernel(
    const float* __restrict__ W0, __nv_bfloat16* __restrict__ Th0,
    __nv_bfloat16* __restrict__ Tl0,
    const float* __restrict__ W1, __nv_bfloat16* __restrict__ Th1,
    __nv_bfloat16* __restrict__ Tl1)
{
    const float* W = blockIdx.z ? W1 : W0;
    __nv_bfloat16* Th = blockIdx.z ? Th1 : Th0;
    __nv_bfloat16* Tl = blockIdx.z ? Tl1 : Tl0;
    __shared__ float t[32][33];
    const int n0 = blockIdx.x * 32, k0 = blockIdx.y * 32;
    const int tx = threadIdx.x, ty = threadIdx.y;   // (32, 8)
#pragma unroll
    for (int i = 0; i < 4; i++)
        t[ty + 8 * i][tx] = W[(size_t)(k0 + ty + 8 * i) * HID + n0 + tx];
    __syncthreads();
#pragma unroll
    for (int i = 0; i < 4; i++) {
        float v = t[tx][ty + 8 * i];
        __nv_bfloat16 h, l;
        splitf(v, h, l);
        const size_t o = (size_t)(n0 + ty + 8 * i) * HID + k0 + tx;
        Th[o] = h;
        Tl[o] = l;
    }
}

// ---------------------------------------------------------------------------
// mma.sync split-bf16 GEMM. 512 threads / 16 warps, BM=128, BN=256, BK=32.
// (unchanged from R7)
// ---------------------------------------------------------------------------
#define AT2 10240                       // 128 rows x 80B
#define BT2 20480                       // 256 rows x 80B
#define STG_B (2*AT2 + 2*BT2)           // 61440: [Ah][Al][Bh][Bl]
#define GSTAGES 3
#define GSMEM (GSTAGES * STG_B)         // 184320
#define NKCHUNK (HID / 32)              // 64

__device__ __forceinline__ void gemm_mma_body(
    const __nv_bfloat16* __restrict__ Ah, const __nv_bfloat16* __restrict__ Al,
    const __nv_bfloat16* __restrict__ Bh, const __nv_bfloat16* __restrict__ Bl,
    const float* __restrict__ bias,
    float* __restrict__ Yf, __nv_bfloat16* __restrict__ Yh,
    __nv_bfloat16* __restrict__ Yl, float oscale,
    const float* __restrict__ stab, const float* __restrict__ ctab, int mode)
{
    extern __shared__ __align__(128) char smem[];
    const uint32_t sb = smem_to_u32(smem);
    const int tid = threadIdx.x;
    const int wid = tid >> 5, lane = tid & 31;
    const int warp_m = wid & 3, warp_n = wid >> 2;   // 4 x 4 warps
    const int bm = blockIdx.y * 128, bn = blockIdx.x * 256;

    const int ar = tid >> 2, aseg = tid & 3;
    const int br = tid >> 1, bseg = (tid & 1) * 2;

    const uint32_t aoff =
        (warp_m * 32 + ((lane >> 3) & 1) * 8 + (lane & 7)) * 80 +
        ((lane >> 4) * 8) * 2;
    const uint32_t boff =
        (warp_n * 64 + ((lane >> 4) & 1) * 8 + (lane & 7)) * 80 +
        (((lane >> 3) & 1) * 8) * 2;

    float acc[2][8][4];
#pragma unroll
    for (int mt = 0; mt < 2; mt++)
#pragma unroll
        for (int nt = 0; nt < 8; nt++)
#pragma unroll
            for (int e = 0; e < 4; e++) acc[mt][nt][e] = 0.0f;

    auto issue = [&](int c, int stg) {
        const int k0 = c << 5;
        const uint32_t so = sb + stg * STG_B;
        const __nv_bfloat16* ahp = Ah + (size_t)(bm + ar) * HID + k0 + aseg * 8;
        const __nv_bfloat16* alp = Al + (size_t)(bm + ar) * HID + k0 + aseg * 8;
        cp16(so + ar * 80 + aseg * 16, ahp);
        cp16(so + AT2 + ar * 80 + aseg * 16, alp);
        const __nv_bfloat16* bhp = Bh + (size_t)(bn + br) * HID + k0 + bseg * 8;
        const __nv_bfloat16* blp = Bl + (size_t)(bn + br) * HID + k0 + bseg * 8;
#pragma unroll
        for (int j = 0; j < 2; j++) {
            cp16(so + 2 * AT2 + br * 80 + (bseg + j) * 16, bhp + j * 8);
            cp16(so + 2 * AT2 + BT2 + br * 80 + (bseg + j) * 16, blp + j * 8);
        }
    };

    issue(0, 0);
    asm volatile("cp.async.commit_group;" ::: "memory");
    issue(1, 1);
    asm volatile("cp.async.commit_group;" ::: "memory");

    for (int c = 0; c < NKCHUNK; c++) {
        asm volatile("cp.async.wait_group 1;" ::: "memory");
        __syncthreads();
        if (c + 2 < NKCHUNK) {
            int stg = c + 2;
            stg -= (stg / GSTAGES) * GSTAGES;
            issue(c + 2, stg);
        }
        asm volatile("cp.async.commit_group;" ::: "memory");

        int stgc = c;
        stgc -= (stgc / GSTAGES) * GSTAGES;
        const uint32_t so = stgc * STG_B;
        const uint32_t aB = sb + so + aoff;
        const uint32_t bB = sb + so + 2 * AT2 + boff;
#pragma unroll
        for (int ks = 0; ks < 2; ks++) {
            uint32_t ah[2][4], al[2][4];
#pragma unroll
            for (int mt = 0; mt < 2; mt++) {
                ldsm_x4(ah[mt], aB + mt * 1280 + ks * 32);
                ldsm_x4(al[mt], aB + AT2 + mt * 1280 + ks * 32);
            }
#pragma unroll
            for (int ng = 0; ng < 4; ng++) {
                uint32_t bh4[4], bl4[4];
                ldsm_x4(bh4, bB + ng * 1280 + ks * 32);
                ldsm_x4(bl4, bB + BT2 + ng * 1280 + ks * 32);
#pragma unroll
                for (int mt = 0; mt < 2; mt++) {
                    mma_bf16(acc[mt][2 * ng],     ah[mt], bh4[0], bh4[1]);
                    mma_bf16(acc[mt][2 * ng],     al[mt], bh4[0], bh4[1]);
                    mma_bf16(acc[mt][2 * ng],     ah[mt], bl4[0], bl4[1]);
                    mma_bf16(acc[mt][2 * ng + 1], ah[mt], bh4[2], bh4[3]);
                    mma_bf16(acc[mt][2 * ng + 1], al[mt], bh4[2], bh4[3]);
                    mma_bf16(acc[mt][2 * ng + 1], ah[mt], bl4[2], bl4[3]);
                }
            }
        }
    }

    const int r0 = bm + warp_m * 32 + (lane >> 2);
    const int c0 = bn + warp_n * 64 + (lane & 3) * 2;
#pragma unroll
    for (int mt = 0; mt < 2; mt++) {
#pragma unroll
        for (int half = 0; half < 2; half++) {
            const int row = r0 + mt * 16 + half * 8;
            const int s = row & (SEQ - 1);
#pragma unroll
            for (int nt = 0; nt < 8; nt++) {
                const int col = c0 + nt * 8;
                float e  = acc[mt][nt][half * 2 + 0] + bias[col];
                float od = acc[mt][nt][half * 2 + 1] + bias[col + 1];
                if (mode == 1) {
                    const int j = (col & (HD - 1)) >> 1;
                    const float sn = stab[(s << 6) + j];
                    const float cs = ctab[(s << 6) + j];
                    float re = e * cs - od * sn;
                    float ro = od * cs + e * sn;
                    e = re * oscale;
                    od = ro * oscale;
                }
                if (mode == 0) {
                    float2 r;
                    r.x = e; r.y = od;
                    *(float2*)(Yf + (size_t)row * HID + col) = r;
                } else {
                    __nv_bfloat16 h0, l0, h1, l1;
                    splitf(e, h0, l0);
                    splitf(od, h1, l1);
                    *(uint32_t*)(Yh + (size_t)row * HID + col) = pk2(h0, h1);
                    *(uint32_t*)(Yl + (size_t)row * HID + col) = pk2(l0, l1);
                }
            }
        }
    }
}

// Q scale folds softmax 1/sqrt(128) AND log2(e) (base-2 softmax)
#define QSCALE (0.08838834764831843f * 1.4426950408889634f)

__global__ void __launch_bounds__(512, 1) mma_gemm_qkv_kernel(
    const __nv_bfloat16* xh, const __nv_bfloat16* xl,
    const __nv_bfloat16* wqh, const __nv_bfloat16* wql,
    const __nv_bfloat16* wkh, const __nv_bfloat16* wkl,
    const __nv_bfloat16* wvh, const __nv_bfloat16* wvl,
    const float* bq, const float* bk, const float* bv,
    __nv_bfloat16* qh, __nv_bfloat16* ql,
    __nv_bfloat16* kh, __nv_bfloat16* kl,
    __nv_bfloat16* vh, __nv_bfloat16* vl,
    const float* stab, const float* ctab)
{
    if (blockIdx.z == 0)
        gemm_mma_body(xh, xl, wqh, wql, bq, nullptr, qh, ql,
                      QSCALE, stab, ctab, 1);
    else if (blockIdx.z == 1)
        gemm_mma_body(xh, xl, wkh, wkl, bk, nullptr, kh, kl, 1.0f, stab, ctab, 1);
    else
        gemm_mma_body(xh, xl, wvh, wvl, bv, nullptr, vh, vl, 1.0f, nullptr, nullptr, 2);
}

__global__ void __launch_bounds__(512, 1) mma_gemm_out_kernel(
    const __nv_bfloat16* ah, const __nv_bfloat16* al,
    const __nv_bfloat16* wh, const __nv_bfloat16* wl,
    const float* bo, float* Y)
{
    gemm_mma_body(ah, al, wh, wl, bo, Y, nullptr, nullptr, 1.0f, nullptr, nullptr, 0);
}

// ---------------------------------------------------------------------------
// Flash attention v3: tensor-core split-bf16, base-2 softmax.
// Br=128, Bc=64, 8 warps. ONE __syncthreads per kv-tile; exp/split work
// interleaved into the PV MMA blocks (per ks2) so FMA overlaps tensor.
// ---------------------------------------------------------------------------
#define BR 128
#define BC 64
#define RQ 136
#define RB (RQ*2)
#define QBYTES (BR*RB)          // 34816
#define QTOT (2*QBYTES)         // 69632
#define KVSTG (4*BC*RB)         // 69632
#define FL2_SMEM (QTOT + 2*KVSTG)   // 208896
#define NKT (SEQ/BC)            // 32

__global__ void __launch_bounds__(256, 1) flash2_kernel(
    const __nv_bfloat16* __restrict__ Qh, const __nv_bfloat16* __restrict__ Ql,
    const __nv_bfloat16* __restrict__ Kh, const __nv_bfloat16* __restrict__ Kl,
    const __nv_bfloat16* __restrict__ Vh, const __nv_bfloat16* __restrict__ Vl,
    __nv_bfloat16* __restrict__ CtxH, __nv_bfloat16* __restrict__ CtxL)
{
    extern __shared__ __align__(128) char smem[];
    const uint32_t sb = smem_to_u32(smem);
    const int tid = threadIdx.x;
    const int wid = tid >> 5, lane = tid & 31;
    const int bh = blockIdx.y;
    const int b = bh >> 4, h = bh & 15;
    const int q0 = blockIdx.x * BR;
    const size_t rowbase = (size_t)b * SEQ;
    const int coff = h * HD;

    // Q tile loads (join cp.async group 0 with KV(0))
    {
        const int row = tid >> 1;
        const int ch0 = (tid & 1) * 8;
        const size_t gq = (rowbase + q0 + row) * HID + coff;
        const __nv_bfloat16* sh = Qh + gq;
        const __nv_bfloat16* sl = Ql + gq;
#pragma unroll
        for (int c = 0; c < 8; c++) {
            const int ch = ch0 + c;
            cp16(sb + row * RB + ch * 16, sh + ch * 8);
            cp16(sb + QBYTES + row * RB + ch * 16, sl + ch * 8);
        }
    }

    auto issue_kv = [&](int kt, int stg) {
        const int row = tid >> 2;
        const int cq = tid & 3;
        const size_t g = (rowbase + (size_t)kt * BC + row) * HID + coff;
        const uint32_t base = sb + QTOT + stg * KVSTG + row * RB;
#pragma unroll
        for (int c = 0; c < 4; c++) {
            const int ch = cq + c * 4;
            cp16(base + ch * 16,         Kh + g + ch * 8);
            cp16(base + 17408 + ch * 16, Kl + g + ch * 8);
            cp16(base + 34816 + ch * 16, Vh + g + ch * 8);
            cp16(base + 52224 + ch * 16, Vl + g + ch * 8);
        }
    };

    issue_kv(0, 0);
    asm volatile("cp.async.commit_group;" ::: "memory");

    float m0 = -1e30f, m1 = -1e30f, l0 = 0.0f, l1 = 0.0f;
    float oacc[16][4];
#pragma unroll
    for (int nt = 0; nt < 16; nt++)
#pragma unroll
        for (int e = 0; e < 4; e++) oacc[nt][e] = 0.0f;

    const uint32_t qBh = sb + (wid * 16 + (lane & 15)) * RB + ((lane >> 4) * 8) * 2;
    const uint32_t qBl = qBh + QBYTES;
    const uint32_t kRel = (((lane >> 4) & 1) * 8 + (lane & 7)) * RB +
                          (((lane >> 3) & 1) * 8) * 2;
    const uint32_t vRel = (lane & 15) * RB + ((lane >> 4) * 8) * 2;

    for (int kt = 0; kt < NKT; kt++) {
        // KV(kt) ready (and, at kt=0, Q too)
        asm volatile("cp.async.wait_group 0;" ::: "memory");
        // publishes KV(kt) to all warps AND guarantees all warps finished
        // reading buffer (kt+1)&1 during iter kt-1 -> safe to refill it.
        __syncthreads();
        if (kt + 1 < NKT) {
            issue_kv(kt + 1, (kt + 1) & 1);
            asm volatile("cp.async.commit_group;" ::: "memory");
        }

        const uint32_t kb = sb + QTOT + (kt & 1) * KVSTG;

        // ---- S = Q K^T (split bf16, 3 products); log2-domain scores ----
        float sacc[8][4];
#pragma unroll
        for (int nt = 0; nt < 8; nt++)
#pragma unroll
            for (int e = 0; e < 4; e++) sacc[nt][e] = 0.0f;

#pragma unroll
        for (int ks = 0; ks < 8; ks++) {
            uint32_t qa[4], ql4[4];
            ldsm_x4(qa, qBh + ks * 32);
            ldsm_x4(ql4, qBl + ks * 32);
#pragma unroll
            for (int ng = 0; ng < 4; ng++) {
                uint32_t bh4[4], bl4[4];
                const uint32_t ka = kb + kRel + ng * (16 * RB) + ks * 32;
                ldsm_x4(bh4, ka);
                ldsm_x4(bl4, ka + 17408);
                mma_bf16(sacc[2 * ng],     qa,  bh4[0], bh4[1]);
                mma_bf16(sacc[2 * ng],     ql4, bh4[0], bh4[1]);
                mma_bf16(sacc[2 * ng],     qa,  bl4[0], bl4[1]);
                mma_bf16(sacc[2 * ng + 1], qa,  bh4[2], bh4[3]);
                mma_bf16(sacc[2 * ng + 1], ql4, bh4[2], bh4[3]);
                mma_bf16(sacc[2 * ng + 1], qa,  bl4[2], bl4[3]);
            }
        }

        // ---- row max + rescale (cheap, must precede PV) ----
        float mx0 = -1e30f, mx1 = -1e30f;
#pragma unroll
        for (int nt = 0; nt < 8; nt++) {
            mx0 = fmaxf(mx0, fmaxf(sacc[nt][0], sacc[nt][1]));
            mx1 = fmaxf(mx1, fmaxf(sacc[nt][2], sacc[nt][3]));
        }
        mx0 = fmaxf(mx0, __shfl_xor_sync(0xffffffffu, mx0, 1));
        mx0 = fmaxf(mx0, __shfl_xor_sync(0xffffffffu, mx0, 2));
        mx1 = fmaxf(mx1, __shfl_xor_sync(0xffffffffu, mx1, 1));
        mx1 = fmaxf(mx1, __shfl_xor_sync(0xffffffffu, mx1, 2));

        const float mn0 = fmaxf(m0, mx0);
        const float mn1 = fmaxf(m1, mx1);
        const float corr0 = fexp2(m0 - mn0);
        const float corr1 = fexp2(m1 - mn1);
        m0 = mn0;
        m1 = mn1;
#pragma unroll
        for (int nt = 0; nt < 16; nt++) {
            oacc[nt][0] *= corr0;
            oacc[nt][1] *= corr0;
            oacc[nt][2] *= corr1;
            oacc[nt][3] *= corr1;
        }

        // ---- PV with exp/split interleaved per ks2 block ----
        const uint32_t vb = kb + 34816;
        float rs0 = 0.0f, rs1 = 0.0f;
#pragma unroll
        for (int ks2 = 0; ks2 < 4; ks2++) {
            // exp + split ONLY the two score fragments this ks2 needs
            uint32_t ah[4], al[4];
#pragma unroll
            for (int j = 0; j < 2; j++) {
                const int nt = 2 * ks2 + j;
                float p00 = fexp2(sacc[nt][0] - mn0);
                float p01 = fexp2(sacc[nt][1] - mn0);
                float p10 = fexp2(sacc[nt][2] - mn1);
                float p11 = fexp2(sacc[nt][3] - mn1);
                rs0 += p00 + p01;
                rs1 += p10 + p11;
                __nv_bfloat16 a, bb, c, d;
                splitf(p00, a, bb); splitf(p01, c, d);
                ah[2 * j]     = pk2(a, c);
                al[2 * j]     = pk2(bb, d);
                splitf(p10, a, bb); splitf(p11, c, d);
                ah[2 * j + 1] = pk2(a, c);
                al[2 * j + 1] = pk2(bb, d);
            }
#pragma unroll
            for (int ng = 0; ng < 8; ng++) {
                uint32_t vh4[4], vl4[4];
                const uint32_t va = vb + vRel + ks2 * (16 * RB) + ng * 32;
                ldsm_x4_t(vh4, va);
                ldsm_x4_t(vl4, va + 17408);
                mma_bf16(oacc[2 * ng],     ah, vh4[0], vh4[1]);
                mma_bf16(oacc[2 * ng],     al, vh4[0], vh4[1]);
                mma_bf16(oacc[2 * ng],     ah, vl4[0], vl4[1]);
                mma_bf16(oacc[2 * ng + 1], ah, vh4[2], vh4[3]);
                mma_bf16(oacc[2 * ng + 1], al, vh4[2], vh4[3]);
                mma_bf16(oacc[2 * ng + 1], ah, vl4[2], vl4[3]);
            }
        }

        rs0 += __shfl_xor_sync(0xffffffffu, rs0, 1);
        rs0 += __shfl_xor_sync(0xffffffffu, rs0, 2);
        rs1 += __shfl_xor_sync(0xffffffffu, rs1, 1);
        rs1 += __shfl_xor_sync(0xffffffffu, rs1, 2);
        l0 = l0 * corr0 + rs0;
        l1 = l1 * corr1 + rs1;
    }

    const float inv0 = 1.0f / l0;
    const float inv1 = 1.0f / l1;
    const size_t row0 = rowbase + q0 + wid * 16 + (lane >> 2);
    const size_t row1 = row0 + 8;
    const int cb = coff + (lane & 3) * 2;
#pragma unroll
    for (int nt = 0; nt < 16; nt++) {
        const int col = cb + nt * 8;
        __nv_bfloat16 h0, lo0, h1, lo1;
        splitf(oacc[nt][0] * inv0, h0, lo0);
        splitf(oacc[nt][1] * inv0, h1, lo1);
        *(uint32_t*)(CtxH + row0 * HID + col) = pk2(h0, h1);
        *(uint32_t*)(CtxL + row0 * HID + col) = pk2(lo0, lo1);
        splitf(oacc[nt][2] * inv1, h0, lo0);
        splitf(oacc[nt][3] * inv1, h1, lo1);
        *(uint32_t*)(CtxH + row1 * HID + col) = pk2(h0, h1);
        *(uint32_t*)(CtxL + row1 * HID + col) = pk2(lo0, lo1);
    }
}

// ---------------------------------------------------------------------------
extern "C" void kernel_launch(void* const* d_in, const int* in_sizes, int n_in,
                              void* d_out, int out_size)
{
    const float* X  = (const float*)d_in[0];
    const float* Wq = (const float*)d_in[1];
    const float* bq = (const float*)d_in[2];
    const float* Wk = (const float*)d_in[3];
    const float* bk = (const float*)d_in[4];
    const float* Wv = (const float*)d_in[5];
    const float* bv = (const float*)d_in[6];
    const float* Wo = (const float*)d_in[7];
    const float* bo = (const float*)d_in[8];
    float* out = (float*)d_out;

    __nv_bfloat16 *xh, *xl, *wqh, *wql, *wkh, *wkl, *wvh, *wvl, *woh, *wol;
    __nv_bfloat16 *qh, *ql, *kh, *kl, *vh, *vl, *cxh, *cxl;
    float *stab, *ctab;
    cudaGetSymbolAddress((void**)&xh,  g_xh);
    cudaGetSymbolAddress((void**)&xl,  g_xl);
    cudaGetSymbolAddress((void**)&wqh, g_wqh);
    cudaGetSymbolAddress((void**)&wql, g_wql);
    cudaGetSymbolAddress((void**)&wkh, g_wkh);
    cudaGetSymbolAddress((void**)&wkl, g_wkl);
    cudaGetSymbolAddress((void**)&wvh, g_wvh);
    cudaGetSymbolAddress((void**)&wvl, g_wvl);
    cudaGetSymbolAddress((void**)&woh, g_woh);
    cudaGetSymbolAddress((void**)&wol, g_wol);
    cudaGetSymbolAddress((void**)&qh,  g_qh);
    cudaGetSymbolAddress((void**)&ql,  g_ql);
    cudaGetSymbolAddress((void**)&kh,  g_kh);
    cudaGetSymbolAddress((void**)&kl,  g_kl);
    cudaGetSymbolAddress((void**)&vh,  g_vh);
    cudaGetSymbolAddress((void**)&vl,  g_vl);
    cudaGetSymbolAddress((void**)&cxh, g_cxh);
    cudaGetSymbolAddress((void**)&cxl, g_cxl);
    cudaGetSymbolAddress((void**)&stab, g_sin);
    cudaGetSymbolAddress((void**)&ctab, g_cos);

    cudaFuncSetAttribute(mma_gemm_qkv_kernel,
                         cudaFuncAttributeMaxDynamicSharedMemorySize, GSMEM);
    cudaFuncSetAttribute(mma_gemm_out_kernel,
                         cudaFuncAttributeMaxDynamicSharedMemorySize, GSMEM);
    cudaFuncSetAttribute(flash2_kernel,
                         cudaFuncAttributeMaxDynamicSharedMemorySize, FL2_SMEM);

    // RoPE sin/cos table
    rope_table_kernel<<<SEQ * 64 / 256, 256>>>(stab, ctab);

    // split X into bf16 hi/lo
    split_x_kernel<<<(int)(((size_t)M_ROWS * HID / 4) / 256), 256>>>(
        (const float4*)X, (uint2*)xh, (uint2*)xl);

    // transpose + split weights (2 matrices per launch)
    {
        dim3 g(HID / 32, HID / 32, 2), blk(32, 8);
        wtrans2_kernel<<<g, blk>>>(Wq, wqh, wql, Wk, wkh, wkl);
        wtrans2_kernel<<<g, blk>>>(Wv, wvh, wvl, Wo, woh, wol);
    }

    // QKV projections + bias + RoPE -> split-bf16 q/k/v
    {
        dim3 grid(HID / 256, M_ROWS / 128, 3);
        mma_gemm_qkv_kernel<<<grid, 512, GSMEM>>>(
            xh, xl, wqh, wql, wkh, wkl, wvh, wvl, bq, bk, bv,
            qh, ql, kh, kl, vh, vl, stab, ctab);
    }

    // flash attention -> split-bf16 context
    {
        dim3 grid(SEQ / BR, BATCH * NH);
        flash2_kernel<<<grid, 256, FL2_SMEM>>>(qh, ql, kh, kl, vh, vl, cxh, cxl);
    }

    // output projection + bias -> out
    {
        dim3 grid(HID / 256, M_ROWS / 128);
        mma_gemm_out_kernel<<<grid, 512, GSMEM>>>(cxh, cxl, woh, wol, bo, out);
    }
}

// round 9
// speedup vs baseline: 1.1675x; 1.0248x over previous
#include <cuda_runtime.h>
#include <cuda_bf16.h>
#include <cstdint>
#include <math.h>

#define HID 2048
#define SEQ 2048
#define NH  16
#define HD  128
#define BATCH 2
#define M_ROWS (BATCH*SEQ)   // 4096

// ---------------------------------------------------------------------------
// Scratch (__device__ globals; no allocation allowed)
// ---------------------------------------------------------------------------
__device__ __nv_bfloat16 g_xh[(size_t)M_ROWS * HID];
__device__ __nv_bfloat16 g_xl[(size_t)M_ROWS * HID];
__device__ __nv_bfloat16 g_wqh[(size_t)HID * HID];
__device__ __nv_bfloat16 g_wql[(size_t)HID * HID];
__device__ __nv_bfloat16 g_wkh[(size_t)HID * HID];
__device__ __nv_bfloat16 g_wkl[(size_t)HID * HID];
__device__ __nv_bfloat16 g_wvh[(size_t)HID * HID];
__device__ __nv_bfloat16 g_wvl[(size_t)HID * HID];
__device__ __nv_bfloat16 g_woh[(size_t)HID * HID];
__device__ __nv_bfloat16 g_wol[(size_t)HID * HID];
__device__ __nv_bfloat16 g_qh[(size_t)M_ROWS * HID];
__device__ __nv_bfloat16 g_ql[(size_t)M_ROWS * HID];
__device__ __nv_bfloat16 g_kh[(size_t)M_ROWS * HID];
__device__ __nv_bfloat16 g_kl[(size_t)M_ROWS * HID];
__device__ __nv_bfloat16 g_vh[(size_t)M_ROWS * HID];
__device__ __nv_bfloat16 g_vl[(size_t)M_ROWS * HID];
__device__ __nv_bfloat16 g_cxh[(size_t)M_ROWS * HID];
__device__ __nv_bfloat16 g_cxl[(size_t)M_ROWS * HID];
__device__ float g_sin[SEQ * (HD/2)];
__device__ float g_cos[SEQ * (HD/2)];

// ---------------------------------------------------------------------------
// helpers
// ---------------------------------------------------------------------------
__device__ __forceinline__ uint32_t smem_to_u32(const void* p) {
    uint32_t a;
    asm("{ .reg .u64 t; cvta.to.shared.u64 t, %1; cvt.u32.u64 %0, t; }"
        : "=r"(a) : "l"(p));
    return a;
}

__device__ __forceinline__ void cp16(uint32_t dst, const void* src) {
    asm volatile("cp.async.cg.shared.global [%0], [%1], 16;"
                 :: "r"(dst), "l"(src) : "memory");
}

__device__ __forceinline__ void ldsm_x4(uint32_t* r, uint32_t addr) {
    asm volatile("ldmatrix.sync.aligned.m8n8.x4.shared.b16 {%0,%1,%2,%3}, [%4];"
                 : "=r"(r[0]), "=r"(r[1]), "=r"(r[2]), "=r"(r[3]) : "r"(addr));
}

__device__ __forceinline__ void ldsm_x4_t(uint32_t* r, uint32_t addr) {
    asm volatile("ldmatrix.sync.aligned.m8n8.x4.trans.shared.b16 {%0,%1,%2,%3}, [%4];"
                 : "=r"(r[0]), "=r"(r[1]), "=r"(r[2]), "=r"(r[3]) : "r"(addr));
}

__device__ __forceinline__ void mma_bf16(float* c, const uint32_t* a,
                                         uint32_t b0, uint32_t b1) {
    asm volatile(
        "mma.sync.aligned.m16n8k16.row.col.f32.bf16.bf16.f32 "
        "{%0,%1,%2,%3}, {%4,%5,%6,%7}, {%8,%9}, {%0,%1,%2,%3};"
        : "+f"(c[0]), "+f"(c[1]), "+f"(c[2]), "+f"(c[3])
        : "r"(a[0]), "r"(a[1]), "r"(a[2]), "r"(a[3]), "r"(b0), "r"(b1));
}

__device__ __forceinline__ void splitf(float v, __nv_bfloat16& h, __nv_bfloat16& l) {
    h = __float2bfloat16_rn(v);
    l = __float2bfloat16_rn(v - __bfloat162float(h));
}
__device__ __forceinline__ uint32_t pk2(__nv_bfloat16 a, __nv_bfloat16 b) {
    __nv_bfloat162 t = __halves2bfloat162(a, b);
    return *reinterpret_cast<uint32_t*>(&t);
}

// fast 2^t on the FMA pipe. t <= 0 expected; clamped at -30.
__device__ __forceinline__ float fexp2(float t) {
    t = fmaxf(t, -30.0f);
    const float fi = t + 12582912.0f;          // 1.5*2^23 round-to-int
    const float r  = fi - 12582912.0f;
    const float f  = t - r;
    float p = 1.3333558146e-3f;
    p = fmaf(p, f, 9.6181291076e-3f);
    p = fmaf(p, f, 5.5504108665e-2f);
    p = fmaf(p, f, 2.4022650696e-1f);
    p = fmaf(p, f, 6.9314718056e-1f);
    p = fmaf(p, f, 1.0f);
    const int e = __float_as_int(fi) - 0x4B400000;
    return __int_as_float(__float_as_int(p) + (e << 23));
}

// ---------------------------------------------------------------------------
// Prep kernel 0: RoPE table (blocks 0..511) + X split (blocks 512..8703)
// ---------------------------------------------------------------------------
__global__ void __launch_bounds__(256) prep0_kernel(
    float* __restrict__ st, float* __restrict__ ct,
    const float4* __restrict__ X, uint2* __restrict__ H, uint2* __restrict__ L)
{
    const int bid = blockIdx.x;
    if (bid < 512) {
        int idx = bid * 256 + threadIdx.x;   // SEQ*64 total
        int s = idx >> 6, j = idx & 63;
        double f = exp(-0.14391156831212787 * (double)j);  // 10000^(-2j/128)
        double sn, cs;
        sincos((double)s * f, &sn, &cs);
        st[idx] = (float)sn;
        ct[idx] = (float)cs;
    } else {
        size_t i = (size_t)(bid - 512) * 256 + threadIdx.x;
        float4 v = X[i];
        __nv_bfloat16 h0, l0, h1, l1, h2, l2, h3, l3;
        splitf(v.x, h0, l0); splitf(v.y, h1, l1);
        splitf(v.z, h2, l2); splitf(v.w, h3, l3);
        H[i] = make_uint2(pk2(h0, h1), pk2(h2, h3));
        L[i] = make_uint2(pk2(l0, l1), pk2(l2, l3));
    }
}

// Prep kernel 1: all four W [K][N] fp32 -> Wt [N][K] bf16 hi/lo; z selects.
__global__ void __launch_bounds__(256) wtrans4_kernel(
    const float* __restrict__ W0, __nv_bfloat16* Th0, __nv_bfloat16* Tl0,
    const float* __restrict__ W1, __nv_bfloat16* Th1, __nv_bfloat16* Tl1,
    const float* __restrict__ W2, __nv_bfloat16* Th2, __nv_bfloat16* Tl2,
    const float* __restrict__ W3, __nv_bfloat16* Th3, __nv_bfloat16* Tl3)
{
    const float* W;
    __nv_bfloat16 *Th, *Tl;
    switch (blockIdx.z) {
        case 0:  W = W0; Th = Th0; Tl = Tl0; break;
        case 1:  W = W1; Th = Th1; Tl = Tl1; break;
        case 2:  W = W2; Th = Th2; Tl = Tl2; break;
        default: W = W3; Th = Th3; Tl = Tl3; break;
    }
    __shared__ float t[32][33];
    const int n0 = blockIdx.x * 32, k0 = blockIdx.y * 32;
    const int tx = threadIdx.x, ty = threadIdx.y;   // (32, 8)
#pragma unroll
    for (int i = 0; i < 4; i++)
        t[ty + 8 * i][tx] = W[(size_t)(k0 + ty + 8 * i) * HID + n0 + tx];
    __syncthreads();
#pragma unroll
    for (int i = 0; i < 4; i++) {
        float v = t[tx][ty + 8 * i];
        __nv_bfloat16 h, l;
        splitf(v, h, l);
        const size_t o = (size_t)(n0 + ty + 8 * i) * HID + k0 + tx;
        Th[o] = h;
        Tl[o] = l;
    }
}

// ---------------------------------------------------------------------------
// mma.sync split-bf16 GEMM v3: 256 threads / 8 warps, 2 CTAs per SM.
// BM=128, BN=128, BK=32. Warp tile 32x64 (4x2 warp grid). All 4 tiles per
// chunk loaded once; 3 products fused. 2-stage pipeline, 1 syncthreads/chunk.
// Two CTAs per SM give two independent barrier domains -> tensor pipe stays
// fed across chunk boundaries.
// ---------------------------------------------------------------------------
#define TLB 10240                       // one tile: 128 rows x 80B
#define STG3 (4*TLB)                    // 40960: [Ah][Al][Bh][Bl]
#define GSMEM3 (2*STG3)                 // 81920 (2 stages)
#define NKCHUNK (HID / 32)              // 64

__device__ __forceinline__ void gemm_mma_body(
    const __nv_bfloat16* __restrict__ Ah, const __nv_bfloat16* __restrict__ Al,
    const __nv_bfloat16* __restrict__ Bh, const __nv_bfloat16* __restrict__ Bl,
    const float* __restrict__ bias,
    float* __restrict__ Yf, __nv_bfloat16* __restrict__ Yh,
    __nv_bfloat16* __restrict__ Yl, float oscale,
    const float* __restrict__ stab, const float* __restrict__ ctab, int mode)
{
    extern __shared__ __align__(128) char smem[];
    const uint32_t sb = smem_to_u32(smem);
    const int tid = threadIdx.x;
    const int wid = tid >> 5, lane = tid & 31;
    const int warp_m = wid & 3, warp_n = wid >> 2;   // 4 x 2 warps
    const int bm = blockIdx.y * 128, bn = blockIdx.x * 128;

    const int r2 = tid >> 1, seg = (tid & 1) * 2;    // loader: 2 cp16 per tile

    const uint32_t aoff =
        (warp_m * 32 + ((lane >> 3) & 1) * 8 + (lane & 7)) * 80 +
        ((lane >> 4) * 8) * 2;
    const uint32_t boff =
        (warp_n * 64 + ((lane >> 4) & 1) * 8 + (lane & 7)) * 80 +
        (((lane >> 3) & 1) * 8) * 2;

    float acc[2][8][4];
#pragma unroll
    for (int mt = 0; mt < 2; mt++)
#pragma unroll
        for (int nt = 0; nt < 8; nt++)
#pragma unroll
            for (int e = 0; e < 4; e++) acc[mt][nt][e] = 0.0f;

    auto issue = [&](int c, int stg) {
        const int k0 = c << 5;
        const uint32_t so = sb + stg * STG3;
        const __nv_bfloat16* ahp = Ah + (size_t)(bm + r2) * HID + k0 + seg * 8;
        const __nv_bfloat16* alp = Al + (size_t)(bm + r2) * HID + k0 + seg * 8;
        const __nv_bfloat16* bhp = Bh + (size_t)(bn + r2) * HID + k0 + seg * 8;
        const __nv_bfloat16* blp = Bl + (size_t)(bn + r2) * HID + k0 + seg * 8;
        const uint32_t rowo = r2 * 80 + seg * 16;
#pragma unroll
        for (int j = 0; j < 2; j++) {
            cp16(so + rowo + j * 16,            ahp + j * 8);
            cp16(so + TLB + rowo + j * 16,      alp + j * 8);
            cp16(so + 2 * TLB + rowo + j * 16,  bhp + j * 8);
            cp16(so + 3 * TLB + rowo + j * 16,  blp + j * 8);
        }
    };

    issue(0, 0);
    asm volatile("cp.async.commit_group;" ::: "memory");

    for (int c = 0; c < NKCHUNK; c++) {
        asm volatile("cp.async.wait_group 0;" ::: "memory");
        __syncthreads();   // publishes stage c&1; prior reads of (c+1)&1 done
        if (c + 1 < NKCHUNK) {
            issue(c + 1, (c + 1) & 1);
            asm volatile("cp.async.commit_group;" ::: "memory");
        }

        const uint32_t so = (c & 1) * STG3;
        const uint32_t aB = sb + so + aoff;
        const uint32_t bB = sb + so + 2 * TLB + boff;
#pragma unroll
        for (int ks = 0; ks < 2; ks++) {
            uint32_t ah[2][4], al[2][4];
#pragma unroll
            for (int mt = 0; mt < 2; mt++) {
                ldsm_x4(ah[mt], aB + mt * 1280 + ks * 32);
                ldsm_x4(al[mt], aB + TLB + mt * 1280 + ks * 32);
            }
#pragma unroll
            for (int ng = 0; ng < 4; ng++) {
                uint32_t bh4[4], bl4[4];
                ldsm_x4(bh4, bB + ng * 1280 + ks * 32);
                ldsm_x4(bl4, bB + TLB + ng * 1280 + ks * 32);
#pragma unroll
                for (int mt = 0; mt < 2; mt++) {
                    mma_bf16(acc[mt][2 * ng],     ah[mt], bh4[0], bh4[1]);
                    mma_bf16(acc[mt][2 * ng],     al[mt], bh4[0], bh4[1]);
                    mma_bf16(acc[mt][2 * ng],     ah[mt], bl4[0], bl4[1]);
                    mma_bf16(acc[mt][2 * ng + 1], ah[mt], bh4[2], bh4[3]);
                    mma_bf16(acc[mt][2 * ng + 1], al[mt], bh4[2], bh4[3]);
                    mma_bf16(acc[mt][2 * ng + 1], ah[mt], bl4[2], bl4[3]);
                }
            }
        }
    }

    const int r0 = bm + warp_m * 32 + (lane >> 2);
    const int c0 = bn + warp_n * 64 + (lane & 3) * 2;
#pragma unroll
    for (int mt = 0; mt < 2; mt++) {
#pragma unroll
        for (int half = 0; half < 2; half++) {
            const int row = r0 + mt * 16 + half * 8;
            const int s = row & (SEQ - 1);
#pragma unroll
            for (int nt = 0; nt < 8; nt++) {
                const int col = c0 + nt * 8;
                float e  = acc[mt][nt][half * 2 + 0] + bias[col];
                float od = acc[mt][nt][half * 2 + 1] + bias[col + 1];
                if (mode == 1) {
                    const int j = (col & (HD - 1)) >> 1;
                    const float sn = stab[(s << 6) + j];
                    const float cs = ctab[(s << 6) + j];
                    float re = e * cs - od * sn;
                    float ro = od * cs + e * sn;
                    e = re * oscale;
                    od = ro * oscale;
                }
                if (mode == 0) {
                    float2 r;
                    r.x = e; r.y = od;
                    *(float2*)(Yf + (size_t)row * HID + col) = r;
                } else {
                    __nv_bfloat16 h0, l0, h1, l1;
                    splitf(e, h0, l0);
                    splitf(od, h1, l1);
                    *(uint32_t*)(Yh + (size_t)row * HID + col) = pk2(h0, h1);
                    *(uint32_t*)(Yl + (size_t)row * HID + col) = pk2(l0, l1);
                }
            }
        }
    }
}

// Q scale folds softmax 1/sqrt(128) AND log2(e) (base-2 softmax)
#define QSCALE (0.08838834764831843f * 1.4426950408889634f)

__global__ void __launch_bounds__(256, 2) mma_gemm_qkv_kernel(
    const __nv_bfloat16* xh, const __nv_bfloat16* xl,
    const __nv_bfloat16* wqh, const __nv_bfloat16* wql,
    const __nv_bfloat16* wkh, const __nv_bfloat16* wkl,
    const __nv_bfloat16* wvh, const __nv_bfloat16* wvl,
    const float* bq, const float* bk, const float* bv,
    __nv_bfloat16* qh, __nv_bfloat16* ql,
    __nv_bfloat16* kh, __nv_bfloat16* kl,
    __nv_bfloat16* vh, __nv_bfloat16* vl,
    const float* stab, const float* ctab)
{
    if (blockIdx.z == 0)
        gemm_mma_body(xh, xl, wqh, wql, bq, nullptr, qh, ql,
                      QSCALE, stab, ctab, 1);
    else if (blockIdx.z == 1)
        gemm_mma_body(xh, xl, wkh, wkl, bk, nullptr, kh, kl, 1.0f, stab, ctab, 1);
    else
        gemm_mma_body(xh, xl, wvh, wvl, bv, nullptr, vh, vl, 1.0f, nullptr, nullptr, 2);
}

__global__ void __launch_bounds__(256, 2) mma_gemm_out_kernel(
    const __nv_bfloat16* ah, const __nv_bfloat16* al,
    const __nv_bfloat16* wh, const __nv_bfloat16* wl,
    const float* bo, float* Y)
{
    gemm_mma_body(ah, al, wh, wl, bo, Y, nullptr, nullptr, 1.0f, nullptr, nullptr, 0);
}

// ---------------------------------------------------------------------------
// Flash attention v3 (unchanged from R8): tensor-core split-bf16, base-2
// softmax, one __syncthreads per kv-tile, exp interleaved into PV.
// ---------------------------------------------------------------------------
#define BR 128
#define BC 64
#define RQ 136
#define RB (RQ*2)
#define QBYTES (BR*RB)          // 34816
#define QTOT (2*QBYTES)         // 69632
#define KVSTG (4*BC*RB)         // 69632
#define FL2_SMEM (QTOT + 2*KVSTG)   // 208896
#define NKT (SEQ/BC)            // 32

__global__ void __launch_bounds__(256, 1) flash2_kernel(
    const __nv_bfloat16* __restrict__ Qh, const __nv_bfloat16* __restrict__ Ql,
    const __nv_bfloat16* __restrict__ Kh, const __nv_bfloat16* __restrict__ Kl,
    const __nv_bfloat16* __restrict__ Vh, const __nv_bfloat16* __restrict__ Vl,
    __nv_bfloat16* __restrict__ CtxH, __nv_bfloat16* __restrict__ CtxL)
{
    extern __shared__ __align__(128) char smem[];
    const uint32_t sb = smem_to_u32(smem);
    const int tid = threadIdx.x;
    const int wid = tid >> 5, lane = tid & 31;
    const int bh = blockIdx.y;
    const int b = bh >> 4, h = bh & 15;
    const int q0 = blockIdx.x * BR;
    const size_t rowbase = (size_t)b * SEQ;
    const int coff = h * HD;

    {
        const int row = tid >> 1;
        const int ch0 = (tid & 1) * 8;
        const size_t gq = (rowbase + q0 + row) * HID + coff;
        const __nv_bfloat16* sh = Qh + gq;
        const __nv_bfloat16* sl = Ql + gq;
#pragma unroll
        for (int c = 0; c < 8; c++) {
            const int ch = ch0 + c;
            cp16(sb + row * RB + ch * 16, sh + ch * 8);
            cp16(sb + QBYTES + row * RB + ch * 16, sl + ch * 8);
        }
    }

    auto issue_kv = [&](int kt, int stg) {
        const int row = tid >> 2;
        const int cq = tid & 3;
        const size_t g = (rowbase + (size_t)kt * BC + row) * HID + coff;
        const uint32_t base = sb + QTOT + stg * KVSTG + row * RB;
#pragma unroll
        for (int c = 0; c < 4; c++) {
            const int ch = cq + c * 4;
            cp16(base + ch * 16,         Kh + g + ch * 8);
            cp16(base + 17408 + ch * 16, Kl + g + ch * 8);
            cp16(base + 34816 + ch * 16, Vh + g + ch * 8);
            cp16(base + 52224 + ch * 16, Vl + g + ch * 8);
        }
    };

    issue_kv(0, 0);
    asm volatile("cp.async.commit_group;" ::: "memory");

    float m0 = -1e30f, m1 = -1e30f, l0 = 0.0f, l1 = 0.0f;
    float oacc[16][4];
#pragma unroll
    for (int nt = 0; nt < 16; nt++)
#pragma unroll
        for (int e = 0; e < 4; e++) oacc[nt][e] = 0.0f;

    const uint32_t qBh = sb + (wid * 16 + (lane & 15)) * RB + ((lane >> 4) * 8) * 2;
    const uint32_t qBl = qBh + QBYTES;
    const uint32_t kRel = (((lane >> 4) & 1) * 8 + (lane & 7)) * RB +
                          (((lane >> 3) & 1) * 8) * 2;
    const uint32_t vRel = (lane & 15) * RB + ((lane >> 4) * 8) * 2;

    for (int kt = 0; kt < NKT; kt++) {
        asm volatile("cp.async.wait_group 0;" ::: "memory");
        __syncthreads();
        if (kt + 1 < NKT) {
            issue_kv(kt + 1, (kt + 1) & 1);
            asm volatile("cp.async.commit_group;" ::: "memory");
        }

        const uint32_t kb = sb + QTOT + (kt & 1) * KVSTG;

        float sacc[8][4];
#pragma unroll
        for (int nt = 0; nt < 8; nt++)
#pragma unroll
            for (int e = 0; e < 4; e++) sacc[nt][e] = 0.0f;

#pragma unroll
        for (int ks = 0; ks < 8; ks++) {
            uint32_t qa[4], ql4[4];
            ldsm_x4(qa, qBh + ks * 32);
            ldsm_x4(ql4, qBl + ks * 32);
#pragma unroll
            for (int ng = 0; ng < 4; ng++) {
                uint32_t bh4[4], bl4[4];
                const uint32_t ka = kb + kRel + ng * (16 * RB) + ks * 32;
                ldsm_x4(bh4, ka);
                ldsm_x4(bl4, ka + 17408);
                mma_bf16(sacc[2 * ng],     qa,  bh4[0], bh4[1]);
                mma_bf16(sacc[2 * ng],     ql4, bh4[0], bh4[1]);
                mma_bf16(sacc[2 * ng],     qa,  bl4[0], bl4[1]);
                mma_bf16(sacc[2 * ng + 1], qa,  bh4[2], bh4[3]);
                mma_bf16(sacc[2 * ng + 1], ql4, bh4[2], bh4[3]);
                mma_bf16(sacc[2 * ng + 1], qa,  bl4[2], bl4[3]);
            }
        }

        float mx0 = -1e30f, mx1 = -1e30f;
#pragma unroll
        for (int nt = 0; nt < 8; nt++) {
            mx0 = fmaxf(mx0, fmaxf(sacc[nt][0], sacc[nt][1]));
            mx1 = fmaxf(mx1, fmaxf(sacc[nt][2], sacc[nt][3]));
        }
        mx0 = fmaxf(mx0, __shfl_xor_sync(0xffffffffu, mx0, 1));
        mx0 = fmaxf(mx0, __shfl_xor_sync(0xffffffffu, mx0, 2));
        mx1 = fmaxf(mx1, __shfl_xor_sync(0xffffffffu, mx1, 1));
        mx1 = fmaxf(mx1, __shfl_xor_sync(0xffffffffu, mx1, 2));

        const float mn0 = fmaxf(m0, mx0);
        const float mn1 = fmaxf(m1, mx1);
        const float corr0 = fexp2(m0 - mn0);
        const float corr1 = fexp2(m1 - mn1);
        m0 = mn0;
        m1 = mn1;
#pragma unroll
        for (int nt = 0; nt < 16; nt++) {
            oacc[nt][0] *= corr0;
            oacc[nt][1] *= corr0;
            oacc[nt][2] *= corr1;
            oacc[nt][3] *= corr1;
        }

        const uint32_t vb = kb + 34816;
        float rs0 = 0.0f, rs1 = 0.0f;
#pragma unroll
        for (int ks2 = 0; ks2 < 4; ks2++) {
            uint32_t ah[4], al[4];
#pragma unroll
            for (int j = 0; j < 2; j++) {
                const int nt = 2 * ks2 + j;
                float p00 = fexp2(sacc[nt][0] - mn0);
                float p01 = fexp2(sacc[nt][1] - mn0);
                float p10 = fexp2(sacc[nt][2] - mn1);
                float p11 = fexp2(sacc[nt][3] - mn1);
                rs0 += p00 + p01;
                rs1 += p10 + p11;
                __nv_bfloat16 a, bb, c, d;
                splitf(p00, a, bb); splitf(p01, c, d);
                ah[2 * j]     = pk2(a, c);
                al[2 * j]     = pk2(bb, d);
                splitf(p10, a, bb); splitf(p11, c, d);
                ah[2 * j + 1] = pk2(a, c);
                al[2 * j + 1] = pk2(bb, d);
            }
#pragma unroll
            for (int ng = 0; ng < 8; ng++) {
                uint32_t vh4[4], vl4[4];
                const uint32_t va = vb + vRel + ks2 * (16 * RB) + ng * 32;
                ldsm_x4_t(vh4, va);
                ldsm_x4_t(vl4, va + 17408);
                mma_bf16(oacc[2 * ng],     ah, vh4[0], vh4[1]);
                mma_bf16(oacc[2 * ng],     al, vh4[0], vh4[1]);
                mma_bf16(oacc[2 * ng],     ah, vl4[0], vl4[1]);
                mma_bf16(oacc[2 * ng + 1], ah, vh4[2], vh4[3]);
                mma_bf16(oacc[2 * ng + 1], al, vh4[2], vh4[3]);
                mma_bf16(oacc[2 * ng + 1], ah, vl4[2], vl4[3]);
            }
        }

        rs0 += __shfl_xor_sync(0xffffffffu, rs0, 1);
        rs0 += __shfl_xor_sync(0xffffffffu, rs0, 2);
        rs1 += __shfl_xor_sync(0xffffffffu, rs1, 1);
        rs1 += __shfl_xor_sync(0xffffffffu, rs1, 2);
        l0 = l0 * corr0 + rs0;
        l1 = l1 * corr1 + rs1;
    }

    const float inv0 = 1.0f / l0;
    const float inv1 = 1.0f / l1;
    const size_t row0 = rowbase + q0 + wid * 16 + (lane >> 2);
    const size_t row1 = row0 + 8;
    const int cb = coff + (lane & 3) * 2;
#pragma unroll
    for (int nt = 0; nt < 16; nt++) {
        const int col = cb + nt * 8;
        __nv_bfloat16 h0, lo0, h1, lo1;
        splitf(oacc[nt][0] * inv0, h0, lo0);
        splitf(oacc[nt][1] * inv0, h1, lo1);
        *(uint32_t*)(CtxH + row0 * HID + col) = pk2(h0, h1);
        *(uint32_t*)(CtxL + row0 * HID + col) = pk2(lo0, lo1);
        splitf(oacc[nt][2] * inv1, h0, lo0);
        splitf(oacc[nt][3] * inv1, h1, lo1);
        *(uint32_t*)(CtxH + row1 * HID + col) = pk2(h0, h1);
        *(uint32_t*)(CtxL + row1 * HID + col) = pk2(lo0, lo1);
    }
}

// ---------------------------------------------------------------------------
extern "C" void kernel_launch(void* const* d_in, const int* in_sizes, int n_in,
                              void* d_out, int out_size)
{
    const float* X  = (const float*)d_in[0];
    const float* Wq = (const float*)d_in[1];
    const float* bq = (const float*)d_in[2];
    const float* Wk = (const float*)d_in[3];
    const float* bk = (const float*)d_in[4];
    const float* Wv = (const float*)d_in[5];
    const float* bv = (const float*)d_in[6];
    const float* Wo = (const float*)d_in[7];
    const float* bo = (const float*)d_in[8];
    float* out = (float*)d_out;

    __nv_bfloat16 *xh, *xl, *wqh, *wql, *wkh, *wkl, *wvh, *wvl, *woh, *wol;
    __nv_bfloat16 *qh, *ql, *kh, *kl, *vh, *vl, *cxh, *cxl;
    float *stab, *ctab;
    cudaGetSymbolAddress((void**)&xh,  g_xh);
    cudaGetSymbolAddress((void**)&xl,  g_xl);
    cudaGetSymbolAddress((void**)&wqh, g_wqh);
    cudaGetSymbolAddress((void**)&wql, g_wql);
    cudaGetSymbolAddress((void**)&wkh, g_wkh);
    cudaGetSymbolAddress((void**)&wkl, g_wkl);
    cudaGetSymbolAddress((void**)&wvh, g_wvh);
    cudaGetSymbolAddress((void**)&wvl, g_wvl);
    cudaGetSymbolAddress((void**)&woh, g_woh);
    cudaGetSymbolAddress((void**)&wol, g_wol);
    cudaGetSymbolAddress((void**)&qh,  g_qh);
    cudaGetSymbolAddress((void**)&ql,  g_ql);
    cudaGetSymbolAddress((void**)&kh,  g_kh);
    cudaGetSymbolAddress((void**)&kl,  g_kl);
    cudaGetSymbolAddress((void**)&vh,  g_vh);
    cudaGetSymbolAddress((void**)&vl,  g_vl);
    cudaGetSymbolAddress((void**)&cxh, g_cxh);
    cudaGetSymbolAddress((void**)&cxl, g_cxl);
    cudaGetSymbolAddress((void**)&stab, g_sin);
    cudaGetSymbolAddress((void**)&ctab, g_cos);

    cudaFuncSetAttribute(mma_gemm_qkv_kernel,
                         cudaFuncAttributeMaxDynamicSharedMemorySize, GSMEM3);
    cudaFuncSetAttribute(mma_gemm_out_kernel,
                         cudaFuncAttributeMaxDynamicSharedMemorySize, GSMEM3);
    cudaFuncSetAttribute(flash2_kernel,
                         cudaFuncAttributeMaxDynamicSharedMemorySize, FL2_SMEM);

    // launch 0: RoPE table + X split (fused)
    prep0_kernel<<<512 + (int)(((size_t)M_ROWS * HID / 4) / 256), 256>>>(
        stab, ctab, (const float4*)X, (uint2*)xh, (uint2*)xl);

    // launch 1: transpose + split all 4 weights
    {
        dim3 g(HID / 32, HID / 32, 4), blk(32, 8);
        wtrans4_kernel<<<g, blk>>>(Wq, wqh, wql, Wk, wkh, wkl,
                                   Wv, wvh, wvl, Wo, woh, wol);
    }

    // launch 2: QKV projections + bias + RoPE -> split-bf16 q/k/v
    {
        dim3 grid(HID / 128, M_ROWS / 128, 3);
        mma_gemm_qkv_kernel<<<grid, 256, GSMEM3>>>(
            xh, xl, wqh, wql, wkh, wkl, wvh, wvl, bq, bk, bv,
            qh, ql, kh, kl, vh, vl, stab, ctab);
    }

    // launch 3: flash attention -> split-bf16 context
    {
        dim3 grid(SEQ / BR, BATCH * NH);
        flash2_kernel<<<grid, 256, FL2_SMEM>>>(qh, ql, kh, kl, vh, vl, cxh, cxl);
    }

    // launch 4: output projection + bias -> out
    {
        dim3 grid(HID / 128, M_ROWS / 128);
        mma_gemm_out_kernel<<<grid, 256, GSMEM3>>>(cxh, cxl, woh, wol, bo, out);
    }
}

// round 10
// speedup vs baseline: 1.2234x; 1.0479x over previous
#include <cuda_runtime.h>
#include <cuda_bf16.h>
#include <cuda_fp16.h>
#include <cstdint>
#include <math.h>

#define HID 2048
#define SEQ 2048
#define NH  16
#define HD  128
#define BATCH 2
#define M_ROWS (BATCH*SEQ)   // 4096

// ---------------------------------------------------------------------------
// Scratch (__device__ globals; no allocation allowed).
// g_qh..g_vl hold PACKED FP16 bits (declared bf16 as bit containers).
// ---------------------------------------------------------------------------
__device__ __nv_bfloat16 g_xh[(size_t)M_ROWS * HID];
__device__ __nv_bfloat16 g_xl[(size_t)M_ROWS * HID];
__device__ __nv_bfloat16 g_wqh[(size_t)HID * HID];
__device__ __nv_bfloat16 g_wql[(size_t)HID * HID];
__device__ __nv_bfloat16 g_wkh[(size_t)HID * HID];
__device__ __nv_bfloat16 g_wkl[(size_t)HID * HID];
__device__ __nv_bfloat16 g_wvh[(size_t)HID * HID];
__device__ __nv_bfloat16 g_wvl[(size_t)HID * HID];
__device__ __nv_bfloat16 g_woh[(size_t)HID * HID];
__device__ __nv_bfloat16 g_wol[(size_t)HID * HID];
__device__ __nv_bfloat16 g_qh[(size_t)M_ROWS * HID];   // fp16 bits
__device__ __nv_bfloat16 g_ql[(size_t)M_ROWS * HID];   // fp16 bits
__device__ __nv_bfloat16 g_kh[(size_t)M_ROWS * HID];   // fp16 bits
__device__ __nv_bfloat16 g_kl[(size_t)M_ROWS * HID];   // fp16 bits
__device__ __nv_bfloat16 g_vh[(size_t)M_ROWS * HID];   // fp16 bits
__device__ __nv_bfloat16 g_vl[(size_t)M_ROWS * HID];   // fp16 bits
__device__ __nv_bfloat16 g_cxh[(size_t)M_ROWS * HID];  // bf16
__device__ __nv_bfloat16 g_cxl[(size_t)M_ROWS * HID];  // bf16
__device__ float g_sin[SEQ * (HD/2)];
__device__ float g_cos[SEQ * (HD/2)];

// ---------------------------------------------------------------------------
// helpers
// ---------------------------------------------------------------------------
__device__ __forceinline__ uint32_t smem_to_u32(const void* p) {
    uint32_t a;
    asm("{ .reg .u64 t; cvta.to.shared.u64 t, %1; cvt.u32.u64 %0, t; }"
        : "=r"(a) : "l"(p));
    return a;
}

__device__ __forceinline__ void cp16(uint32_t dst, const void* src) {
    asm volatile("cp.async.cg.shared.global [%0], [%1], 16;"
                 :: "r"(dst), "l"(src) : "memory");
}

__device__ __forceinline__ void ldsm_x4(uint32_t* r, uint32_t addr) {
    asm volatile("ldmatrix.sync.aligned.m8n8.x4.shared.b16 {%0,%1,%2,%3}, [%4];"
                 : "=r"(r[0]), "=r"(r[1]), "=r"(r[2]), "=r"(r[3]) : "r"(addr));
}

__device__ __forceinline__ void ldsm_x4_t(uint32_t* r, uint32_t addr) {
    asm volatile("ldmatrix.sync.aligned.m8n8.x4.trans.shared.b16 {%0,%1,%2,%3}, [%4];"
                 : "=r"(r[0]), "=r"(r[1]), "=r"(r[2]), "=r"(r[3]) : "r"(addr));
}

__device__ __forceinline__ void mma_bf16(float* c, const uint32_t* a,
                                         uint32_t b0, uint32_t b1) {
    asm volatile(
        "mma.sync.aligned.m16n8k16.row.col.f32.bf16.bf16.f32 "
        "{%0,%1,%2,%3}, {%4,%5,%6,%7}, {%8,%9}, {%0,%1,%2,%3};"
        : "+f"(c[0]), "+f"(c[1]), "+f"(c[2]), "+f"(c[3])
        : "r"(a[0]), "r"(a[1]), "r"(a[2]), "r"(a[3]), "r"(b0), "r"(b1));
}

__device__ __forceinline__ void mma_f16(float* c, const uint32_t* a,
                                        uint32_t b0, uint32_t b1) {
    asm volatile(
        "mma.sync.aligned.m16n8k16.row.col.f32.f16.f16.f32 "
        "{%0,%1,%2,%3}, {%4,%5,%6,%7}, {%8,%9}, {%0,%1,%2,%3};"
        : "+f"(c[0]), "+f"(c[1]), "+f"(c[2]), "+f"(c[3])
        : "r"(a[0]), "r"(a[1]), "r"(a[2]), "r"(a[3]), "r"(b0), "r"(b1));
}

__device__ __forceinline__ void splitf(float v, __nv_bfloat16& h, __nv_bfloat16& l) {
    h = __float2bfloat16_rn(v);
    l = __float2bfloat16_rn(v - __bfloat162float(h));
}
__device__ __forceinline__ uint32_t pk2(__nv_bfloat16 a, __nv_bfloat16 b) {
    __nv_bfloat162 t = __halves2bfloat162(a, b);
    return *reinterpret_cast<uint32_t*>(&t);
}

// fp16 split + pack
__device__ __forceinline__ void splith(float v, __half& h, __half& l) {
    h = __float2half_rn(v);
    l = __float2half_rn(v - __half2float(h));
}
__device__ __forceinline__ uint32_t pk2h(__half a, __half b) {
    __half2 t = __halves2half2(a, b);
    return *reinterpret_cast<uint32_t*>(&t);
}
__device__ __forceinline__ uint32_t pk2hf(float a, float b) {
    __half2 t = __floats2half2_rn(a, b);
    return *reinterpret_cast<uint32_t*>(&t);
}

// fast 2^t on the FMA pipe. t <= 0 expected; clamped at -30.
__device__ __forceinline__ float fexp2(float t) {
    t = fmaxf(t, -30.0f);
    const float fi = t + 12582912.0f;          // 1.5*2^23 round-to-int
    const float r  = fi - 12582912.0f;
    const float f  = t - r;
    float p = 1.3333558146e-3f;
    p = fmaf(p, f, 9.6181291076e-3f);
    p = fmaf(p, f, 5.5504108665e-2f);
    p = fmaf(p, f, 2.4022650696e-1f);
    p = fmaf(p, f, 6.9314718056e-1f);
    p = fmaf(p, f, 1.0f);
    const int e = __float_as_int(fi) - 0x4B400000;
    return __int_as_float(__float_as_int(p) + (e << 23));
}

// ---------------------------------------------------------------------------
// Prep kernel 0: RoPE table (blocks 0..511) + X split (blocks 512..8703)
// ---------------------------------------------------------------------------
__global__ void __launch_bounds__(256) prep0_kernel(
    float* __restrict__ st, float* __restrict__ ct,
    const float4* __restrict__ X, uint2* __restrict__ H, uint2* __restrict__ L)
{
    const int bid = blockIdx.x;
    if (bid < 512) {
        int idx = bid * 256 + threadIdx.x;   // SEQ*64 total
        int s = idx >> 6, j = idx & 63;
        double f = exp(-0.14391156831212787 * (double)j);  // 10000^(-2j/128)
        double sn, cs;
        sincos((double)s * f, &sn, &cs);
        st[idx] = (float)sn;
        ct[idx] = (float)cs;
    } else {
        size_t i = (size_t)(bid - 512) * 256 + threadIdx.x;
        float4 v = X[i];
        __nv_bfloat16 h0, l0, h1, l1, h2, l2, h3, l3;
        splitf(v.x, h0, l0); splitf(v.y, h1, l1);
        splitf(v.z, h2, l2); splitf(v.w, h3, l3);
        H[i] = make_uint2(pk2(h0, h1), pk2(h2, h3));
        L[i] = make_uint2(pk2(l0, l1), pk2(l2, l3));
    }
}

// Prep kernel 1: all four W [K][N] fp32 -> Wt [N][K] bf16 hi/lo; z selects.
__global__ void __launch_bounds__(256) wtrans4_kernel(
    const float* __restrict__ W0, __nv_bfloat16* Th0, __nv_bfloat16* Tl0,
    const float* __restrict__ W1, __nv_bfloat16* Th1, __nv_bfloat16* Tl1,
    const float* __restrict__ W2, __nv_bfloat16* Th2, __nv_bfloat16* Tl2,
    const float* __restrict__ W3, __nv_bfloat16* Th3, __nv_bfloat16* Tl3)
{
    const float* W;
    __nv_bfloat16 *Th, *Tl;
    switch (blockIdx.z) {
        case 0:  W = W0; Th = Th0; Tl = Tl0; break;
        case 1:  W = W1; Th = Th1; Tl = Tl1; break;
        case 2:  W = W2; Th = Th2; Tl = Tl2; break;
        default: W = W3; Th = Th3; Tl = Tl3; break;
    }
    __shared__ float t[32][33];
    const int n0 = blockIdx.x * 32, k0 = blockIdx.y * 32;
    const int tx = threadIdx.x, ty = threadIdx.y;   // (32, 8)
#pragma unroll
    for (int i = 0; i < 4; i++)
        t[ty + 8 * i][tx] = W[(size_t)(k0 + ty + 8 * i) * HID + n0 + tx];
    __syncthreads();
#pragma unroll
    for (int i = 0; i < 4; i++) {
        float v = t[tx][ty + 8 * i];
        __nv_bfloat16 h, l;
        splitf(v, h, l);
        const size_t o = (size_t)(n0 + ty + 8 * i) * HID + k0 + tx;
        Th[o] = h;
        Tl[o] = l;
    }
}

// tiny dummy to shift ncu capture index so idx 3 = qkv GEMM
__global__ void dummy_kernel() {}

// ---------------------------------------------------------------------------
// mma.sync split-bf16 GEMM v3: 256 threads / 8 warps, 2 CTAs per SM.
// BM=128, BN=128, BK=32. (structure unchanged from R9)
// mode 0: fp32 out (+bias); mode 1: bias+RoPE, scaled, FP16 hi/lo out;
// mode 2: bias only, FP16 hi/lo out.
// ---------------------------------------------------------------------------
#define TLB 10240                       // one tile: 128 rows x 80B
#define STG3 (4*TLB)                    // 40960: [Ah][Al][Bh][Bl]
#define GSMEM3 (2*STG3)                 // 81920 (2 stages)
#define NKCHUNK (HID / 32)              // 64

__device__ __forceinline__ void gemm_mma_body(
    const __nv_bfloat16* __restrict__ Ah, const __nv_bfloat16* __restrict__ Al,
    const __nv_bfloat16* __restrict__ Bh, const __nv_bfloat16* __restrict__ Bl,
    const float* __restrict__ bias,
    float* __restrict__ Yf, __nv_bfloat16* __restrict__ Yh,
    __nv_bfloat16* __restrict__ Yl, float oscale,
    const float* __restrict__ stab, const float* __restrict__ ctab, int mode)
{
    extern __shared__ __align__(128) char smem[];
    const uint32_t sb = smem_to_u32(smem);
    const int tid = threadIdx.x;
    const int wid = tid >> 5, lane = tid & 31;
    const int warp_m = wid & 3, warp_n = wid >> 2;   // 4 x 2 warps
    const int bm = blockIdx.y * 128, bn = blockIdx.x * 128;

    const int r2 = tid >> 1, seg = (tid & 1) * 2;

    const uint32_t aoff =
        (warp_m * 32 + ((lane >> 3) & 1) * 8 + (lane & 7)) * 80 +
        ((lane >> 4) * 8) * 2;
    const uint32_t boff =
        (warp_n * 64 + ((lane >> 4) & 1) * 8 + (lane & 7)) * 80 +
        (((lane >> 3) & 1) * 8) * 2;

    float acc[2][8][4];
#pragma unroll
    for (int mt = 0; mt < 2; mt++)
#pragma unroll
        for (int nt = 0; nt < 8; nt++)
#pragma unroll
            for (int e = 0; e < 4; e++) acc[mt][nt][e] = 0.0f;

    auto issue = [&](int c, int stg) {
        const int k0 = c << 5;
        const uint32_t so = sb + stg * STG3;
        const __nv_bfloat16* ahp = Ah + (size_t)(bm + r2) * HID + k0 + seg * 8;
        const __nv_bfloat16* alp = Al + (size_t)(bm + r2) * HID + k0 + seg * 8;
        const __nv_bfloat16* bhp = Bh + (size_t)(bn + r2) * HID + k0 + seg * 8;
        const __nv_bfloat16* blp = Bl + (size_t)(bn + r2) * HID + k0 + seg * 8;
        const uint32_t rowo = r2 * 80 + seg * 16;
#pragma unroll
        for (int j = 0; j < 2; j++) {
            cp16(so + rowo + j * 16,            ahp + j * 8);
            cp16(so + TLB + rowo + j * 16,      alp + j * 8);
            cp16(so + 2 * TLB + rowo + j * 16,  bhp + j * 8);
            cp16(so + 3 * TLB + rowo + j * 16,  blp + j * 8);
        }
    };

    issue(0, 0);
    asm volatile("cp.async.commit_group;" ::: "memory");

    for (int c = 0; c < NKCHUNK; c++) {
        asm volatile("cp.async.wait_group 0;" ::: "memory");
        __syncthreads();
        if (c + 1 < NKCHUNK) {
            issue(c + 1, (c + 1) & 1);
            asm volatile("cp.async.commit_group;" ::: "memory");
        }

        const uint32_t so = (c & 1) * STG3;
        const uint32_t aB = sb + so + aoff;
        const uint32_t bB = sb + so + 2 * TLB + boff;
#pragma unroll
        for (int ks = 0; ks < 2; ks++) {
            uint32_t ah[2][4], al[2][4];
#pragma unroll
            for (int mt = 0; mt < 2; mt++) {
                ldsm_x4(ah[mt], aB + mt * 1280 + ks * 32);
                ldsm_x4(al[mt], aB + TLB + mt * 1280 + ks * 32);
            }
#pragma unroll
            for (int ng = 0; ng < 4; ng++) {
                uint32_t bh4[4], bl4[4];
                ldsm_x4(bh4, bB + ng * 1280 + ks * 32);
                ldsm_x4(bl4, bB + TLB + ng * 1280 + ks * 32);
#pragma unroll
                for (int mt = 0; mt < 2; mt++) {
                    mma_bf16(acc[mt][2 * ng],     ah[mt], bh4[0], bh4[1]);
                    mma_bf16(acc[mt][2 * ng],     al[mt], bh4[0], bh4[1]);
                    mma_bf16(acc[mt][2 * ng],     ah[mt], bl4[0], bl4[1]);
                    mma_bf16(acc[mt][2 * ng + 1], ah[mt], bh4[2], bh4[3]);
                    mma_bf16(acc[mt][2 * ng + 1], al[mt], bh4[2], bh4[3]);
                    mma_bf16(acc[mt][2 * ng + 1], ah[mt], bl4[2], bl4[3]);
                }
            }
        }
    }

    const int r0 = bm + warp_m * 32 + (lane >> 2);
    const int c0 = bn + warp_n * 64 + (lane & 3) * 2;
#pragma unroll
    for (int mt = 0; mt < 2; mt++) {
#pragma unroll
        for (int half = 0; half < 2; half++) {
            const int row = r0 + mt * 16 + half * 8;
            const int s = row & (SEQ - 1);
#pragma unroll
            for (int nt = 0; nt < 8; nt++) {
                const int col = c0 + nt * 8;
                float e  = acc[mt][nt][half * 2 + 0] + bias[col];
                float od = acc[mt][nt][half * 2 + 1] + bias[col + 1];
                if (mode == 1) {
                    const int j = (col & (HD - 1)) >> 1;
                    const float sn = stab[(s << 6) + j];
                    const float cs = ctab[(s << 6) + j];
                    float re = e * cs - od * sn;
                    float ro = od * cs + e * sn;
                    e = re * oscale;
                    od = ro * oscale;
                }
                if (mode == 0) {
                    float2 r;
                    r.x = e; r.y = od;
                    *(float2*)(Yf + (size_t)row * HID + col) = r;
                } else {
                    // FP16 hi/lo output (bit-container bf16 buffers)
                    __half h0, l0, h1, l1;
                    splith(e, h0, l0);
                    splith(od, h1, l1);
                    *(uint32_t*)(Yh + (size_t)row * HID + col) = pk2h(h0, h1);
                    *(uint32_t*)(Yl + (size_t)row * HID + col) = pk2h(l0, l1);
                }
            }
        }
    }
}

// Q scale folds softmax 1/sqrt(128) AND log2(e) (base-2 softmax)
#define QSCALE (0.08838834764831843f * 1.4426950408889634f)

__global__ void __launch_bounds__(256, 2) mma_gemm_qkv_kernel(
    const __nv_bfloat16* xh, const __nv_bfloat16* xl,
    const __nv_bfloat16* wqh, const __nv_bfloat16* wql,
    const __nv_bfloat16* wkh, const __nv_bfloat16* wkl,
    const __nv_bfloat16* wvh, const __nv_bfloat16* wvl,
    const float* bq, const float* bk, const float* bv,
    __nv_bfloat16* qh, __nv_bfloat16* ql,
    __nv_bfloat16* kh, __nv_bfloat16* kl,
    __nv_bfloat16* vh, __nv_bfloat16* vl,
    const float* stab, const float* ctab)
{
    if (blockIdx.z == 0)
        gemm_mma_body(xh, xl, wqh, wql, bq, nullptr, qh, ql,
                      QSCALE, stab, ctab, 1);
    else if (blockIdx.z == 1)
        gemm_mma_body(xh, xl, wkh, wkl, bk, nullptr, kh, kl, 1.0f, stab, ctab, 1);
    else
        gemm_mma_body(xh, xl, wvh, wvl, bv, nullptr, vh, vl, 1.0f, nullptr, nullptr, 2);
}

__global__ void __launch_bounds__(256, 2) mma_gemm_out_kernel(
    const __nv_bfloat16* ah, const __nv_bfloat16* al,
    const __nv_bfloat16* wh, const __nv_bfloat16* wl,
    const float* bo, float* Y)
{
    gemm_mma_body(ah, al, wh, wl, bo, Y, nullptr, nullptr, 1.0f, nullptr, nullptr, 0);
}

// ---------------------------------------------------------------------------
// Flash attention v4: FP16 tensor-core. S = 3-product fp16 split (err 2^-22);
// PV = 2-product (ph*vh + ph*vl, P-lo dropped: ~1e-4 rel). Base-2 softmax.
// Br=128, Bc=64, 8 warps, one __syncthreads per kv-tile.
// ---------------------------------------------------------------------------
#define BR 128
#define BC 64
#define RQ 136
#define RB (RQ*2)
#define QBYTES (BR*RB)          // 34816
#define QTOT (2*QBYTES)         // 69632
#define KVSTG (4*BC*RB)         // 69632
#define FL2_SMEM (QTOT + 2*KVSTG)   // 208896
#define NKT (SEQ/BC)            // 32

__global__ void __launch_bounds__(256, 1) flash2_kernel(
    const __nv_bfloat16* __restrict__ Qh, const __nv_bfloat16* __restrict__ Ql,
    const __nv_bfloat16* __restrict__ Kh, const __nv_bfloat16* __restrict__ Kl,
    const __nv_bfloat16* __restrict__ Vh, const __nv_bfloat16* __restrict__ Vl,
    __nv_bfloat16* __restrict__ CtxH, __nv_bfloat16* __restrict__ CtxL)
{
    extern __shared__ __align__(128) char smem[];
    const uint32_t sb = smem_to_u32(smem);
    const int tid = threadIdx.x;
    const int wid = tid >> 5, lane = tid & 31;
    const int bh = blockIdx.y;
    const int b = bh >> 4, h = bh & 15;
    const int q0 = blockIdx.x * BR;
    const size_t rowbase = (size_t)b * SEQ;
    const int coff = h * HD;

    {
        const int row = tid >> 1;
        const int ch0 = (tid & 1) * 8;
        const size_t gq = (rowbase + q0 + row) * HID + coff;
        const __nv_bfloat16* sh = Qh + gq;
        const __nv_bfloat16* sl = Ql + gq;
#pragma unroll
        for (int c = 0; c < 8; c++) {
            const int ch = ch0 + c;
            cp16(sb + row * RB + ch * 16, sh + ch * 8);
            cp16(sb + QBYTES + row * RB + ch * 16, sl + ch * 8);
        }
    }

    auto issue_kv = [&](int kt, int stg) {
        const int row = tid >> 2;
        const int cq = tid & 3;
        const size_t g = (rowbase + (size_t)kt * BC + row) * HID + coff;
        const uint32_t base = sb + QTOT + stg * KVSTG + row * RB;
#pragma unroll
        for (int c = 0; c < 4; c++) {
            const int ch = cq + c * 4;
            cp16(base + ch * 16,         Kh + g + ch * 8);
            cp16(base + 17408 + ch * 16, Kl + g + ch * 8);
            cp16(base + 34816 + ch * 16, Vh + g + ch * 8);
            cp16(base + 52224 + ch * 16, Vl + g + ch * 8);
        }
    };

    issue_kv(0, 0);
    asm volatile("cp.async.commit_group;" ::: "memory");

    float m0 = -1e30f, m1 = -1e30f, l0 = 0.0f, l1 = 0.0f;
    float oacc[16][4];
#pragma unroll
    for (int nt = 0; nt < 16; nt++)
#pragma unroll
        for (int e = 0; e < 4; e++) oacc[nt][e] = 0.0f;

    const uint32_t qBh = sb + (wid * 16 + (lane & 15)) * RB + ((lane >> 4) * 8) * 2;
    const uint32_t qBl = qBh + QBYTES;
    const uint32_t kRel = (((lane >> 4) & 1) * 8 + (lane & 7)) * RB +
                          (((lane >> 3) & 1) * 8) * 2;
    const uint32_t vRel = (lane & 15) * RB + ((lane >> 4) * 8) * 2;

    for (int kt = 0; kt < NKT; kt++) {
        asm volatile("cp.async.wait_group 0;" ::: "memory");
        __syncthreads();
        if (kt + 1 < NKT) {
            issue_kv(kt + 1, (kt + 1) & 1);
            asm volatile("cp.async.commit_group;" ::: "memory");
        }

        const uint32_t kb = sb + QTOT + (kt & 1) * KVSTG;

        // ---- S = Q K^T (fp16, 3 products); log2-domain scores ----
        float sacc[8][4];
#pragma unroll
        for (int nt = 0; nt < 8; nt++)
#pragma unroll
            for (int e = 0; e < 4; e++) sacc[nt][e] = 0.0f;

#pragma unroll
        for (int ks = 0; ks < 8; ks++) {
            uint32_t qa[4], ql4[4];
            ldsm_x4(qa, qBh + ks * 32);
            ldsm_x4(ql4, qBl + ks * 32);
#pragma unroll
            for (int ng = 0; ng < 4; ng++) {
                uint32_t bh4[4], bl4[4];
                const uint32_t ka = kb + kRel + ng * (16 * RB) + ks * 32;
                ldsm_x4(bh4, ka);
                ldsm_x4(bl4, ka + 17408);
                mma_f16(sacc[2 * ng],     qa,  bh4[0], bh4[1]);
                mma_f16(sacc[2 * ng],     ql4, bh4[0], bh4[1]);
                mma_f16(sacc[2 * ng],     qa,  bl4[0], bl4[1]);
                mma_f16(sacc[2 * ng + 1], qa,  bh4[2], bh4[3]);
                mma_f16(sacc[2 * ng + 1], ql4, bh4[2], bh4[3]);
                mma_f16(sacc[2 * ng + 1], qa,  bl4[2], bl4[3]);
            }
        }

        // ---- row max + rescale ----
        float mx0 = -1e30f, mx1 = -1e30f;
#pragma unroll
        for (int nt = 0; nt < 8; nt++) {
            mx0 = fmaxf(mx0, fmaxf(sacc[nt][0], sacc[nt][1]));
            mx1 = fmaxf(mx1, fmaxf(sacc[nt][2], sacc[nt][3]));
        }
        mx0 = fmaxf(mx0, __shfl_xor_sync(0xffffffffu, mx0, 1));
        mx0 = fmaxf(mx0, __shfl_xor_sync(0xffffffffu, mx0, 2));
        mx1 = fmaxf(mx1, __shfl_xor_sync(0xffffffffu, mx1, 1));
        mx1 = fmaxf(mx1, __shfl_xor_sync(0xffffffffu, mx1, 2));

        const float mn0 = fmaxf(m0, mx0);
        const float mn1 = fmaxf(m1, mx1);
        const float corr0 = fexp2(m0 - mn0);
        const float corr1 = fexp2(m1 - mn1);
        m0 = mn0;
        m1 = mn1;
#pragma unroll
        for (int nt = 0; nt < 16; nt++) {
            oacc[nt][0] *= corr0;
            oacc[nt][1] *= corr0;
            oacc[nt][2] *= corr1;
            oacc[nt][3] *= corr1;
        }

        // ---- PV (fp16, 2 products: ph*vh + ph*vl); exp interleaved ----
        const uint32_t vb = kb + 34816;
        float rs0 = 0.0f, rs1 = 0.0f;
#pragma unroll
        for (int ks2 = 0; ks2 < 4; ks2++) {
            uint32_t ah[4];
#pragma unroll
            for (int j = 0; j < 2; j++) {
                const int nt = 2 * ks2 + j;
                float p00 = fexp2(sacc[nt][0] - mn0);
                float p01 = fexp2(sacc[nt][1] - mn0);
                float p10 = fexp2(sacc[nt][2] - mn1);
                float p11 = fexp2(sacc[nt][3] - mn1);
                rs0 += p00 + p01;
                rs1 += p10 + p11;
                ah[2 * j]     = pk2hf(p00, p01);
                ah[2 * j + 1] = pk2hf(p10, p11);
            }
#pragma unroll
            for (int ng = 0; ng < 8; ng++) {
                uint32_t vh4[4], vl4[4];
                const uint32_t va = vb + vRel + ks2 * (16 * RB) + ng * 32;
                ldsm_x4_t(vh4, va);
                ldsm_x4_t(vl4, va + 17408);
                mma_f16(oacc[2 * ng],     ah, vh4[0], vh4[1]);
                mma_f16(oacc[2 * ng],     ah, vl4[0], vl4[1]);
                mma_f16(oacc[2 * ng + 1], ah, vh4[2], vh4[3]);
                mma_f16(oacc[2 * ng + 1], ah, vl4[2], vl4[3]);
            }
        }

        rs0 += __shfl_xor_sync(0xffffffffu, rs0, 1);
        rs0 += __shfl_xor_sync(0xffffffffu, rs0, 2);
        rs1 += __shfl_xor_sync(0xffffffffu, rs1, 1);
        rs1 += __shfl_xor_sync(0xffffffffu, rs1, 2);
        l0 = l0 * corr0 + rs0;
        l1 = l1 * corr1 + rs1;
    }

    const float inv0 = 1.0f / l0;
    const float inv1 = 1.0f / l1;
    const size_t row0 = rowbase + q0 + wid * 16 + (lane >> 2);
    const size_t row1 = row0 + 8;
    const int cb = coff + (lane & 3) * 2;
#pragma unroll
    for (int nt = 0; nt < 16; nt++) {
        const int col = cb + nt * 8;
        __nv_bfloat16 h0, lo0, h1, lo1;
        splitf(oacc[nt][0] * inv0, h0, lo0);
        splitf(oacc[nt][1] * inv0, h1, lo1);
        *(uint32_t*)(CtxH + row0 * HID + col) = pk2(h0, h1);
        *(uint32_t*)(CtxL + row0 * HID + col) = pk2(lo0, lo1);
        splitf(oacc[nt][2] * inv1, h0, lo0);
        splitf(oacc[nt][3] * inv1, h1, lo1);
        *(uint32_t*)(CtxH + row1 * HID + col) = pk2(h0, h1);
        *(uint32_t*)(CtxL + row1 * HID + col) = pk2(lo0, lo1);
    }
}

// ---------------------------------------------------------------------------
extern "C" void kernel_launch(void* const* d_in, const int* in_sizes, int n_in,
                              void* d_out, int out_size)
{
    const float* X  = (const float*)d_in[0];
    const float* Wq = (const float*)d_in[1];
    const float* bq = (const float*)d_in[2];
    const float* Wk = (const float*)d_in[3];
    const float* bk = (const float*)d_in[4];
    const float* Wv = (const float*)d_in[5];
    const float* bv = (const float*)d_in[6];
    const float* Wo = (const float*)d_in[7];
    const float* bo = (const float*)d_in[8];
    float* out = (float*)d_out;

    __nv_bfloat16 *xh, *xl, *wqh, *wql, *wkh, *wkl, *wvh, *wvl, *woh, *wol;
    __nv_bfloat16 *qh, *ql, *kh, *kl, *vh, *vl, *cxh, *cxl;
    float *stab, *ctab;
    cudaGetSymbolAddress((void**)&xh,  g_xh);
    cudaGetSymbolAddress((void**)&xl,  g_xl);
    cudaGetSymbolAddress((void**)&wqh, g_wqh);
    cudaGetSymbolAddress((void**)&wql, g_wql);
    cudaGetSymbolAddress((void**)&wkh, g_wkh);
    cudaGetSymbolAddress((void**)&wkl, g_wkl);
    cudaGetSymbolAddress((void**)&wvh, g_wvh);
    cudaGetSymbolAddress((void**)&wvl, g_wvl);
    cudaGetSymbolAddress((void**)&woh, g_woh);
    cudaGetSymbolAddress((void**)&wol, g_wol);
    cudaGetSymbolAddress((void**)&qh,  g_qh);
    cudaGetSymbolAddress((void**)&ql,  g_ql);
    cudaGetSymbolAddress((void**)&kh,  g_kh);
    cudaGetSymbolAddress((void**)&kl,  g_kl);
    cudaGetSymbolAddress((void**)&vh,  g_vh);
    cudaGetSymbolAddress((void**)&vl,  g_vl);
    cudaGetSymbolAddress((void**)&cxh, g_cxh);
    cudaGetSymbolAddress((void**)&cxl, g_cxl);
    cudaGetSymbolAddress((void**)&stab, g_sin);
    cudaGetSymbolAddress((void**)&ctab, g_cos);

    cudaFuncSetAttribute(mma_gemm_qkv_kernel,
                         cudaFuncAttributeMaxDynamicSharedMemorySize, GSMEM3);
    cudaFuncSetAttribute(mma_gemm_out_kernel,
                         cudaFuncAttributeMaxDynamicSharedMemorySize, GSMEM3);
    cudaFuncSetAttribute(flash2_kernel,
                         cudaFuncAttributeMaxDynamicSharedMemorySize, FL2_SMEM);

    // launch 0: RoPE table + X split (fused)
    prep0_kernel<<<512 + (int)(((size_t)M_ROWS * HID / 4) / 256), 256>>>(
        stab, ctab, (const float4*)X, (uint2*)xh, (uint2*)xl);

    // launch 1: transpose + split all 4 weights
    {
        dim3 g(HID / 32, HID / 32, 4), blk(32, 8);
        wtrans4_kernel<<<g, blk>>>(Wq, wqh, wql, Wk, wkh, wkl,
                                   Wv, wvh, wvl, Wo, woh, wol);
    }

    // launch 2: dummy (shifts ncu capture so idx 3 = qkv GEMM)
    dummy_kernel<<<1, 32>>>();

    // launch 3: QKV projections + bias + RoPE -> fp16 hi/lo q/k/v
    {
        dim3 grid(HID / 128, M_ROWS / 128, 3);
        mma_gemm_qkv_kernel<<<grid, 256, GSMEM3>>>(
            xh, xl, wqh, wql, wkh, wkl, wvh, wvl, bq, bk, bv,
            qh, ql, kh, kl, vh, vl, stab, ctab);
    }

    // launch 4: flash attention (fp16 tensor cores) -> bf16 hi/lo context
    {
        dim3 grid(SEQ / BR, BATCH * NH);
        flash2_kernel<<<grid, 256, FL2_SMEM>>>(qh, ql, kh, kl, vh, vl, cxh, cxl);
    }

    // launch 5: output projection + bias -> out
    {
        dim3 grid(HID / 128, M_ROWS / 128);
        mma_gemm_out_kernel<<<grid, 256, GSMEM3>>>(cxh, cxl, woh, wol, bo, out);
    }
}

// round 11
// speedup vs baseline: 1.2790x; 1.0455x over previous
#include <cuda_runtime.h>
#include <cuda_bf16.h>
#include <cuda_fp16.h>
#include <cstdint>
#include <math.h>

#define HID 2048
#define SEQ 2048
#define NH  16
#define HD  128
#define BATCH 2
#define M_ROWS (BATCH*SEQ)   // 4096

// ---------------------------------------------------------------------------
// Scratch (__device__ globals; no allocation allowed).
// g_qh..g_vl hold PACKED FP16 bits (declared bf16 as bit containers).
// ---------------------------------------------------------------------------
__device__ __nv_bfloat16 g_xh[(size_t)M_ROWS * HID];
__device__ __nv_bfloat16 g_xl[(size_t)M_ROWS * HID];
__device__ __nv_bfloat16 g_wqh[(size_t)HID * HID];
__device__ __nv_bfloat16 g_wql[(size_t)HID * HID];
__device__ __nv_bfloat16 g_wkh[(size_t)HID * HID];
__device__ __nv_bfloat16 g_wkl[(size_t)HID * HID];
__device__ __nv_bfloat16 g_wvh[(size_t)HID * HID];
__device__ __nv_bfloat16 g_wvl[(size_t)HID * HID];
__device__ __nv_bfloat16 g_woh[(size_t)HID * HID];
__device__ __nv_bfloat16 g_wol[(size_t)HID * HID];
__device__ __nv_bfloat16 g_qh[(size_t)M_ROWS * HID];   // fp16 bits
__device__ __nv_bfloat16 g_ql[(size_t)M_ROWS * HID];   // fp16 bits
__device__ __nv_bfloat16 g_kh[(size_t)M_ROWS * HID];   // fp16 bits
__device__ __nv_bfloat16 g_kl[(size_t)M_ROWS * HID];   // fp16 bits
__device__ __nv_bfloat16 g_vh[(size_t)M_ROWS * HID];   // fp16 bits
__device__ __nv_bfloat16 g_vl[(size_t)M_ROWS * HID];   // fp16 bits
__device__ __nv_bfloat16 g_cxh[(size_t)M_ROWS * HID];  // bf16
__device__ __nv_bfloat16 g_cxl[(size_t)M_ROWS * HID];  // bf16
__device__ float g_sin[SEQ * (HD/2)];
__device__ float g_cos[SEQ * (HD/2)];

// ---------------------------------------------------------------------------
// helpers
// ---------------------------------------------------------------------------
__device__ __forceinline__ uint32_t smem_to_u32(const void* p) {
    uint32_t a;
    asm("{ .reg .u64 t; cvta.to.shared.u64 t, %1; cvt.u32.u64 %0, t; }"
        : "=r"(a) : "l"(p));
    return a;
}

__device__ __forceinline__ void cp16(uint32_t dst, const void* src) {
    asm volatile("cp.async.cg.shared.global [%0], [%1], 16;"
                 :: "r"(dst), "l"(src) : "memory");
}

__device__ __forceinline__ void ldsm_x4(uint32_t* r, uint32_t addr) {
    asm volatile("ldmatrix.sync.aligned.m8n8.x4.shared.b16 {%0,%1,%2,%3}, [%4];"
                 : "=r"(r[0]), "=r"(r[1]), "=r"(r[2]), "=r"(r[3]) : "r"(addr));
}

__device__ __forceinline__ void ldsm_x4_t(uint32_t* r, uint32_t addr) {
    asm volatile("ldmatrix.sync.aligned.m8n8.x4.trans.shared.b16 {%0,%1,%2,%3}, [%4];"
                 : "=r"(r[0]), "=r"(r[1]), "=r"(r[2]), "=r"(r[3]) : "r"(addr));
}

__device__ __forceinline__ void mma_bf16(float* c, const uint32_t* a,
                                         uint32_t b0, uint32_t b1) {
    asm volatile(
        "mma.sync.aligned.m16n8k16.row.col.f32.bf16.bf16.f32 "
        "{%0,%1,%2,%3}, {%4,%5,%6,%7}, {%8,%9}, {%0,%1,%2,%3};"
        : "+f"(c[0]), "+f"(c[1]), "+f"(c[2]), "+f"(c[3])
        : "r"(a[0]), "r"(a[1]), "r"(a[2]), "r"(a[3]), "r"(b0), "r"(b1));
}

__device__ __forceinline__ void mma_f16(float* c, const uint32_t* a,
                                        uint32_t b0, uint32_t b1) {
    asm volatile(
        "mma.sync.aligned.m16n8k16.row.col.f32.f16.f16.f32 "
        "{%0,%1,%2,%3}, {%4,%5,%6,%7}, {%8,%9}, {%0,%1,%2,%3};"
        : "+f"(c[0]), "+f"(c[1]), "+f"(c[2]), "+f"(c[3])
        : "r"(a[0]), "r"(a[1]), "r"(a[2]), "r"(a[3]), "r"(b0), "r"(b1));
}

__device__ __forceinline__ void splitf(float v, __nv_bfloat16& h, __nv_bfloat16& l) {
    h = __float2bfloat16_rn(v);
    l = __float2bfloat16_rn(v - __bfloat162float(h));
}
__device__ __forceinline__ uint32_t pk2(__nv_bfloat16 a, __nv_bfloat16 b) {
    __nv_bfloat162 t = __halves2bfloat162(a, b);
    return *reinterpret_cast<uint32_t*>(&t);
}

// fp16 split + pack
__device__ __forceinline__ void splith(float v, __half& h, __half& l) {
    h = __float2half_rn(v);
    l = __float2half_rn(v - __half2float(h));
}
__device__ __forceinline__ uint32_t pk2h(__half a, __half b) {
    __half2 t = __halves2half2(a, b);
    return *reinterpret_cast<uint32_t*>(&t);
}
__device__ __forceinline__ uint32_t pk2hf(float a, float b) {
    __half2 t = __floats2half2_rn(a, b);
    return *reinterpret_cast<uint32_t*>(&t);
}

// fast 2^t on the FMA pipe. t <= 0 expected; clamped at -30.
__device__ __forceinline__ float fexp2(float t) {
    t = fmaxf(t, -30.0f);
    const float fi = t + 12582912.0f;          // 1.5*2^23 round-to-int
    const float r  = fi - 12582912.0f;
    const float f  = t - r;
    float p = 1.3333558146e-3f;
    p = fmaf(p, f, 9.6181291076e-3f);
    p = fmaf(p, f, 5.5504108665e-2f);
    p = fmaf(p, f, 2.4022650696e-1f);
    p = fmaf(p, f, 6.9314718056e-1f);
    p = fmaf(p, f, 1.0f);
    const int e = __float_as_int(fi) - 0x4B400000;
    return __int_as_float(__float_as_int(p) + (e << 23));
}

// ---------------------------------------------------------------------------
// Prep kernel 0: RoPE table (blocks 0..511) + X split (blocks 512..8703)
// ---------------------------------------------------------------------------
__global__ void __launch_bounds__(256) prep0_kernel(
    float* __restrict__ st, float* __restrict__ ct,
    const float4* __restrict__ X, uint2* __restrict__ H, uint2* __restrict__ L)
{
    const int bid = blockIdx.x;
    if (bid < 512) {
        int idx = bid * 256 + threadIdx.x;   // SEQ*64 total
        int s = idx >> 6, j = idx & 63;
        double f = exp(-0.14391156831212787 * (double)j);  // 10000^(-2j/128)
        double sn, cs;
        sincos((double)s * f, &sn, &cs);
        st[idx] = (float)sn;
        ct[idx] = (float)cs;
    } else {
        size_t i = (size_t)(bid - 512) * 256 + threadIdx.x;
        float4 v = X[i];
        __nv_bfloat16 h0, l0, h1, l1, h2, l2, h3, l3;
        splitf(v.x, h0, l0); splitf(v.y, h1, l1);
        splitf(v.z, h2, l2); splitf(v.w, h3, l3);
        H[i] = make_uint2(pk2(h0, h1), pk2(h2, h3));
        L[i] = make_uint2(pk2(l0, l1), pk2(l2, l3));
    }
}

// Prep kernel 1: all four W [K][N] fp32 -> Wt [N][K] bf16 hi/lo; z selects.
__global__ void __launch_bounds__(256) wtrans4_kernel(
    const float* __restrict__ W0, __nv_bfloat16* Th0, __nv_bfloat16* Tl0,
    const float* __restrict__ W1, __nv_bfloat16* Th1, __nv_bfloat16* Tl1,
    const float* __restrict__ W2, __nv_bfloat16* Th2, __nv_bfloat16* Tl2,
    const float* __restrict__ W3, __nv_bfloat16* Th3, __nv_bfloat16* Tl3)
{
    const float* W;
    __nv_bfloat16 *Th, *Tl;
    switch (blockIdx.z) {
        case 0:  W = W0; Th = Th0; Tl = Tl0; break;
        case 1:  W = W1; Th = Th1; Tl = Tl1; break;
        case 2:  W = W2; Th = Th2; Tl = Tl2; break;
        default: W = W3; Th = Th3; Tl = Tl3; break;
    }
    __shared__ float t[32][33];
    const int n0 = blockIdx.x * 32, k0 = blockIdx.y * 32;
    const int tx = threadIdx.x, ty = threadIdx.y;   // (32, 8)
#pragma unroll
    for (int i = 0; i < 4; i++)
        t[ty + 8 * i][tx] = W[(size_t)(k0 + ty + 8 * i) * HID + n0 + tx];
    __syncthreads();
#pragma unroll
    for (int i = 0; i < 4; i++) {
        float v = t[tx][ty + 8 * i];
        __nv_bfloat16 h, l;
        splitf(v, h, l);
        const size_t o = (size_t)(n0 + ty + 8 * i) * HID + k0 + tx;
        Th[o] = h;
        Tl[o] = l;
    }
}

// tiny dummy to shift ncu capture index so idx 3 = qkv GEMM
__global__ void dummy_kernel() {}

// ---------------------------------------------------------------------------
// mma.sync split-bf16 GEMM v4: 256 threads / 8 warps, 2 CTAs per SM.
// BM=128, BN=128, BK=32. Tiles use 64B rows with XOR swizzle
// (phys_chunk = logical_chunk ^ ((row>>1)&3); conflict-free for cp.async
// writes and ldmatrix reads). Stage = 32KB -> THREE stages per CTA (96KB),
// prefetch depth 2 with cp.async.wait_group 1.
// mode 0: fp32 out (+bias); mode 1: bias+RoPE, scaled, FP16 hi/lo out;
// mode 2: bias only, FP16 hi/lo out.
// ---------------------------------------------------------------------------
#define TLB4 8192                       // one tile: 128 rows x 64B
#define STG4 (4*TLB4)                   // 32768: [Ah][Al][Bh][Bl]
#define GSTAGES4 3
#define GSMEM4 (GSTAGES4 * STG4)        // 98304 per CTA
#define NKCHUNK (HID / 32)              // 64

__device__ __forceinline__ void gemm_mma_body(
    const __nv_bfloat16* __restrict__ Ah, const __nv_bfloat16* __restrict__ Al,
    const __nv_bfloat16* __restrict__ Bh, const __nv_bfloat16* __restrict__ Bl,
    const float* __restrict__ bias,
    float* __restrict__ Yf, __nv_bfloat16* __restrict__ Yh,
    __nv_bfloat16* __restrict__ Yl, float oscale,
    const float* __restrict__ stab, const float* __restrict__ ctab, int mode)
{
    extern __shared__ __align__(128) char smem[];
    const uint32_t sb = smem_to_u32(smem);
    const int tid = threadIdx.x;
    const int wid = tid >> 5, lane = tid & 31;
    const int warp_m = wid & 3, warp_n = wid >> 2;   // 4 x 2 warps
    const int bm = blockIdx.y * 128, bn = blockIdx.x * 128;

    // loader: row = tid>>1 (128 rows), logical chunks seg, seg+1
    const int r2 = tid >> 1, seg = (tid & 1) * 2;
    const uint32_t xr2 = ((uint32_t)r2 >> 1) & 3;
    const uint32_t pc0 = ((uint32_t)(seg)     ^ xr2) << 4;
    const uint32_t pc1 = ((uint32_t)(seg | 1) ^ xr2) << 4;
    const uint32_t rowo = (uint32_t)r2 * 64;

    // ldmatrix lane constants (A fragment)
    const uint32_t arow = (uint32_t)(warp_m * 32 + (lane & 15)) * 64;
    const uint32_t xrA = (((uint32_t)lane & 15) >> 1) & 3;
    const uint32_t hcA = (uint32_t)lane >> 4;                 // 0/1
    const uint32_t axc0 = ((0 + hcA) ^ xrA) << 4;             // ks=0
    const uint32_t axc1 = ((2 + hcA) ^ xrA) << 4;             // ks=1
    // B fragment
    const uint32_t brow = (uint32_t)(warp_n * 64 + ((lane >> 4) & 1) * 8 +
                                     (lane & 7)) * 64;
    const uint32_t xrB = (((uint32_t)lane & 7) >> 1) & 3;
    const uint32_t hcB = ((uint32_t)lane >> 3) & 1;
    const uint32_t bxc0 = ((0 + hcB) ^ xrB) << 4;
    const uint32_t bxc1 = ((2 + hcB) ^ xrB) << 4;

    float acc[2][8][4];
#pragma unroll
    for (int mt = 0; mt < 2; mt++)
#pragma unroll
        for (int nt = 0; nt < 8; nt++)
#pragma unroll
            for (int e = 0; e < 4; e++) acc[mt][nt][e] = 0.0f;

    auto issue = [&](int c, int stg) {
        const int k0 = c << 5;
        const uint32_t so = sb + stg * STG4;
        const __nv_bfloat16* ahp = Ah + (size_t)(bm + r2) * HID + k0 + seg * 8;
        const __nv_bfloat16* alp = Al + (size_t)(bm + r2) * HID + k0 + seg * 8;
        const __nv_bfloat16* bhp = Bh + (size_t)(bn + r2) * HID + k0 + seg * 8;
        const __nv_bfloat16* blp = Bl + (size_t)(bn + r2) * HID + k0 + seg * 8;
        cp16(so + rowo + pc0,            ahp);
        cp16(so + rowo + pc1,            ahp + 8);
        cp16(so + TLB4 + rowo + pc0,     alp);
        cp16(so + TLB4 + rowo + pc1,     alp + 8);
        cp16(so + 2 * TLB4 + rowo + pc0, bhp);
        cp16(so + 2 * TLB4 + rowo + pc1, bhp + 8);
        cp16(so + 3 * TLB4 + rowo + pc0, blp);
        cp16(so + 3 * TLB4 + rowo + pc1, blp + 8);
    };

    issue(0, 0);
    asm volatile("cp.async.commit_group;" ::: "memory");
    issue(1, 1);
    asm volatile("cp.async.commit_group;" ::: "memory");

    for (int c = 0; c < NKCHUNK; c++) {
        asm volatile("cp.async.wait_group 1;" ::: "memory");
        __syncthreads();   // publishes stage c%3; reads of (c+2)%3 done at c-1
        if (c + 2 < NKCHUNK) {
            int stg = c + 2;
            stg -= (stg / GSTAGES4) * GSTAGES4;
            issue(c + 2, stg);
        }
        asm volatile("cp.async.commit_group;" ::: "memory");

        int stgc = c;
        stgc -= (stgc / GSTAGES4) * GSTAGES4;
        const uint32_t so = stgc * STG4;
        const uint32_t aB = sb + so + arow;
        const uint32_t bB = sb + so + 2 * TLB4 + brow;
#pragma unroll
        for (int ks = 0; ks < 2; ks++) {
            const uint32_t axc = ks ? axc1 : axc0;
            const uint32_t bxc = ks ? bxc1 : bxc0;
            uint32_t ah[2][4], al[2][4];
#pragma unroll
            for (int mt = 0; mt < 2; mt++) {
                ldsm_x4(ah[mt], aB + mt * 1024 + axc);
                ldsm_x4(al[mt], aB + TLB4 + mt * 1024 + axc);
            }
#pragma unroll
            for (int ng = 0; ng < 4; ng++) {
                uint32_t bh4[4], bl4[4];
                ldsm_x4(bh4, bB + ng * 1024 + bxc);
                ldsm_x4(bl4, bB + TLB4 + ng * 1024 + bxc);
#pragma unroll
                for (int mt = 0; mt < 2; mt++) {
                    mma_bf16(acc[mt][2 * ng],     ah[mt], bh4[0], bh4[1]);
                    mma_bf16(acc[mt][2 * ng],     al[mt], bh4[0], bh4[1]);
                    mma_bf16(acc[mt][2 * ng],     ah[mt], bl4[0], bl4[1]);
                    mma_bf16(acc[mt][2 * ng + 1], ah[mt], bh4[2], bh4[3]);
                    mma_bf16(acc[mt][2 * ng + 1], al[mt], bh4[2], bh4[3]);
                    mma_bf16(acc[mt][2 * ng + 1], ah[mt], bl4[2], bl4[3]);
                }
            }
        }
    }

    const int r0 = bm + warp_m * 32 + (lane >> 2);
    const int c0 = bn + warp_n * 64 + (lane & 3) * 2;
#pragma unroll
    for (int mt = 0; mt < 2; mt++) {
#pragma unroll
        for (int half = 0; half < 2; half++) {
            const int row = r0 + mt * 16 + half * 8;
            const int s = row & (SEQ - 1);
#pragma unroll
            for (int nt = 0; nt < 8; nt++) {
                const int col = c0 + nt * 8;
                float e  = acc[mt][nt][half * 2 + 0] + bias[col];
                float od = acc[mt][nt][half * 2 + 1] + bias[col + 1];
                if (mode == 1) {
                    const int j = (col & (HD - 1)) >> 1;
                    const float sn = stab[(s << 6) + j];
                    const float cs = ctab[(s << 6) + j];
                    float re = e * cs - od * sn;
                    float ro = od * cs + e * sn;
                    e = re * oscale;
                    od = ro * oscale;
                }
                if (mode == 0) {
                    float2 r;
                    r.x = e; r.y = od;
                    *(float2*)(Yf + (size_t)row * HID + col) = r;
                } else {
                    // FP16 hi/lo output (bit-container bf16 buffers)
                    __half h0, l0, h1, l1;
                    splith(e, h0, l0);
                    splith(od, h1, l1);
                    *(uint32_t*)(Yh + (size_t)row * HID + col) = pk2h(h0, h1);
                    *(uint32_t*)(Yl + (size_t)row * HID + col) = pk2h(l0, l1);
                }
            }
        }
    }
}

// Q scale folds softmax 1/sqrt(128) AND log2(e) (base-2 softmax)
#define QSCALE (0.08838834764831843f * 1.4426950408889634f)

__global__ void __launch_bounds__(256, 2) mma_gemm_qkv_kernel(
    const __nv_bfloat16* xh, const __nv_bfloat16* xl,
    const __nv_bfloat16* wqh, const __nv_bfloat16* wql,
    const __nv_bfloat16* wkh, const __nv_bfloat16* wkl,
    const __nv_bfloat16* wvh, const __nv_bfloat16* wvl,
    const float* bq, const float* bk, const float* bv,
    __nv_bfloat16* qh, __nv_bfloat16* ql,
    __nv_bfloat16* kh, __nv_bfloat16* kl,
    __nv_bfloat16* vh, __nv_bfloat16* vl,
    const float* stab, const float* ctab)
{
    if (blockIdx.z == 0)
        gemm_mma_body(xh, xl, wqh, wql, bq, nullptr, qh, ql,
                      QSCALE, stab, ctab, 1);
    else if (blockIdx.z == 1)
        gemm_mma_body(xh, xl, wkh, wkl, bk, nullptr, kh, kl, 1.0f, stab, ctab, 1);
    else
        gemm_mma_body(xh, xl, wvh, wvl, bv, nullptr, vh, vl, 1.0f, nullptr, nullptr, 2);
}

__global__ void __launch_bounds__(256, 2) mma_gemm_out_kernel(
    const __nv_bfloat16* ah, const __nv_bfloat16* al,
    const __nv_bfloat16* wh, const __nv_bfloat16* wl,
    const float* bo, float* Y)
{
    gemm_mma_body(ah, al, wh, wl, bo, Y, nullptr, nullptr, 1.0f, nullptr, nullptr, 0);
}

// ---------------------------------------------------------------------------
// Flash attention v4 (unchanged from R10): FP16 tensor-core.
// S = 3-product fp16 split; PV = 2-product. Base-2 softmax.
// ---------------------------------------------------------------------------
#define BR 128
#define BC 64
#define RQ 136
#define RB (RQ*2)
#define QBYTES (BR*RB)          // 34816
#define QTOT (2*QBYTES)         // 69632
#define KVSTG (4*BC*RB)         // 69632
#define FL2_SMEM (QTOT + 2*KVSTG)   // 208896
#define NKT (SEQ/BC)            // 32

__global__ void __launch_bounds__(256, 1) flash2_kernel(
    const __nv_bfloat16* __restrict__ Qh, const __nv_bfloat16* __restrict__ Ql,
    const __nv_bfloat16* __restrict__ Kh, const __nv_bfloat16* __restrict__ Kl,
    const __nv_bfloat16* __restrict__ Vh, const __nv_bfloat16* __restrict__ Vl,
    __nv_bfloat16* __restrict__ CtxH, __nv_bfloat16* __restrict__ CtxL)
{
    extern __shared__ __align__(128) char smem[];
    const uint32_t sb = smem_to_u32(smem);
    const int tid = threadIdx.x;
    const int wid = tid >> 5, lane = tid & 31;
    const int bh = blockIdx.y;
    const int b = bh >> 4, h = bh & 15;
    const int q0 = blockIdx.x * BR;
    const size_t rowbase = (size_t)b * SEQ;
    const int coff = h * HD;

    {
        const int row = tid >> 1;
        const int ch0 = (tid & 1) * 8;
        const size_t gq = (rowbase + q0 + row) * HID + coff;
        const __nv_bfloat16* sh = Qh + gq;
        const __nv_bfloat16* sl = Ql + gq;
#pragma unroll
        for (int c = 0; c < 8; c++) {
            const int ch = ch0 + c;
            cp16(sb + row * RB + ch * 16, sh + ch * 8);
            cp16(sb + QBYTES + row * RB + ch * 16, sl + ch * 8);
        }
    }

    auto issue_kv = [&](int kt, int stg) {
        const int row = tid >> 2;
        const int cq = tid & 3;
        const size_t g = (rowbase + (size_t)kt * BC + row) * HID + coff;
        const uint32_t base = sb + QTOT + stg * KVSTG + row * RB;
#pragma unroll
        for (int c = 0; c < 4; c++) {
            const int ch = cq + c * 4;
            cp16(base + ch * 16,         Kh + g + ch * 8);
            cp16(base + 17408 + ch * 16, Kl + g + ch * 8);
            cp16(base + 34816 + ch * 16, Vh + g + ch * 8);
            cp16(base + 52224 + ch * 16, Vl + g + ch * 8);
        }
    };

    issue_kv(0, 0);
    asm volatile("cp.async.commit_group;" ::: "memory");

    float m0 = -1e30f, m1 = -1e30f, l0 = 0.0f, l1 = 0.0f;
    float oacc[16][4];
#pragma unroll
    for (int nt = 0; nt < 16; nt++)
#pragma unroll
        for (int e = 0; e < 4; e++) oacc[nt][e] = 0.0f;

    const uint32_t qBh = sb + (wid * 16 + (lane & 15)) * RB + ((lane >> 4) * 8) * 2;
    const uint32_t qBl = qBh + QBYTES;
    const uint32_t kRel = (((lane >> 4) & 1) * 8 + (lane & 7)) * RB +
                          (((lane >> 3) & 1) * 8) * 2;
    const uint32_t vRel = (lane & 15) * RB + ((lane >> 4) * 8) * 2;

    for (int kt = 0; kt < NKT; kt++) {
        asm volatile("cp.async.wait_group 0;" ::: "memory");
        __syncthreads();
        if (kt + 1 < NKT) {
            issue_kv(kt + 1, (kt + 1) & 1);
            asm volatile("cp.async.commit_group;" ::: "memory");
        }

        const uint32_t kb = sb + QTOT + (kt & 1) * KVSTG;

        // ---- S = Q K^T (fp16, 3 products); log2-domain scores ----
        float sacc[8][4];
#pragma unroll
        for (int nt = 0; nt < 8; nt++)
#pragma unroll
            for (int e = 0; e < 4; e++) sacc[nt][e] = 0.0f;

#pragma unroll
        for (int ks = 0; ks < 8; ks++) {
            uint32_t qa[4], ql4[4];
            ldsm_x4(qa, qBh + ks * 32);
            ldsm_x4(ql4, qBl + ks * 32);
#pragma unroll
            for (int ng = 0; ng < 4; ng++) {
                uint32_t bh4[4], bl4[4];
                const uint32_t ka = kb + kRel + ng * (16 * RB) + ks * 32;
                ldsm_x4(bh4, ka);
                ldsm_x4(bl4, ka + 17408);
                mma_f16(sacc[2 * ng],     qa,  bh4[0], bh4[1]);
                mma_f16(sacc[2 * ng],     ql4, bh4[0], bh4[1]);
                mma_f16(sacc[2 * ng],     qa,  bl4[0], bl4[1]);
                mma_f16(sacc[2 * ng + 1], qa,  bh4[2], bh4[3]);
                mma_f16(sacc[2 * ng + 1], ql4, bh4[2], bh4[3]);
                mma_f16(sacc[2 * ng + 1], qa,  bl4[2], bl4[3]);
            }
        }

        // ---- row max + rescale ----
        float mx0 = -1e30f, mx1 = -1e30f;
#pragma unroll
        for (int nt = 0; nt < 8; nt++) {
            mx0 = fmaxf(mx0, fmaxf(sacc[nt][0], sacc[nt][1]));
            mx1 = fmaxf(mx1, fmaxf(sacc[nt][2], sacc[nt][3]));
        }
        mx0 = fmaxf(mx0, __shfl_xor_sync(0xffffffffu, mx0, 1));
        mx0 = fmaxf(mx0, __shfl_xor_sync(0xffffffffu, mx0, 2));
        mx1 = fmaxf(mx1, __shfl_xor_sync(0xffffffffu, mx1, 1));
        mx1 = fmaxf(mx1, __shfl_xor_sync(0xffffffffu, mx1, 2));

        const float mn0 = fmaxf(m0, mx0);
        const float mn1 = fmaxf(m1, mx1);
        const float corr0 = fexp2(m0 - mn0);
        const float corr1 = fexp2(m1 - mn1);
        m0 = mn0;
        m1 = mn1;
#pragma unroll
        for (int nt = 0; nt < 16; nt++) {
            oacc[nt][0] *= corr0;
            oacc[nt][1] *= corr0;
            oacc[nt][2] *= corr1;
            oacc[nt][3] *= corr1;
        }

        // ---- PV (fp16, 2 products: ph*vh + ph*vl); exp interleaved ----
        const uint32_t vb = kb + 34816;
        float rs0 = 0.0f, rs1 = 0.0f;
#pragma unroll
        for (int ks2 = 0; ks2 < 4; ks2++) {
            uint32_t ah[4];
#pragma unroll
            for (int j = 0; j < 2; j++) {
                const int nt = 2 * ks2 + j;
                float p00 = fexp2(sacc[nt][0] - mn0);
                float p01 = fexp2(sacc[nt][1] - mn0);
                float p10 = fexp2(sacc[nt][2] - mn1);
                float p11 = fexp2(sacc[nt][3] - mn1);
                rs0 += p00 + p01;
                rs1 += p10 + p11;
                ah[2 * j]     = pk2hf(p00, p01);
                ah[2 * j + 1] = pk2hf(p10, p11);
            }
#pragma unroll
            for (int ng = 0; ng < 8; ng++) {
                uint32_t vh4[4], vl4[4];
                const uint32_t va = vb + vRel + ks2 * (16 * RB) + ng * 32;
                ldsm_x4_t(vh4, va);
                ldsm_x4_t(vl4, va + 17408);
                mma_f16(oacc[2 * ng],     ah, vh4[0], vh4[1]);
                mma_f16(oacc[2 * ng],     ah, vl4[0], vl4[1]);
                mma_f16(oacc[2 * ng + 1], ah, vh4[2], vh4[3]);
                mma_f16(oacc[2 * ng + 1], ah, vl4[2], vl4[3]);
            }
        }

        rs0 += __shfl_xor_sync(0xffffffffu, rs0, 1);
        rs0 += __shfl_xor_sync(0xffffffffu, rs0, 2);
        rs1 += __shfl_xor_sync(0xffffffffu, rs1, 1);
        rs1 += __shfl_xor_sync(0xffffffffu, rs1, 2);
        l0 = l0 * corr0 + rs0;
        l1 = l1 * corr1 + rs1;
    }

    const float inv0 = 1.0f / l0;
    const float inv1 = 1.0f / l1;
    const size_t row0 = rowbase + q0 + wid * 16 + (lane >> 2);
    const size_t row1 = row0 + 8;
    const int cb = coff + (lane & 3) * 2;
#pragma unroll
    for (int nt = 0; nt < 16; nt++) {
        const int col = cb + nt * 8;
        __nv_bfloat16 h0, lo0, h1, lo1;
        splitf(oacc[nt][0] * inv0, h0, lo0);
        splitf(oacc[nt][1] * inv0, h1, lo1);
        *(uint32_t*)(CtxH + row0 * HID + col) = pk2(h0, h1);
        *(uint32_t*)(CtxL + row0 * HID + col) = pk2(lo0, lo1);
        splitf(oacc[nt][2] * inv1, h0, lo0);
        splitf(oacc[nt][3] * inv1, h1, lo1);
        *(uint32_t*)(CtxH + row1 * HID + col) = pk2(h0, h1);
        *(uint32_t*)(CtxL + row1 * HID + col) = pk2(lo0, lo1);
    }
}

// ---------------------------------------------------------------------------
extern "C" void kernel_launch(void* const* d_in, const int* in_sizes, int n_in,
                              void* d_out, int out_size)
{
    const float* X  = (const float*)d_in[0];
    const float* Wq = (const float*)d_in[1];
    const float* bq = (const float*)d_in[2];
    const float* Wk = (const float*)d_in[3];
    const float* bk = (const float*)d_in[4];
    const float* Wv = (const float*)d_in[5];
    const float* bv = (const float*)d_in[6];
    const float* Wo = (const float*)d_in[7];
    const float* bo = (const float*)d_in[8];
    float* out = (float*)d_out;

    __nv_bfloat16 *xh, *xl, *wqh, *wql, *wkh, *wkl, *wvh, *wvl, *woh, *wol;
    __nv_bfloat16 *qh, *ql, *kh, *kl, *vh, *vl, *cxh, *cxl;
    float *stab, *ctab;
    cudaGetSymbolAddress((void**)&xh,  g_xh);
    cudaGetSymbolAddress((void**)&xl,  g_xl);
    cudaGetSymbolAddress((void**)&wqh, g_wqh);
    cudaGetSymbolAddress((void**)&wql, g_wql);
    cudaGetSymbolAddress((void**)&wkh, g_wkh);
    cudaGetSymbolAddress((void**)&wkl, g_wkl);
    cudaGetSymbolAddress((void**)&wvh, g_wvh);
    cudaGetSymbolAddress((void**)&wvl, g_wvl);
    cudaGetSymbolAddress((void**)&woh, g_woh);
    cudaGetSymbolAddress((void**)&wol, g_wol);
    cudaGetSymbolAddress((void**)&qh,  g_qh);
    cudaGetSymbolAddress((void**)&ql,  g_ql);
    cudaGetSymbolAddress((void**)&kh,  g_kh);
    cudaGetSymbolAddress((void**)&kl,  g_kl);
    cudaGetSymbolAddress((void**)&vh,  g_vh);
    cudaGetSymbolAddress((void**)&vl,  g_vl);
    cudaGetSymbolAddress((void**)&cxh, g_cxh);
    cudaGetSymbolAddress((void**)&cxl, g_cxl);
    cudaGetSymbolAddress((void**)&stab, g_sin);
    cudaGetSymbolAddress((void**)&ctab, g_cos);

    cudaFuncSetAttribute(mma_gemm_qkv_kernel,
                         cudaFuncAttributeMaxDynamicSharedMemorySize, GSMEM4);
    cudaFuncSetAttribute(mma_gemm_out_kernel,
                         cudaFuncAttributeMaxDynamicSharedMemorySize, GSMEM4);
    cudaFuncSetAttribute(flash2_kernel,
                         cudaFuncAttributeMaxDynamicSharedMemorySize, FL2_SMEM);

    // launch 0: RoPE table + X split (fused)
    prep0_kernel<<<512 + (int)(((size_t)M_ROWS * HID / 4) / 256), 256>>>(
        stab, ctab, (const float4*)X, (uint2*)xh, (uint2*)xl);

    // launch 1: transpose + split all 4 weights
    {
        dim3 g(HID / 32, HID / 32, 4), blk(32, 8);
        wtrans4_kernel<<<g, blk>>>(Wq, wqh, wql, Wk, wkh, wkl,
                                   Wv, wvh, wvl, Wo, woh, wol);
    }

    // launch 2: dummy (keeps ncu capture idx 3 = qkv GEMM)
    dummy_kernel<<<1, 32>>>();

    // launch 3: QKV projections + bias + RoPE -> fp16 hi/lo q/k/v
    {
        dim3 grid(HID / 128, M_ROWS / 128, 3);
        mma_gemm_qkv_kernel<<<grid, 256, GSMEM4>>>(
            xh, xl, wqh, wql, wkh, wkl, wvh, wvl, bq, bk, bv,
            qh, ql, kh, kl, vh, vl, stab, ctab);
    }

    // launch 4: flash attention (fp16 tensor cores) -> bf16 hi/lo context
    {
        dim3 grid(SEQ / BR, BATCH * NH);
        flash2_kernel<<<grid, 256, FL2_SMEM>>>(qh, ql, kh, kl, vh, vl, cxh, cxl);
    }

    // launch 5: output projection + bias -> out
    {
        dim3 grid(HID / 128, M_ROWS / 128);
        mma_gemm_out_kernel<<<grid, 256, GSMEM4>>>(cxh, cxl, woh, wol, bo, out);
    }
}

// round 12
// speedup vs baseline: 1.5299x; 1.1962x over previous
#include <cuda_runtime.h>
#include <cuda_bf16.h>
#include <cuda_fp16.h>
#include <cstdint>
#include <math.h>

#define HID 2048
#define SEQ 2048
#define NH  16
#define HD  128
#define BATCH 2
#define M_ROWS (BATCH*SEQ)   // 4096

// ---------------------------------------------------------------------------
// Scratch (__device__ globals; no allocation allowed).
// ALL split buffers now hold PACKED FP16 bits (bf16-typed bit containers).
// ---------------------------------------------------------------------------
__device__ __nv_bfloat16 g_xh[(size_t)M_ROWS * HID];
__device__ __nv_bfloat16 g_xl[(size_t)M_ROWS * HID];
__device__ __nv_bfloat16 g_wqh[(size_t)HID * HID];
__device__ __nv_bfloat16 g_wql[(size_t)HID * HID];
__device__ __nv_bfloat16 g_wkh[(size_t)HID * HID];
__device__ __nv_bfloat16 g_wkl[(size_t)HID * HID];
__device__ __nv_bfloat16 g_wvh[(size_t)HID * HID];
__device__ __nv_bfloat16 g_wvl[(size_t)HID * HID];
__device__ __nv_bfloat16 g_woh[(size_t)HID * HID];
__device__ __nv_bfloat16 g_wol[(size_t)HID * HID];
__device__ __nv_bfloat16 g_qh[(size_t)M_ROWS * HID];
__device__ __nv_bfloat16 g_ql[(size_t)M_ROWS * HID];
__device__ __nv_bfloat16 g_kh[(size_t)M_ROWS * HID];
__device__ __nv_bfloat16 g_kl[(size_t)M_ROWS * HID];
__device__ __nv_bfloat16 g_vh[(size_t)M_ROWS * HID];
__device__ __nv_bfloat16 g_vl[(size_t)M_ROWS * HID];
__device__ __nv_bfloat16 g_cxh[(size_t)M_ROWS * HID];
__device__ __nv_bfloat16 g_cxl[(size_t)M_ROWS * HID];
__device__ float g_sin[SEQ * (HD/2)];
__device__ float g_cos[SEQ * (HD/2)];

// ---------------------------------------------------------------------------
// helpers
// ---------------------------------------------------------------------------
__device__ __forceinline__ uint32_t smem_to_u32(const void* p) {
    uint32_t a;
    asm("{ .reg .u64 t; cvta.to.shared.u64 t, %1; cvt.u32.u64 %0, t; }"
        : "=r"(a) : "l"(p));
    return a;
}

__device__ __forceinline__ void cp16(uint32_t dst, const void* src) {
    asm volatile("cp.async.cg.shared.global [%0], [%1], 16;"
                 :: "r"(dst), "l"(src) : "memory");
}

__device__ __forceinline__ void ldsm_x4(uint32_t* r, uint32_t addr) {
    asm volatile("ldmatrix.sync.aligned.m8n8.x4.shared.b16 {%0,%1,%2,%3}, [%4];"
                 : "=r"(r[0]), "=r"(r[1]), "=r"(r[2]), "=r"(r[3]) : "r"(addr));
}

__device__ __forceinline__ void ldsm_x4_t(uint32_t* r, uint32_t addr) {
    asm volatile("ldmatrix.sync.aligned.m8n8.x4.trans.shared.b16 {%0,%1,%2,%3}, [%4];"
                 : "=r"(r[0]), "=r"(r[1]), "=r"(r[2]), "=r"(r[3]) : "r"(addr));
}

__device__ __forceinline__ void mma_f16(float* c, const uint32_t* a,
                                        uint32_t b0, uint32_t b1) {
    asm volatile(
        "mma.sync.aligned.m16n8k16.row.col.f32.f16.f16.f32 "
        "{%0,%1,%2,%3}, {%4,%5,%6,%7}, {%8,%9}, {%0,%1,%2,%3};"
        : "+f"(c[0]), "+f"(c[1]), "+f"(c[2]), "+f"(c[3])
        : "r"(a[0]), "r"(a[1]), "r"(a[2]), "r"(a[3]), "r"(b0), "r"(b1));
}

// fp16 split + pack
__device__ __forceinline__ void splith(float v, __half& h, __half& l) {
    h = __float2half_rn(v);
    l = __float2half_rn(v - __half2float(h));
}
__device__ __forceinline__ uint32_t pk2h(__half a, __half b) {
    __half2 t = __halves2half2(a, b);
    return *reinterpret_cast<uint32_t*>(&t);
}
__device__ __forceinline__ uint32_t pk2hf(float a, float b) {
    __half2 t = __floats2half2_rn(a, b);
    return *reinterpret_cast<uint32_t*>(&t);
}

// fast 2^t on the FMA pipe. t <= 0 expected; clamped at -30.
__device__ __forceinline__ float fexp2(float t) {
    t = fmaxf(t, -30.0f);
    const float fi = t + 12582912.0f;          // 1.5*2^23 round-to-int
    const float r  = fi - 12582912.0f;
    const float f  = t - r;
    float p = 1.3333558146e-3f;
    p = fmaf(p, f, 9.6181291076e-3f);
    p = fmaf(p, f, 5.5504108665e-2f);
    p = fmaf(p, f, 2.4022650696e-1f);
    p = fmaf(p, f, 6.9314718056e-1f);
    p = fmaf(p, f, 1.0f);
    const int e = __float_as_int(fi) - 0x4B400000;
    return __int_as_float(__float_as_int(p) + (e << 23));
}

// ---------------------------------------------------------------------------
// Prep kernel 0: RoPE table (blocks 0..511) + X split fp16 (blocks 512..)
// ---------------------------------------------------------------------------
__global__ void __launch_bounds__(256) prep0_kernel(
    float* __restrict__ st, float* __restrict__ ct,
    const float4* __restrict__ X, uint2* __restrict__ H, uint2* __restrict__ L)
{
    const int bid = blockIdx.x;
    if (bid < 512) {
        int idx = bid * 256 + threadIdx.x;   // SEQ*64 total
        int s = idx >> 6, j = idx & 63;
        double f = exp(-0.14391156831212787 * (double)j);  // 10000^(-2j/128)
        double sn, cs;
        sincos((double)s * f, &sn, &cs);
        st[idx] = (float)sn;
        ct[idx] = (float)cs;
    } else {
        size_t i = (size_t)(bid - 512) * 256 + threadIdx.x;
        float4 v = X[i];
        __half h0, l0, h1, l1, h2, l2, h3, l3;
        splith(v.x, h0, l0); splith(v.y, h1, l1);
        splith(v.z, h2, l2); splith(v.w, h3, l3);
        H[i] = make_uint2(pk2h(h0, h1), pk2h(h2, h3));
        L[i] = make_uint2(pk2h(l0, l1), pk2h(l2, l3));
    }
}

// Prep kernel 1: all four W [K][N] fp32 -> Wt [N][K] fp16 hi/lo; z selects.
__global__ void __launch_bounds__(256) wtrans4_kernel(
    const float* __restrict__ W0, __nv_bfloat16* Th0, __nv_bfloat16* Tl0,
    const float* __restrict__ W1, __nv_bfloat16* Th1, __nv_bfloat16* Tl1,
    const float* __restrict__ W2, __nv_bfloat16* Th2, __nv_bfloat16* Tl2,
    const float* __restrict__ W3, __nv_bfloat16* Th3, __nv_bfloat16* Tl3)
{
    const float* W;
    __nv_bfloat16 *Th, *Tl;
    switch (blockIdx.z) {
        case 0:  W = W0; Th = Th0; Tl = Tl0; break;
        case 1:  W = W1; Th = Th1; Tl = Tl1; break;
        case 2:  W = W2; Th = Th2; Tl = Tl2; break;
        default: W = W3; Th = Th3; Tl = Tl3; break;
    }
    __shared__ float t[32][33];
    const int n0 = blockIdx.x * 32, k0 = blockIdx.y * 32;
    const int tx = threadIdx.x, ty = threadIdx.y;   // (32, 8)
#pragma unroll
    for (int i = 0; i < 4; i++)
        t[ty + 8 * i][tx] = W[(size_t)(k0 + ty + 8 * i) * HID + n0 + tx];
    __syncthreads();
#pragma unroll
    for (int i = 0; i < 4; i++) {
        float v = t[tx][ty + 8 * i];
        __half h, l;
        splith(v, h, l);
        const size_t o = (size_t)(n0 + ty + 8 * i) * HID + k0 + tx;
        *(uint16_t*)(Th + o) = *(uint16_t*)&h;
        *(uint16_t*)(Tl + o) = *(uint16_t*)&l;
    }
}

// tiny dummy to shift ncu capture index so idx 3 = qkv GEMM
__global__ void dummy_kernel() {}

// ---------------------------------------------------------------------------
// GEMM v5a (QKV): fp16 2-product. 256 thr / 8 warps, 2 CTAs/SM.
// BM=128, BN=128, BK=32. Tiles: [Ah][Al][Bh], 64B rows + XOR swizzle.
// Stage = 24KB; FOUR stages (96KB/CTA), prefetch depth 3 (wait_group 2).
// Y = (Ah+Al) * Bh^T; bias (+RoPE); outputs fp16 hi/lo.
// ---------------------------------------------------------------------------
#define TQ 8192
#define STGQ (3*TQ)                     // 24576
#define QSTAGES 4
#define GSMEMQ (QSTAGES*STGQ)           // 98304
#define NKCHUNK (HID / 32)              // 64

__device__ __forceinline__ void gemm_qkv_body(
    const __nv_bfloat16* __restrict__ Ah, const __nv_bfloat16* __restrict__ Al,
    const __nv_bfloat16* __restrict__ Bh,
    const float* __restrict__ bias,
    __nv_bfloat16* __restrict__ Yh, __nv_bfloat16* __restrict__ Yl,
    float oscale, const float* __restrict__ stab,
    const float* __restrict__ ctab, int rope)
{
    extern __shared__ __align__(128) char smem[];
    const uint32_t sb = smem_to_u32(smem);
    const int tid = threadIdx.x;
    const int wid = tid >> 5, lane = tid & 31;
    const int warp_m = wid & 3, warp_n = wid >> 2;   // 4 x 2 warps
    const int bm = blockIdx.y * 128, bn = blockIdx.x * 128;

    const int r2 = tid >> 1, seg = (tid & 1) * 2;
    const uint32_t xr2 = ((uint32_t)r2 >> 1) & 3;
    const uint32_t pc0 = ((uint32_t)(seg)     ^ xr2) << 4;
    const uint32_t pc1 = ((uint32_t)(seg | 1) ^ xr2) << 4;
    const uint32_t rowo = (uint32_t)r2 * 64;

    const uint32_t arow = (uint32_t)(warp_m * 32 + (lane & 15)) * 64;
    const uint32_t xrA = (((uint32_t)lane & 15) >> 1) & 3;
    const uint32_t hcA = (uint32_t)lane >> 4;
    const uint32_t axc0 = ((0 + hcA) ^ xrA) << 4;
    const uint32_t axc1 = ((2 + hcA) ^ xrA) << 4;
    const uint32_t brow = (uint32_t)(warp_n * 64 + ((lane >> 4) & 1) * 8 +
                                     (lane & 7)) * 64;
    const uint32_t xrB = (((uint32_t)lane & 7) >> 1) & 3;
    const uint32_t hcB = ((uint32_t)lane >> 3) & 1;
    const uint32_t bxc0 = ((0 + hcB) ^ xrB) << 4;
    const uint32_t bxc1 = ((2 + hcB) ^ xrB) << 4;

    float acc[2][8][4];
#pragma unroll
    for (int mt = 0; mt < 2; mt++)
#pragma unroll
        for (int nt = 0; nt < 8; nt++)
#pragma unroll
            for (int e = 0; e < 4; e++) acc[mt][nt][e] = 0.0f;

    auto issue = [&](int c, int stg) {
        const int k0 = c << 5;
        const uint32_t so = sb + stg * STGQ;
        const __nv_bfloat16* ahp = Ah + (size_t)(bm + r2) * HID + k0 + seg * 8;
        const __nv_bfloat16* alp = Al + (size_t)(bm + r2) * HID + k0 + seg * 8;
        const __nv_bfloat16* bhp = Bh + (size_t)(bn + r2) * HID + k0 + seg * 8;
        cp16(so + rowo + pc0,          ahp);
        cp16(so + rowo + pc1,          ahp + 8);
        cp16(so + TQ + rowo + pc0,     alp);
        cp16(so + TQ + rowo + pc1,     alp + 8);
        cp16(so + 2 * TQ + rowo + pc0, bhp);
        cp16(so + 2 * TQ + rowo + pc1, bhp + 8);
    };

#pragma unroll
    for (int s = 0; s < 3; s++) {
        issue(s, s);
        asm volatile("cp.async.commit_group;" ::: "memory");
    }

    for (int c = 0; c < NKCHUNK; c++) {
        asm volatile("cp.async.wait_group 2;" ::: "memory");
        __syncthreads();   // publishes stage c&3; reads of (c+3)&3 done at c-1
        if (c + 3 < NKCHUNK) issue(c + 3, (c + 3) & 3);
        asm volatile("cp.async.commit_group;" ::: "memory");

        const uint32_t so = (c & 3) * STGQ;
        const uint32_t aB = sb + so + arow;
        const uint32_t bB = sb + so + 2 * TQ + brow;
#pragma unroll
        for (int ks = 0; ks < 2; ks++) {
            const uint32_t axc = ks ? axc1 : axc0;
            const uint32_t bxc = ks ? bxc1 : bxc0;
            uint32_t ah[2][4], al[2][4];
#pragma unroll
            for (int mt = 0; mt < 2; mt++) {
                ldsm_x4(ah[mt], aB + mt * 1024 + axc);
                ldsm_x4(al[mt], aB + TQ + mt * 1024 + axc);
            }
#pragma unroll
            for (int ng = 0; ng < 4; ng++) {
                uint32_t bh4[4];
                ldsm_x4(bh4, bB + ng * 1024 + bxc);
#pragma unroll
                for (int mt = 0; mt < 2; mt++) {
                    mma_f16(acc[mt][2 * ng],     ah[mt], bh4[0], bh4[1]);
                    mma_f16(acc[mt][2 * ng],     al[mt], bh4[0], bh4[1]);
                    mma_f16(acc[mt][2 * ng + 1], ah[mt], bh4[2], bh4[3]);
                    mma_f16(acc[mt][2 * ng + 1], al[mt], bh4[2], bh4[3]);
                }
            }
        }
    }

    const int r0 = bm + warp_m * 32 + (lane >> 2);
    const int c0 = bn + warp_n * 64 + (lane & 3) * 2;
#pragma unroll
    for (int mt = 0; mt < 2; mt++) {
#pragma unroll
        for (int half = 0; half < 2; half++) {
            const int row = r0 + mt * 16 + half * 8;
            const int s = row & (SEQ - 1);
#pragma unroll
            for (int nt = 0; nt < 8; nt++) {
                const int col = c0 + nt * 8;
                float e  = acc[mt][nt][half * 2 + 0] + bias[col];
                float od = acc[mt][nt][half * 2 + 1] + bias[col + 1];
                if (rope) {
                    const int j = (col & (HD - 1)) >> 1;
                    const float sn = stab[(s << 6) + j];
                    const float cs = ctab[(s << 6) + j];
                    float re = e * cs - od * sn;
                    float ro = od * cs + e * sn;
                    e = re * oscale;
                    od = ro * oscale;
                }
                __half h0, l0, h1, l1;
                splith(e, h0, l0);
                splith(od, h1, l1);
                *(uint32_t*)(Yh + (size_t)row * HID + col) = pk2h(h0, h1);
                *(uint32_t*)(Yl + (size_t)row * HID + col) = pk2h(l0, l1);
            }
        }
    }
}

// Q scale folds softmax 1/sqrt(128) AND log2(e) (base-2 softmax)
#define QSCALE (0.08838834764831843f * 1.4426950408889634f)

__global__ void __launch_bounds__(256, 2) mma_gemm_qkv_kernel(
    const __nv_bfloat16* xh, const __nv_bfloat16* xl,
    const __nv_bfloat16* wqh, const __nv_bfloat16* wkh,
    const __nv_bfloat16* wvh,
    const float* bq, const float* bk, const float* bv,
    __nv_bfloat16* qh, __nv_bfloat16* ql,
    __nv_bfloat16* kh, __nv_bfloat16* kl,
    __nv_bfloat16* vh, __nv_bfloat16* vl,
    const float* stab, const float* ctab)
{
    if (blockIdx.z == 0)
        gemm_qkv_body(xh, xl, wqh, bq, qh, ql, QSCALE, stab, ctab, 1);
    else if (blockIdx.z == 1)
        gemm_qkv_body(xh, xl, wkh, bk, kh, kl, 1.0f, stab, ctab, 1);
    else
        gemm_qkv_body(xh, xl, wvh, bv, vh, vl, 1.0f, nullptr, nullptr, 0);
}

// ---------------------------------------------------------------------------
// GEMM v5b (out-proj): fp16 3-product (full accuracy). Structure = R11:
// 4 tiles [Ah][Al][Bh][Bl], 32KB stage, 3 stages, wait_group 1. fp32 out.
// ---------------------------------------------------------------------------
#define TLB4 8192
#define STG4 (4*TLB4)                   // 32768
#define GSTAGES4 3
#define GSMEM4 (GSTAGES4 * STG4)        // 98304

__global__ void __launch_bounds__(256, 2) mma_gemm_out_kernel(
    const __nv_bfloat16* __restrict__ Ah, const __nv_bfloat16* __restrict__ Al,
    const __nv_bfloat16* __restrict__ Bh, const __nv_bfloat16* __restrict__ Bl,
    const float* __restrict__ bias, float* __restrict__ Yf)
{
    extern __shared__ __align__(128) char smem[];
    const uint32_t sb = smem_to_u32(smem);
    const int tid = threadIdx.x;
    const int wid = tid >> 5, lane = tid & 31;
    const int warp_m = wid & 3, warp_n = wid >> 2;
    const int bm = blockIdx.y * 128, bn = blockIdx.x * 128;

    const int r2 = tid >> 1, seg = (tid & 1) * 2;
    const uint32_t xr2 = ((uint32_t)r2 >> 1) & 3;
    const uint32_t pc0 = ((uint32_t)(seg)     ^ xr2) << 4;
    const uint32_t pc1 = ((uint32_t)(seg | 1) ^ xr2) << 4;
    const uint32_t rowo = (uint32_t)r2 * 64;

    const uint32_t arow = (uint32_t)(warp_m * 32 + (lane & 15)) * 64;
    const uint32_t xrA = (((uint32_t)lane & 15) >> 1) & 3;
    const uint32_t hcA = (uint32_t)lane >> 4;
    const uint32_t axc0 = ((0 + hcA) ^ xrA) << 4;
    const uint32_t axc1 = ((2 + hcA) ^ xrA) << 4;
    const uint32_t brow = (uint32_t)(warp_n * 64 + ((lane >> 4) & 1) * 8 +
                                     (lane & 7)) * 64;
    const uint32_t xrB = (((uint32_t)lane & 7) >> 1) & 3;
    const uint32_t hcB = ((uint32_t)lane >> 3) & 1;
    const uint32_t bxc0 = ((0 + hcB) ^ xrB) << 4;
    const uint32_t bxc1 = ((2 + hcB) ^ xrB) << 4;

    float acc[2][8][4];
#pragma unroll
    for (int mt = 0; mt < 2; mt++)
#pragma unroll
        for (int nt = 0; nt < 8; nt++)
#pragma unroll
            for (int e = 0; e < 4; e++) acc[mt][nt][e] = 0.0f;

    auto issue = [&](int c, int stg) {
        const int k0 = c << 5;
        const uint32_t so = sb + stg * STG4;
        const __nv_bfloat16* ahp = Ah + (size_t)(bm + r2) * HID + k0 + seg * 8;
        const __nv_bfloat16* alp = Al + (size_t)(bm + r2) * HID + k0 + seg * 8;
        const __nv_bfloat16* bhp = Bh + (size_t)(bn + r2) * HID + k0 + seg * 8;
        const __nv_bfloat16* blp = Bl + (size_t)(bn + r2) * HID + k0 + seg * 8;
        cp16(so + rowo + pc0,            ahp);
        cp16(so + rowo + pc1,            ahp + 8);
        cp16(so + TLB4 + rowo + pc0,     alp);
        cp16(so + TLB4 + rowo + pc1,     alp + 8);
        cp16(so + 2 * TLB4 + rowo + pc0, bhp);
        cp16(so + 2 * TLB4 + rowo + pc1, bhp + 8);
        cp16(so + 3 * TLB4 + rowo + pc0, blp);
        cp16(so + 3 * TLB4 + rowo + pc1, blp + 8);
    };

    issue(0, 0);
    asm volatile("cp.async.commit_group;" ::: "memory");
    issue(1, 1);
    asm volatile("cp.async.commit_group;" ::: "memory");

    for (int c = 0; c < NKCHUNK; c++) {
        asm volatile("cp.async.wait_group 1;" ::: "memory");
        __syncthreads();
        if (c + 2 < NKCHUNK) {
            int stg = c + 2;
            stg -= (stg / GSTAGES4) * GSTAGES4;
            issue(c + 2, stg);
        }
        asm volatile("cp.async.commit_group;" ::: "memory");

        int stgc = c;
        stgc -= (stgc / GSTAGES4) * GSTAGES4;
        const uint32_t so = stgc * STG4;
        const uint32_t aB = sb + so + arow;
        const uint32_t bB = sb + so + 2 * TLB4 + brow;
#pragma unroll
        for (int ks = 0; ks < 2; ks++) {
            const uint32_t axc = ks ? axc1 : axc0;
            const uint32_t bxc = ks ? bxc1 : bxc0;
            uint32_t ah[2][4], al[2][4];
#pragma unroll
            for (int mt = 0; mt < 2; mt++) {
                ldsm_x4(ah[mt], aB + mt * 1024 + axc);
                ldsm_x4(al[mt], aB + TLB4 + mt * 1024 + axc);
            }
#pragma unroll
            for (int ng = 0; ng < 4; ng++) {
                uint32_t bh4[4], bl4[4];
                ldsm_x4(bh4, bB + ng * 1024 + bxc);
                ldsm_x4(bl4, bB + TLB4 + ng * 1024 + bxc);
#pragma unroll
                for (int mt = 0; mt < 2; mt++) {
                    mma_f16(acc[mt][2 * ng],     ah[mt], bh4[0], bh4[1]);
                    mma_f16(acc[mt][2 * ng],     al[mt], bh4[0], bh4[1]);
                    mma_f16(acc[mt][2 * ng],     ah[mt], bl4[0], bl4[1]);
                    mma_f16(acc[mt][2 * ng + 1], ah[mt], bh4[2], bh4[3]);
                    mma_f16(acc[mt][2 * ng + 1], al[mt], bh4[2], bh4[3]);
                    mma_f16(acc[mt][2 * ng + 1], ah[mt], bl4[2], bl4[3]);
                }
            }
        }
    }

    const int r0 = bm + warp_m * 32 + (lane >> 2);
    const int c0 = bn + warp_n * 64 + (lane & 3) * 2;
#pragma unroll
    for (int mt = 0; mt < 2; mt++) {
#pragma unroll
        for (int half = 0; half < 2; half++) {
            const int row = r0 + mt * 16 + half * 8;
#pragma unroll
            for (int nt = 0; nt < 8; nt++) {
                const int col = c0 + nt * 8;
                float2 r;
                r.x = acc[mt][nt][half * 2 + 0] + bias[col];
                r.y = acc[mt][nt][half * 2 + 1] + bias[col + 1];
                *(float2*)(Yf + (size_t)row * HID + col) = r;
            }
        }
    }
}

// ---------------------------------------------------------------------------
// Flash attention v4 (R10/R11 body): FP16 tensor-core. S = 3-product;
// PV = 2-product. Base-2 softmax. Ctx written as FP16 hi/lo.
// ---------------------------------------------------------------------------
#define BR 128
#define BC 64
#define RQ 136
#define RB (RQ*2)
#define QBYTES (BR*RB)          // 34816
#define QTOT (2*QBYTES)         // 69632
#define KVSTG (4*BC*RB)         // 69632
#define FL2_SMEM (QTOT + 2*KVSTG)   // 208896
#define NKT (SEQ/BC)            // 32

__global__ void __launch_bounds__(256, 1) flash2_kernel(
    const __nv_bfloat16* __restrict__ Qh, const __nv_bfloat16* __restrict__ Ql,
    const __nv_bfloat16* __restrict__ Kh, const __nv_bfloat16* __restrict__ Kl,
    const __nv_bfloat16* __restrict__ Vh, const __nv_bfloat16* __restrict__ Vl,
    __nv_bfloat16* __restrict__ CtxH, __nv_bfloat16* __restrict__ CtxL)
{
    extern __shared__ __align__(128) char smem[];
    const uint32_t sb = smem_to_u32(smem);
    const int tid = threadIdx.x;
    const int wid = tid >> 5, lane = tid & 31;
    const int bh = blockIdx.y;
    const int b = bh >> 4, h = bh & 15;
    const int q0 = blockIdx.x * BR;
    const size_t rowbase = (size_t)b * SEQ;
    const int coff = h * HD;

    {
        const int row = tid >> 1;
        const int ch0 = (tid & 1) * 8;
        const size_t gq = (rowbase + q0 + row) * HID + coff;
        const __nv_bfloat16* sh = Qh + gq;
        const __nv_bfloat16* sl = Ql + gq;
#pragma unroll
        for (int c = 0; c < 8; c++) {
            const int ch = ch0 + c;
            cp16(sb + row * RB + ch * 16, sh + ch * 8);
            cp16(sb + QBYTES + row * RB + ch * 16, sl + ch * 8);
        }
    }

    auto issue_kv = [&](int kt, int stg) {
        const int row = tid >> 2;
        const int cq = tid & 3;
        const size_t g = (rowbase + (size_t)kt * BC + row) * HID + coff;
        const uint32_t base = sb + QTOT + stg * KVSTG + row * RB;
#pragma unroll
        for (int c = 0; c < 4; c++) {
            const int ch = cq + c * 4;
            cp16(base + ch * 16,         Kh + g + ch * 8);
            cp16(base + 17408 + ch * 16, Kl + g + ch * 8);
            cp16(base + 34816 + ch * 16, Vh + g + ch * 8);
            cp16(base + 52224 + ch * 16, Vl + g + ch * 8);
        }
    };

    issue_kv(0, 0);
    asm volatile("cp.async.commit_group;" ::: "memory");

    float m0 = -1e30f, m1 = -1e30f, l0 = 0.0f, l1 = 0.0f;
    float oacc[16][4];
#pragma unroll
    for (int nt = 0; nt < 16; nt++)
#pragma unroll
        for (int e = 0; e < 4; e++) oacc[nt][e] = 0.0f;

    const uint32_t qBh = sb + (wid * 16 + (lane & 15)) * RB + ((lane >> 4) * 8) * 2;
    const uint32_t qBl = qBh + QBYTES;
    const uint32_t kRel = (((lane >> 4) & 1) * 8 + (lane & 7)) * RB +
                          (((lane >> 3) & 1) * 8) * 2;
    const uint32_t vRel = (lane & 15) * RB + ((lane >> 4) * 8) * 2;

    for (int kt = 0; kt < NKT; kt++) {
        asm volatile("cp.async.wait_group 0;" ::: "memory");
        __syncthreads();
        if (kt + 1 < NKT) {
            issue_kv(kt + 1, (kt + 1) & 1);
            asm volatile("cp.async.commit_group;" ::: "memory");
        }

        const uint32_t kb = sb + QTOT + (kt & 1) * KVSTG;

        // ---- S = Q K^T (fp16, 3 products); log2-domain scores ----
        float sacc[8][4];
#pragma unroll
        for (int nt = 0; nt < 8; nt++)
#pragma unroll
            for (int e = 0; e < 4; e++) sacc[nt][e] = 0.0f;

#pragma unroll
        for (int ks = 0; ks < 8; ks++) {
            uint32_t qa[4], ql4[4];
            ldsm_x4(qa, qBh + ks * 32);
            ldsm_x4(ql4, qBl + ks * 32);
#pragma unroll
            for (int ng = 0; ng < 4; ng++) {
                uint32_t bh4[4], bl4[4];
                const uint32_t ka = kb + kRel + ng * (16 * RB) + ks * 32;
                ldsm_x4(bh4, ka);
                ldsm_x4(bl4, ka + 17408);
                mma_f16(sacc[2 * ng],     qa,  bh4[0], bh4[1]);
                mma_f16(sacc[2 * ng],     ql4, bh4[0], bh4[1]);
                mma_f16(sacc[2 * ng],     qa,  bl4[0], bl4[1]);
                mma_f16(sacc[2 * ng + 1], qa,  bh4[2], bh4[3]);
                mma_f16(sacc[2 * ng + 1], ql4, bh4[2], bh4[3]);
                mma_f16(sacc[2 * ng + 1], qa,  bl4[2], bl4[3]);
            }
        }

        // ---- row max + rescale ----
        float mx0 = -1e30f, mx1 = -1e30f;
#pragma unroll
        for (int nt = 0; nt < 8; nt++) {
            mx0 = fmaxf(mx0, fmaxf(sacc[nt][0], sacc[nt][1]));
            mx1 = fmaxf(mx1, fmaxf(sacc[nt][2], sacc[nt][3]));
        }
        mx0 = fmaxf(mx0, __shfl_xor_sync(0xffffffffu, mx0, 1));
        mx0 = fmaxf(mx0, __shfl_xor_sync(0xffffffffu, mx0, 2));
        mx1 = fmaxf(mx1, __shfl_xor_sync(0xffffffffu, mx1, 1));
        mx1 = fmaxf(mx1, __shfl_xor_sync(0xffffffffu, mx1, 2));

        const float mn0 = fmaxf(m0, mx0);
        const float mn1 = fmaxf(m1, mx1);
        const float corr0 = fexp2(m0 - mn0);
        const float corr1 = fexp2(m1 - mn1);
        m0 = mn0;
        m1 = mn1;
#pragma unroll
        for (int nt = 0; nt < 16; nt++) {
            oacc[nt][0] *= corr0;
            oacc[nt][1] *= corr0;
            oacc[nt][2] *= corr1;
            oacc[nt][3] *= corr1;
        }

        // ---- PV (fp16, 2 products: ph*vh + ph*vl); exp interleaved ----
        const uint32_t vb = kb + 34816;
        float rs0 = 0.0f, rs1 = 0.0f;
#pragma unroll
        for (int ks2 = 0; ks2 < 4; ks2++) {
            uint32_t ah[4];
#pragma unroll
            for (int j = 0; j < 2; j++) {
                const int nt = 2 * ks2 + j;
                float p00 = fexp2(sacc[nt][0] - mn0);
                float p01 = fexp2(sacc[nt][1] - mn0);
                float p10 = fexp2(sacc[nt][2] - mn1);
                float p11 = fexp2(sacc[nt][3] - mn1);
                rs0 += p00 + p01;
                rs1 += p10 + p11;
                ah[2 * j]     = pk2hf(p00, p01);
                ah[2 * j + 1] = pk2hf(p10, p11);
            }
#pragma unroll
            for (int ng = 0; ng < 8; ng++) {
                uint32_t vh4[4], vl4[4];
                const uint32_t va = vb + vRel + ks2 * (16 * RB) + ng * 32;
                ldsm_x4_t(vh4, va);
                ldsm_x4_t(vl4, va + 17408);
                mma_f16(oacc[2 * ng],     ah, vh4[0], vh4[1]);
                mma_f16(oacc[2 * ng],     ah, vl4[0], vl4[1]);
                mma_f16(oacc[2 * ng + 1], ah, vh4[2], vh4[3]);
                mma_f16(oacc[2 * ng + 1], ah, vl4[2], vl4[3]);
            }
        }

        rs0 += __shfl_xor_sync(0xffffffffu, rs0, 1);
        rs0 += __shfl_xor_sync(0xffffffffu, rs0, 2);
        rs1 += __shfl_xor_sync(0xffffffffu, rs1, 1);
        rs1 += __shfl_xor_sync(0xffffffffu, rs1, 2);
        l0 = l0 * corr0 + rs0;
        l1 = l1 * corr1 + rs1;
    }

    const float inv0 = 1.0f / l0;
    const float inv1 = 1.0f / l1;
    const size_t row0 = rowbase + q0 + wid * 16 + (lane >> 2);
    const size_t row1 = row0 + 8;
    const int cb = coff + (lane & 3) * 2;
#pragma unroll
    for (int nt = 0; nt < 16; nt++) {
        const int col = cb + nt * 8;
        __half h0, lo0, h1, lo1;
        splith(oacc[nt][0] * inv0, h0, lo0);
        splith(oacc[nt][1] * inv0, h1, lo1);
        *(uint32_t*)(CtxH + row0 * HID + col) = pk2h(h0, h1);
        *(uint32_t*)(CtxL + row0 * HID + col) = pk2h(lo0, lo1);
        splith(oacc[nt][2] * inv1, h0, lo0);
        splith(oacc[nt][3] * inv1, h1, lo1);
        *(uint32_t*)(CtxH + row1 * HID + col) = pk2h(h0, h1);
        *(uint32_t*)(CtxL + row1 * HID + col) = pk2h(lo0, lo1);
    }
}

// ---------------------------------------------------------------------------
extern "C" void kernel_launch(void* const* d_in, const int* in_sizes, int n_in,
                              void* d_out, int out_size)
{
    const float* X  = (const float*)d_in[0];
    const float* Wq = (const float*)d_in[1];
    const float* bq = (const float*)d_in[2];
    const float* Wk = (const float*)d_in[3];
    const float* bk = (const float*)d_in[4];
    const float* Wv = (const float*)d_in[5];
    const float* bv = (const float*)d_in[6];
    const float* Wo = (const float*)d_in[7];
    const float* bo = (const float*)d_in[8];
    float* out = (float*)d_out;

    __nv_bfloat16 *xh, *xl, *wqh, *wql, *wkh, *wkl, *wvh, *wvl, *woh, *wol;
    __nv_bfloat16 *qh, *ql, *kh, *kl, *vh, *vl, *cxh, *cxl;
    float *stab, *ctab;
    cudaGetSymbolAddress((void**)&xh,  g_xh);
    cudaGetSymbolAddress((void**)&xl,  g_xl);
    cudaGetSymbolAddress((void**)&wqh, g_wqh);
    cudaGetSymbolAddress((void**)&wql, g_wql);
    cudaGetSymbolAddress((void**)&wkh, g_wkh);
    cudaGetSymbolAddress((void**)&wkl, g_wkl);
    cudaGetSymbolAddress((void**)&wvh, g_wvh);
    cudaGetSymbolAddress((void**)&wvl, g_wvl);
    cudaGetSymbolAddress((void**)&woh, g_woh);
    cudaGetSymbolAddress((void**)&wol, g_wol);
    cudaGetSymbolAddress((void**)&qh,  g_qh);
    cudaGetSymbolAddress((void**)&ql,  g_ql);
    cudaGetSymbolAddress((void**)&kh,  g_kh);
    cudaGetSymbolAddress((void**)&kl,  g_kl);
    cudaGetSymbolAddress((void**)&vh,  g_vh);
    cudaGetSymbolAddress((void**)&vl,  g_vl);
    cudaGetSymbolAddress((void**)&cxh, g_cxh);
    cudaGetSymbolAddress((void**)&cxl, g_cxl);
    cudaGetSymbolAddress((void**)&stab, g_sin);
    cudaGetSymbolAddress((void**)&ctab, g_cos);

    cudaFuncSetAttribute(mma_gemm_qkv_kernel,
                         cudaFuncAttributeMaxDynamicSharedMemorySize, GSMEMQ);
    cudaFuncSetAttribute(mma_gemm_out_kernel,
                         cudaFuncAttributeMaxDynamicSharedMemorySize, GSMEM4);
    cudaFuncSetAttribute(flash2_kernel,
                         cudaFuncAttributeMaxDynamicSharedMemorySize, FL2_SMEM);

    // launch 0: RoPE table + X split fp16 (fused)
    prep0_kernel<<<512 + (int)(((size_t)M_ROWS * HID / 4) / 256), 256>>>(
        stab, ctab, (const float4*)X, (uint2*)xh, (uint2*)xl);

    // launch 1: transpose + split all 4 weights (fp16 hi/lo)
    {
        dim3 g(HID / 32, HID / 32, 4), blk(32, 8);
        wtrans4_kernel<<<g, blk>>>(Wq, wqh, wql, Wk, wkh, wkl,
                                   Wv, wvh, wvl, Wo, woh, wol);
    }

    // launch 2: dummy (keeps ncu capture idx 3 = qkv GEMM)
    dummy_kernel<<<1, 32>>>();

    // launch 3: QKV projections (fp16 2-product) + bias + RoPE
    {
        dim3 grid(HID / 128, M_ROWS / 128, 3);
        mma_gemm_qkv_kernel<<<grid, 256, GSMEMQ>>>(
            xh, xl, wqh, wkh, wvh, bq, bk, bv,
            qh, ql, kh, kl, vh, vl, stab, ctab);
    }

    // launch 4: flash attention (fp16) -> fp16 hi/lo context
    {
        dim3 grid(SEQ / BR, BATCH * NH);
        flash2_kernel<<<grid, 256, FL2_SMEM>>>(qh, ql, kh, kl, vh, vl, cxh, cxl);
    }

    // launch 5: output projection (fp16 3-product) + bias -> out
    {
        dim3 grid(HID / 128, M_ROWS / 128);
        mma_gemm_out_kernel<<<grid, 256, GSMEM4>>>(cxh, cxl, woh, wol, bo, out);
    }
}

// round 14
// speedup vs baseline: 1.8039x; 1.1791x over previous
#include <cuda_runtime.h>
#include <cuda_bf16.h>
#include <cuda_fp16.h>
#include <cstdint>
#include <math.h>

#define HID 2048
#define SEQ 2048
#define NH  16
#define HD  128
#define BATCH 2
#define M_ROWS (BATCH*SEQ)   // 4096

// ---------------------------------------------------------------------------
// Scratch (__device__ globals; no allocation allowed).
// All split buffers hold PACKED FP16 bits (bf16-typed bit containers).
// ---------------------------------------------------------------------------
__device__ __nv_bfloat16 g_xh[(size_t)M_ROWS * HID];
__device__ __nv_bfloat16 g_xl[(size_t)M_ROWS * HID];
__device__ __nv_bfloat16 g_wqh[(size_t)HID * HID];
__device__ __nv_bfloat16 g_wkh[(size_t)HID * HID];
__device__ __nv_bfloat16 g_wvh[(size_t)HID * HID];
__device__ __nv_bfloat16 g_woh[(size_t)HID * HID];
__device__ __nv_bfloat16 g_qh[(size_t)M_ROWS * HID];
__device__ __nv_bfloat16 g_ql[(size_t)M_ROWS * HID];
__device__ __nv_bfloat16 g_kh[(size_t)M_ROWS * HID];
__device__ __nv_bfloat16 g_vh[(size_t)M_ROWS * HID];
__device__ __nv_bfloat16 g_vl[(size_t)M_ROWS * HID];
__device__ __nv_bfloat16 g_cxh[(size_t)M_ROWS * HID];
__device__ __nv_bfloat16 g_cxl[(size_t)M_ROWS * HID];
__device__ float g_sin[SEQ * (HD/2)];
__device__ float g_cos[SEQ * (HD/2)];

// ---------------------------------------------------------------------------
// helpers
// ---------------------------------------------------------------------------
__device__ __forceinline__ uint32_t smem_to_u32(const void* p) {
    uint32_t a;
    asm("{ .reg .u64 t; cvta.to.shared.u64 t, %1; cvt.u32.u64 %0, t; }"
        : "=r"(a) : "l"(p));
    return a;
}

__device__ __forceinline__ void cp16(uint32_t dst, const void* src) {
    asm volatile("cp.async.cg.shared.global [%0], [%1], 16;"
                 :: "r"(dst), "l"(src) : "memory");
}

__device__ __forceinline__ void ldsm_x4(uint32_t* r, uint32_t addr) {
    asm volatile("ldmatrix.sync.aligned.m8n8.x4.shared.b16 {%0,%1,%2,%3}, [%4];"
                 : "=r"(r[0]), "=r"(r[1]), "=r"(r[2]), "=r"(r[3]) : "r"(addr));
}

__device__ __forceinline__ void ldsm_x4_t(uint32_t* r, uint32_t addr) {
    asm volatile("ldmatrix.sync.aligned.m8n8.x4.trans.shared.b16 {%0,%1,%2,%3}, [%4];"
                 : "=r"(r[0]), "=r"(r[1]), "=r"(r[2]), "=r"(r[3]) : "r"(addr));
}

__device__ __forceinline__ void mma_f16(float* c, const uint32_t* a,
                                        uint32_t b0, uint32_t b1) {
    asm volatile(
        "mma.sync.aligned.m16n8k16.row.col.f32.f16.f16.f32 "
        "{%0,%1,%2,%3}, {%4,%5,%6,%7}, {%8,%9}, {%0,%1,%2,%3};"
        : "+f"(c[0]), "+f"(c[1]), "+f"(c[2]), "+f"(c[3])
        : "r"(a[0]), "r"(a[1]), "r"(a[2]), "r"(a[3]), "r"(b0), "r"(b1));
}

// fp16 split + pack
__device__ __forceinline__ void splith(float v, __half& h, __half& l) {
    h = __float2half_rn(v);
    l = __float2half_rn(v - __half2float(h));
}
__device__ __forceinline__ uint32_t pk2h(__half a, __half b) {
    __half2 t = __halves2half2(a, b);
    return *reinterpret_cast<uint32_t*>(&t);
}
__device__ __forceinline__ uint32_t pk2hf(float a, float b) {
    __half2 t = __floats2half2_rn(a, b);
    return *reinterpret_cast<uint32_t*>(&t);
}

// fast 2^t on the FMA pipe. t <= 0 expected; clamped at -30.
__device__ __forceinline__ float fexp2(float t) {
    t = fmaxf(t, -30.0f);
    const float fi = t + 12582912.0f;          // 1.5*2^23 round-to-int
    const float r  = fi - 12582912.0f;
    const float f  = t - r;
    float p = 1.3333558146e-3f;
    p = fmaf(p, f, 9.6181291076e-3f);
    p = fmaf(p, f, 5.5504108665e-2f);
    p = fmaf(p, f, 2.4022650696e-1f);
    p = fmaf(p, f, 6.9314718056e-1f);
    p = fmaf(p, f, 1.0f);
    const int e = __float_as_int(fi) - 0x4B400000;
    return __int_as_float(__float_as_int(p) + (e << 23));
}

// ---------------------------------------------------------------------------
// Prep kernel 0: RoPE table (blocks 0..511) + X split fp16 (blocks 512..)
// ---------------------------------------------------------------------------
__global__ void __launch_bounds__(256) prep0_kernel(
    float* __restrict__ st, float* __restrict__ ct,
    const float4* __restrict__ X, uint2* __restrict__ H, uint2* __restrict__ L)
{
    const int bid = blockIdx.x;
    if (bid < 512) {
        int idx = bid * 256 + threadIdx.x;   // SEQ*64 total
        int s = idx >> 6, j = idx & 63;
        double f = exp(-0.14391156831212787 * (double)j);  // 10000^(-2j/128)
        double sn, cs;
        sincos((double)s * f, &sn, &cs);
        st[idx] = (float)sn;
        ct[idx] = (float)cs;
    } else {
        size_t i = (size_t)(bid - 512) * 256 + threadIdx.x;
        float4 v = X[i];
        __half h0, l0, h1, l1, h2, l2, h3, l3;
        splith(v.x, h0, l0); splith(v.y, h1, l1);
        splith(v.z, h2, l2); splith(v.w, h3, l3);
        H[i] = make_uint2(pk2h(h0, h1), pk2h(h2, h3));
        L[i] = make_uint2(pk2h(l0, l1), pk2h(l2, l3));
    }
}

// Prep kernel 1: all four W [K][N] fp32 -> Wt [N][K] fp16 (hi only).
__global__ void __launch_bounds__(256) wtrans4_kernel(
    const float* __restrict__ W0, __nv_bfloat16* Th0,
    const float* __restrict__ W1, __nv_bfloat16* Th1,
    const float* __restrict__ W2, __nv_bfloat16* Th2,
    const float* __restrict__ W3, __nv_bfloat16* Th3)
{
    const float* W;
    __nv_bfloat16* Th;
    switch (blockIdx.z) {
        case 0:  W = W0; Th = Th0; break;
        case 1:  W = W1; Th = Th1; break;
        case 2:  W = W2; Th = Th2; break;
        default: W = W3; Th = Th3; break;
    }
    __shared__ float t[32][33];
    const int n0 = blockIdx.x * 32, k0 = blockIdx.y * 32;
    const int tx = threadIdx.x, ty = threadIdx.y;   // (32, 8)
#pragma unroll
    for (int i = 0; i < 4; i++)
        t[ty + 8 * i][tx] = W[(size_t)(k0 + ty + 8 * i) * HID + n0 + tx];
    __syncthreads();
#pragma unroll
    for (int i = 0; i < 4; i++) {
        float v = t[tx][ty + 8 * i];
        __half h = __float2half_rn(v);
        const size_t o = (size_t)(n0 + ty + 8 * i) * HID + k0 + tx;
        *(uint16_t*)(Th + o) = *(uint16_t*)&h;
    }
}

// tiny dummy to shift ncu capture index so idx 3 = qkv GEMM
__global__ void dummy_kernel() {}

// ---------------------------------------------------------------------------
// GEMM (fp16 2-product): Y = (Ah+Al) * Bh^T. 256 thr / 8 warps, 2 CTAs/SM.
// BM=128, BN=128, BK=32. Tiles [Ah][Al][Bh], 64B rows + XOR swizzle.
// Stage 24KB, FOUR stages, prefetch depth 3 (wait_group 2).
// mode 0: fp32 out (+bias); mode 1: bias+RoPE scaled, fp16 hi/lo out;
// mode 2: bias only, fp16 hi/lo out; mode 3: bias+RoPE scaled, fp16 HI only.
// ---------------------------------------------------------------------------
#define TQ 8192
#define STGQ (3*TQ)                     // 24576
#define GSMEMQ (4*STGQ)                 // 98304
#define NKCHUNK (HID / 32)              // 64

__device__ __forceinline__ void gemm_2p_body(
    const __nv_bfloat16* __restrict__ Ah, const __nv_bfloat16* __restrict__ Al,
    const __nv_bfloat16* __restrict__ Bh,
    const float* __restrict__ bias,
    __nv_bfloat16* __restrict__ Yh, __nv_bfloat16* __restrict__ Yl,
    float* __restrict__ Yf, float oscale,
    const float* __restrict__ stab, const float* __restrict__ ctab, int mode)
{
    extern __shared__ __align__(128) char smem[];
    const uint32_t sb = smem_to_u32(smem);
    const int tid = threadIdx.x;
    const int wid = tid >> 5, lane = tid & 31;
    const int warp_m = wid & 3, warp_n = wid >> 2;   // 4 x 2 warps
    const int bm = blockIdx.y * 128, bn = blockIdx.x * 128;

    const int r2 = tid >> 1, seg = (tid & 1) * 2;
    const uint32_t xr2 = ((uint32_t)r2 >> 1) & 3;
    const uint32_t pc0 = ((uint32_t)(seg)     ^ xr2) << 4;
    const uint32_t pc1 = ((uint32_t)(seg | 1) ^ xr2) << 4;
    const uint32_t rowo = (uint32_t)r2 * 64;

    const uint32_t arow = (uint32_t)(warp_m * 32 + (lane & 15)) * 64;
    const uint32_t xrA = (((uint32_t)lane & 15) >> 1) & 3;
    const uint32_t hcA = (uint32_t)lane >> 4;
    const uint32_t axc0 = ((0 + hcA) ^ xrA) << 4;
    const uint32_t axc1 = ((2 + hcA) ^ xrA) << 4;
    const uint32_t brow = (uint32_t)(warp_n * 64 + ((lane >> 4) & 1) * 8 +
                                     (lane & 7)) * 64;
    const uint32_t xrB = (((uint32_t)lane & 7) >> 1) & 3;
    const uint32_t hcB = ((uint32_t)lane >> 3) & 1;
    const uint32_t bxc0 = ((0 + hcB) ^ xrB) << 4;
    const uint32_t bxc1 = ((2 + hcB) ^ xrB) << 4;

    float acc[2][8][4];
#pragma unroll
    for (int mt = 0; mt < 2; mt++)
#pragma unroll
        for (int nt = 0; nt < 8; nt++)
#pragma unroll
            for (int e = 0; e < 4; e++) acc[mt][nt][e] = 0.0f;

    auto issue = [&](int c, int stg) {
        const int k0 = c << 5;
        const uint32_t so = sb + stg * STGQ;
        const __nv_bfloat16* ahp = Ah + (size_t)(bm + r2) * HID + k0 + seg * 8;
        const __nv_bfloat16* alp = Al + (size_t)(bm + r2) * HID + k0 + seg * 8;
        const __nv_bfloat16* bhp = Bh + (size_t)(bn + r2) * HID + k0 + seg * 8;
        cp16(so + rowo + pc0,          ahp);
        cp16(so + rowo + pc1,          ahp + 8);
        cp16(so + TQ + rowo + pc0,     alp);
        cp16(so + TQ + rowo + pc1,     alp + 8);
        cp16(so + 2 * TQ + rowo + pc0, bhp);
        cp16(so + 2 * TQ + rowo + pc1, bhp + 8);
    };

#pragma unroll
    for (int s = 0; s < 3; s++) {
        issue(s, s);
        asm volatile("cp.async.commit_group;" ::: "memory");
    }

    for (int c = 0; c < NKCHUNK; c++) {
        asm volatile("cp.async.wait_group 2;" ::: "memory");
        __syncthreads();
        if (c + 3 < NKCHUNK) issue(c + 3, (c + 3) & 3);
        asm volatile("cp.async.commit_group;" ::: "memory");

        const uint32_t so = (c & 3) * STGQ;
        const uint32_t aB = sb + so + arow;
        const uint32_t bB = sb + so + 2 * TQ + brow;
#pragma unroll
        for (int ks = 0; ks < 2; ks++) {
            const uint32_t axc = ks ? axc1 : axc0;
            const uint32_t bxc = ks ? bxc1 : bxc0;
            uint32_t ah[2][4], al[2][4];
#pragma unroll
            for (int mt = 0; mt < 2; mt++) {
                ldsm_x4(ah[mt], aB + mt * 1024 + axc);
                ldsm_x4(al[mt], aB + TQ + mt * 1024 + axc);
            }
#pragma unroll
            for (int ng = 0; ng < 4; ng++) {
                uint32_t bh4[4];
                ldsm_x4(bh4, bB + ng * 1024 + bxc);
#pragma unroll
                for (int mt = 0; mt < 2; mt++) {
                    mma_f16(acc[mt][2 * ng],     ah[mt], bh4[0], bh4[1]);
                    mma_f16(acc[mt][2 * ng],     al[mt], bh4[0], bh4[1]);
                    mma_f16(acc[mt][2 * ng + 1], ah[mt], bh4[2], bh4[3]);
                    mma_f16(acc[mt][2 * ng + 1], al[mt], bh4[2], bh4[3]);
                }
            }
        }
    }

    const int r0 = bm + warp_m * 32 + (lane >> 2);
    const int c0 = bn + warp_n * 64 + (lane & 3) * 2;
#pragma unroll
    for (int mt = 0; mt < 2; mt++) {
#pragma unroll
        for (int half = 0; half < 2; half++) {
            const int row = r0 + mt * 16 + half * 8;
            const int s = row & (SEQ - 1);
#pragma unroll
            for (int nt = 0; nt < 8; nt++) {
                const int col = c0 + nt * 8;
                float e  = acc[mt][nt][half * 2 + 0] + bias[col];
                float od = acc[mt][nt][half * 2 + 1] + bias[col + 1];
                if (mode == 1 || mode == 3) {
                    const int j = (col & (HD - 1)) >> 1;
                    const float sn = stab[(s << 6) + j];
                    const float cs = ctab[(s << 6) + j];
                    float re = e * cs - od * sn;
                    float ro = od * cs + e * sn;
                    e = re * oscale;
                    od = ro * oscale;
                }
                if (mode == 0) {
                    float2 r;
                    r.x = e; r.y = od;
                    *(float2*)(Yf + (size_t)row * HID + col) = r;
                } else if (mode == 3) {
                    // hi-only fp16 output (K projection)
                    *(uint32_t*)(Yh + (size_t)row * HID + col) = pk2hf(e, od);
                } else {
                    __half h0, l0, h1, l1;
                    splith(e, h0, l0);
                    splith(od, h1, l1);
                    *(uint32_t*)(Yh + (size_t)row * HID + col) = pk2h(h0, h1);
                    *(uint32_t*)(Yl + (size_t)row * HID + col) = pk2h(l0, l1);
                }
            }
        }
    }
}

// Q scale folds softmax 1/sqrt(128) AND log2(e) (base-2 softmax)
#define QSCALE (0.08838834764831843f * 1.4426950408889634f)

__global__ void __launch_bounds__(256, 2) mma_gemm_qkv_kernel(
    const __nv_bfloat16* xh, const __nv_bfloat16* xl,
    const __nv_bfloat16* wqh, const __nv_bfloat16* wkh,
    const __nv_bfloat16* wvh,
    const float* bq, const float* bk, const float* bv,
    __nv_bfloat16* qh, __nv_bfloat16* ql,
    __nv_bfloat16* kh, __nv_bfloat16* vh, __nv_bfloat16* vl,
    const float* stab, const float* ctab)
{
    if (blockIdx.z == 0)
        gemm_2p_body(xh, xl, wqh, bq, qh, ql, nullptr, QSCALE, stab, ctab, 1);
    else if (blockIdx.z == 1)
        gemm_2p_body(xh, xl, wkh, bk, kh, nullptr, nullptr, 1.0f, stab, ctab, 3);
    else
        gemm_2p_body(xh, xl, wvh, bv, vh, vl, nullptr, 1.0f, nullptr, nullptr, 2);
}

__global__ void __launch_bounds__(256, 2) mma_gemm_out_kernel(
    const __nv_bfloat16* ah, const __nv_bfloat16* al,
    const __nv_bfloat16* wh, const float* bo, float* Y)
{
    gemm_2p_body(ah, al, wh, bo, nullptr, nullptr, Y, 1.0f, nullptr, nullptr, 0);
}

// ---------------------------------------------------------------------------
// Flash attention v5: fp16 tensor-core.
// S = 2-product (qh+ql)*kh (K-lo dropped; averaged error ~5e-5).
// PV = 2-product ph*(vh+vl). Base-2 softmax, FMA-pipe exp.
// KV stage = [Kh][Vh][Vl] (52KB); Q keeps hi+lo.
// ---------------------------------------------------------------------------
#define BR 128
#define BC 64
#define RQ 136
#define RB (RQ*2)
#define QBYTES (BR*RB)          // 34816
#define QTOT (2*QBYTES)         // 69632
#define KVT 17408               // one 64-row tile
#define KVSTG (3*KVT)           // 52224 : [Kh][Vh][Vl]
#define FL2_SMEM (QTOT + 2*KVSTG)   // 174080
#define NKT (SEQ/BC)            // 32

__global__ void __launch_bounds__(256, 1) flash2_kernel(
    const __nv_bfloat16* __restrict__ Qh, const __nv_bfloat16* __restrict__ Ql,
    const __nv_bfloat16* __restrict__ Kh,
    const __nv_bfloat16* __restrict__ Vh, const __nv_bfloat16* __restrict__ Vl,
    __nv_bfloat16* __restrict__ CtxH, __nv_bfloat16* __restrict__ CtxL)
{
    extern __shared__ __align__(128) char smem[];
    const uint32_t sb = smem_to_u32(smem);
    const int tid = threadIdx.x;
    const int wid = tid >> 5, lane = tid & 31;
    const int bh = blockIdx.y;
    const int b = bh >> 4, h = bh & 15;
    const int q0 = blockIdx.x * BR;
    const size_t rowbase = (size_t)b * SEQ;
    const int coff = h * HD;

    {
        const int row = tid >> 1;
        const int ch0 = (tid & 1) * 8;
        const size_t gq = (rowbase + q0 + row) * HID + coff;
        const __nv_bfloat16* sh = Qh + gq;
        const __nv_bfloat16* sl = Ql + gq;
#pragma unroll
        for (int c = 0; c < 8; c++) {
            const int ch = ch0 + c;
            cp16(sb + row * RB + ch * 16, sh + ch * 8);
            cp16(sb + QBYTES + row * RB + ch * 16, sl + ch * 8);
        }
    }

    auto issue_kv = [&](int kt, int stg) {
        const int row = tid >> 2;
        const int cq = tid & 3;
        const size_t g = (rowbase + (size_t)kt * BC + row) * HID + coff;
        const uint32_t base = sb + QTOT + stg * KVSTG + row * RB;
#pragma unroll
        for (int c = 0; c < 4; c++) {
            const int ch = cq + c * 4;
            cp16(base + ch * 16,           Kh + g + ch * 8);
            cp16(base + KVT + ch * 16,     Vh + g + ch * 8);
            cp16(base + 2 * KVT + ch * 16, Vl + g + ch * 8);
        }
    };

    issue_kv(0, 0);
    asm volatile("cp.async.commit_group;" ::: "memory");

    float m0 = -1e30f, m1 = -1e30f, l0 = 0.0f, l1 = 0.0f;
    float oacc[16][4];
#pragma unroll
    for (int nt = 0; nt < 16; nt++)
#pragma unroll
        for (int e = 0; e < 4; e++) oacc[nt][e] = 0.0f;

    const uint32_t qBh = sb + (wid * 16 + (lane & 15)) * RB + ((lane >> 4) * 8) * 2;
    const uint32_t qBl = qBh + QBYTES;
    const uint32_t kRel = (((lane >> 4) & 1) * 8 + (lane & 7)) * RB +
                          (((lane >> 3) & 1) * 8) * 2;
    const uint32_t vRel = (lane & 15) * RB + ((lane >> 4) * 8) * 2;

    for (int kt = 0; kt < NKT; kt++) {
        asm volatile("cp.async.wait_group 0;" ::: "memory");
        __syncthreads();
        if (kt + 1 < NKT) {
            issue_kv(kt + 1, (kt + 1) & 1);
            asm volatile("cp.async.commit_group;" ::: "memory");
        }

        const uint32_t kb = sb + QTOT + (kt & 1) * KVSTG;

        // ---- S = (Qh+Ql) Kh^T (fp16, 2 products); log2-domain scores ----
        float sacc[8][4];
#pragma unroll
        for (int nt = 0; nt < 8; nt++)
#pragma unroll
            for (int e = 0; e < 4; e++) sacc[nt][e] = 0.0f;

#pragma unroll
        for (int ks = 0; ks < 8; ks++) {
            uint32_t qa[4], ql4[4];
            ldsm_x4(qa, qBh + ks * 32);
            ldsm_x4(ql4, qBl + ks * 32);
#pragma unroll
            for (int ng = 0; ng < 4; ng++) {
                uint32_t bh4[4];
                const uint32_t ka = kb + kRel + ng * (16 * RB) + ks * 32;
                ldsm_x4(bh4, ka);
                mma_f16(sacc[2 * ng],     qa,  bh4[0], bh4[1]);
                mma_f16(sacc[2 * ng],     ql4, bh4[0], bh4[1]);
                mma_f16(sacc[2 * ng + 1], qa,  bh4[2], bh4[3]);
                mma_f16(sacc[2 * ng + 1], ql4, bh4[2], bh4[3]);
            }
        }

        // ---- row max + rescale ----
        float mx0 = -1e30f, mx1 = -1e30f;
#pragma unroll
        for (int nt = 0; nt < 8; nt++) {
            mx0 = fmaxf(mx0, fmaxf(sacc[nt][0], sacc[nt][1]));
            mx1 = fmaxf(mx1, fmaxf(sacc[nt][2], sacc[nt][3]));
        }
        mx0 = fmaxf(mx0, __shfl_xor_sync(0xffffffffu, mx0, 1));
        mx0 = fmaxf(mx0, __shfl_xor_sync(0xffffffffu, mx0, 2));
        mx1 = fmaxf(mx1, __shfl_xor_sync(0xffffffffu, mx1, 1));
        mx1 = fmaxf(mx1, __shfl_xor_sync(0xffffffffu, mx1, 2));

        const float mn0 = fmaxf(m0, mx0);
        const float mn1 = fmaxf(m1, mx1);
        const float corr0 = fexp2(m0 - mn0);
        const float corr1 = fexp2(m1 - mn1);
        m0 = mn0;
        m1 = mn1;
#pragma unroll
        for (int nt = 0; nt < 16; nt++) {
            oacc[nt][0] *= corr0;
            oacc[nt][1] *= corr0;
            oacc[nt][2] *= corr1;
            oacc[nt][3] *= corr1;
        }

        // ---- PV (fp16, 2 products: ph*vh + ph*vl); exp interleaved ----
        const uint32_t vb = kb + KVT;
        float rs0 = 0.0f, rs1 = 0.0f;
#pragma unroll
        for (int ks2 = 0; ks2 < 4; ks2++) {
            uint32_t ah[4];
#pragma unroll
            for (int j = 0; j < 2; j++) {
                const int nt = 2 * ks2 + j;
                float p00 = fexp2(sacc[nt][0] - mn0);
                float p01 = fexp2(sacc[nt][1] - mn0);
                float p10 = fexp2(sacc[nt][2] - mn1);
                float p11 = fexp2(sacc[nt][3] - mn1);
                rs0 += p00 + p01;
                rs1 += p10 + p11;
                ah[2 * j]     = pk2hf(p00, p01);
                ah[2 * j + 1] = pk2hf(p10, p11);
            }
#pragma unroll
            for (int ng = 0; ng < 8; ng++) {
                uint32_t vh4[4], vl4[4];
                const uint32_t va = vb + vRel + ks2 * (16 * RB) + ng * 32;
                ldsm_x4_t(vh4, va);
                ldsm_x4_t(vl4, va + KVT);
                mma_f16(oacc[2 * ng],     ah, vh4[0], vh4[1]);
                mma_f16(oacc[2 * ng],     ah, vl4[0], vl4[1]);
                mma_f16(oacc[2 * ng + 1], ah, vh4[2], vh4[3]);
                mma_f16(oacc[2 * ng + 1], ah, vl4[2], vl4[3]);
            }
        }

        rs0 += __shfl_xor_sync(0xffffffffu, rs0, 1);
        rs0 += __shfl_xor_sync(0xffffffffu, rs0, 2);
        rs1 += __shfl_xor_sync(0xffffffffu, rs1, 1);
        rs1 += __shfl_xor_sync(0xffffffffu, rs1, 2);
        l0 = l0 * corr0 + rs0;
        l1 = l1 * corr1 + rs1;
    }

    const float inv0 = 1.0f / l0;
    const float inv1 = 1.0f / l1;
    const size_t row0 = rowbase + q0 + wid * 16 + (lane >> 2);
    const size_t row1 = row0 + 8;
    const int cb = coff + (lane & 3) * 2;
#pragma unroll
    for (int nt = 0; nt < 16; nt++) {
        const int col = cb + nt * 8;
        __half h0, lo0, h1, lo1;
        splith(oacc[nt][0] * inv0, h0, lo0);
        splith(oacc[nt][1] * inv0, h1, lo1);
        *(uint32_t*)(CtxH + row0 * HID + col) = pk2h(h0, h1);
        *(uint32_t*)(CtxL + row0 * HID + col) = pk2h(lo0, lo1);
        splith(oacc[nt][2] * inv1, h0, lo0);
        splith(oacc[nt][3] * inv1, h1, lo1);
        *(uint32_t*)(CtxH + row1 * HID + col) = pk2h(h0, h1);
        *(uint32_t*)(CtxL + row1 * HID + col) = pk2h(lo0, lo1);
    }
}

// ---------------------------------------------------------------------------
extern "C" void kernel_launch(void* const* d_in, const int* in_sizes, int n_in,
                              void* d_out, int out_size)
{
    const float* X  = (const float*)d_in[0];
    const float* Wq = (const float*)d_in[1];
    const float* bq = (const float*)d_in[2];
    const float* Wk = (const float*)d_in[3];
    const float* bk = (const float*)d_in[4];
    const float* Wv = (const float*)d_in[5];
    const float* bv = (const float*)d_in[6];
    const float* Wo = (const float*)d_in[7];
    const float* bo = (const float*)d_in[8];
    float* out = (float*)d_out;

    __nv_bfloat16 *xh, *xl, *wqh, *wkh, *wvh, *woh;
    __nv_bfloat16 *qh, *ql, *kh, *vh, *vl, *cxh, *cxl;
    float *stab, *ctab;
    cudaGetSymbolAddress((void**)&xh,  g_xh);
    cudaGetSymbolAddress((void**)&xl,  g_xl);
    cudaGetSymbolAddress((void**)&wqh, g_wqh);
    cudaGetSymbolAddress((void**)&wkh, g_wkh);
    cudaGetSymbolAddress((void**)&wvh, g_wvh);
    cudaGetSymbolAddress((void**)&woh, g_woh);
    cudaGetSymbolAddress((void**)&qh,  g_qh);
    cudaGetSymbolAddress((void**)&ql,  g_ql);
    cudaGetSymbolAddress((void**)&kh,  g_kh);
    cudaGetSymbolAddress((void**)&vh,  g_vh);
    cudaGetSymbolAddress((void**)&vl,  g_vl);
    cudaGetSymbolAddress((void**)&cxh, g_cxh);
    cudaGetSymbolAddress((void**)&cxl, g_cxl);
    cudaGetSymbolAddress((void**)&stab, g_sin);
    cudaGetSymbolAddress((void**)&ctab, g_cos);

    cudaFuncSetAttribute(mma_gemm_qkv_kernel,
                         cudaFuncAttributeMaxDynamicSharedMemorySize, GSMEMQ);
    cudaFuncSetAttribute(mma_gemm_out_kernel,
                         cudaFuncAttributeMaxDynamicSharedMemorySize, GSMEMQ);
    cudaFuncSetAttribute(flash2_kernel,
                         cudaFuncAttributeMaxDynamicSharedMemorySize, FL2_SMEM);

    // launch 0: RoPE table + X split fp16 (fused)
    prep0_kernel<<<512 + (int)(((size_t)M_ROWS * HID / 4) / 256), 256>>>(
        stab, ctab, (const float4*)X, (uint2*)xh, (uint2*)xl);

    // launch 1: transpose all 4 weights -> fp16 (hi only)
    {
        dim3 g(HID / 32, HID / 32, 4), blk(32, 8);
        wtrans4_kernel<<<g, blk>>>(Wq, wqh, Wk, wkh, Wv, wvh, Wo, woh);
    }

    // launch 2: dummy (keeps ncu capture idx 3 = qkv GEMM)
    dummy_kernel<<<1, 32>>>();

    // launch 3: QKV projections (fp16 2-product) + bias + RoPE
    {
        dim3 grid(HID / 128, M_ROWS / 128, 3);
        mma_gemm_qkv_kernel<<<grid, 256, GSMEMQ>>>(
            xh, xl, wqh, wkh, wvh, bq, bk, bv,
            qh, ql, kh, vh, vl, stab, ctab);
    }

    // launch 4: flash attention (fp16, 2-product S and PV)
    {
        dim3 grid(SEQ / BR, BATCH * NH);
        flash2_kernel<<<grid, 256, FL2_SMEM>>>(qh, ql, kh, vh, vl, cxh, cxl);
    }

    // launch 5: output projection (fp16 2-product) + bias -> out
    {
        dim3 grid(HID / 128, M_ROWS / 128);
        mma_gemm_out_kernel<<<grid, 256, GSMEMQ>>>(cxh, cxl, woh, bo, out);
    }
}

// round 16
// speedup vs baseline: 1.8606x; 1.0314x over previous
#include <cuda_runtime.h>
#include <cuda_bf16.h>
#include <cuda_fp16.h>
#include <cstdint>
#include <math.h>

#define HID 2048
#define SEQ 2048
#define NH  16
#define HD  128
#define BATCH 2
#define M_ROWS (BATCH*SEQ)   // 4096

// ---------------------------------------------------------------------------
// Scratch (__device__ globals). All split buffers hold PACKED FP16 bits.
// ---------------------------------------------------------------------------
__device__ __nv_bfloat16 g_xh[(size_t)M_ROWS * HID];
__device__ __nv_bfloat16 g_xl[(size_t)M_ROWS * HID];
__device__ __nv_bfloat16 g_wqh[(size_t)HID * HID];
__device__ __nv_bfloat16 g_wkh[(size_t)HID * HID];
__device__ __nv_bfloat16 g_wvh[(size_t)HID * HID];
__device__ __nv_bfloat16 g_woh[(size_t)HID * HID];
__device__ __nv_bfloat16 g_qh[(size_t)M_ROWS * HID];
__device__ __nv_bfloat16 g_ql[(size_t)M_ROWS * HID];
__device__ __nv_bfloat16 g_kh[(size_t)M_ROWS * HID];
__device__ __nv_bfloat16 g_vh[(size_t)M_ROWS * HID];
__device__ __nv_bfloat16 g_cxh[(size_t)M_ROWS * HID];
__device__ __nv_bfloat16 g_cxl[(size_t)M_ROWS * HID];
__device__ float g_sin[SEQ * (HD/2)];
__device__ float g_cos[SEQ * (HD/2)];

// ---------------------------------------------------------------------------
// helpers
// ---------------------------------------------------------------------------
__device__ __forceinline__ uint32_t smem_to_u32(const void* p) {
    uint32_t a;
    asm("{ .reg .u64 t; cvta.to.shared.u64 t, %1; cvt.u32.u64 %0, t; }"
        : "=r"(a) : "l"(p));
    return a;
}

__device__ __forceinline__ void cp16(uint32_t dst, const void* src) {
    asm volatile("cp.async.cg.shared.global [%0], [%1], 16;"
                 :: "r"(dst), "l"(src) : "memory");
}

__device__ __forceinline__ void ldsm_x4(uint32_t* r, uint32_t addr) {
    asm volatile("ldmatrix.sync.aligned.m8n8.x4.shared.b16 {%0,%1,%2,%3}, [%4];"
                 : "=r"(r[0]), "=r"(r[1]), "=r"(r[2]), "=r"(r[3]) : "r"(addr));
}

__device__ __forceinline__ void ldsm_x4_t(uint32_t* r, uint32_t addr) {
    asm volatile("ldmatrix.sync.aligned.m8n8.x4.trans.shared.b16 {%0,%1,%2,%3}, [%4];"
                 : "=r"(r[0]), "=r"(r[1]), "=r"(r[2]), "=r"(r[3]) : "r"(addr));
}

__device__ __forceinline__ void mma_f16(float* c, const uint32_t* a,
                                        uint32_t b0, uint32_t b1) {
    asm volatile(
        "mma.sync.aligned.m16n8k16.row.col.f32.f16.f16.f32 "
        "{%0,%1,%2,%3}, {%4,%5,%6,%7}, {%8,%9}, {%0,%1,%2,%3};"
        : "+f"(c[0]), "+f"(c[1]), "+f"(c[2]), "+f"(c[3])
        : "r"(a[0]), "r"(a[1]), "r"(a[2]), "r"(a[3]), "r"(b0), "r"(b1));
}

// fp16 split + pack
__device__ __forceinline__ void splith(float v, __half& h, __half& l) {
    h = __float2half_rn(v);
    l = __float2half_rn(v - __half2float(h));
}
__device__ __forceinline__ uint32_t pk2h(__half a, __half b) {
    __half2 t = __halves2half2(a, b);
    return *reinterpret_cast<uint32_t*>(&t);
}
__device__ __forceinline__ uint32_t pk2hf(float a, float b) {
    __half2 t = __floats2half2_rn(a, b);
    return *reinterpret_cast<uint32_t*>(&t);
}

// fast 2^t on the FMA pipe. t <= 0 expected; clamped at -30.
__device__ __forceinline__ float fexp2(float t) {
    t = fmaxf(t, -30.0f);
    const float fi = t + 12582912.0f;          // 1.5*2^23 round-to-int
    const float r  = fi - 12582912.0f;
    const float f  = t - r;
    float p = 1.3333558146e-3f;
    p = fmaf(p, f, 9.6181291076e-3f);
    p = fmaf(p, f, 5.5504108665e-2f);
    p = fmaf(p, f, 2.4022650696e-1f);
    p = fmaf(p, f, 6.9314718056e-1f);
    p = fmaf(p, f, 1.0f);
    const int e = __float_as_int(fi) - 0x4B400000;
    return __int_as_float(__float_as_int(p) + (e << 23));
}

// ---------------------------------------------------------------------------
// Prep kernel 0: RoPE table (blocks 0..511) + X split fp16 (blocks 512..)
// ---------------------------------------------------------------------------
__global__ void __launch_bounds__(256) prep0_kernel(
    float* __restrict__ st, float* __restrict__ ct,
    const float4* __restrict__ X, uint2* __restrict__ H, uint2* __restrict__ L)
{
    const int bid = blockIdx.x;
    if (bid < 512) {
        int idx = bid * 256 + threadIdx.x;   // SEQ*64 total
        int s = idx >> 6, j = idx & 63;
        double f = exp(-0.14391156831212787 * (double)j);  // 10000^(-2j/128)
        double sn, cs;
        sincos((double)s * f, &sn, &cs);
        st[idx] = (float)sn;
        ct[idx] = (float)cs;
    } else {
        size_t i = (size_t)(bid - 512) * 256 + threadIdx.x;
        float4 v = X[i];
        __half h0, l0, h1, l1, h2, l2, h3, l3;
        splith(v.x, h0, l0); splith(v.y, h1, l1);
        splith(v.z, h2, l2); splith(v.w, h3, l3);
        H[i] = make_uint2(pk2h(h0, h1), pk2h(h2, h3));
        L[i] = make_uint2(pk2h(l0, l1), pk2h(l2, l3));
    }
}

// Prep kernel 1: all four W [K][N] fp32 -> Wt [N][K] fp16 (hi only).
__global__ void __launch_bounds__(256) wtrans4_kernel(
    const float* __restrict__ W0, __nv_bfloat16* Th0,
    const float* __restrict__ W1, __nv_bfloat16* Th1,
    const float* __restrict__ W2, __nv_bfloat16* Th2,
    const float* __restrict__ W3, __nv_bfloat16* Th3)
{
    const float* W;
    __nv_bfloat16* Th;
    switch (blockIdx.z) {
        case 0:  W = W0; Th = Th0; break;
        case 1:  W = W1; Th = Th1; break;
        case 2:  W = W2; Th = Th2; break;
        default: W = W3; Th = Th3; break;
    }
    __shared__ float t[32][33];
    const int n0 = blockIdx.x * 32, k0 = blockIdx.y * 32;
    const int tx = threadIdx.x, ty = threadIdx.y;   // (32, 8)
#pragma unroll
    for (int i = 0; i < 4; i++)
        t[ty + 8 * i][tx] = W[(size_t)(k0 + ty + 8 * i) * HID + n0 + tx];
    __syncthreads();
#pragma unroll
    for (int i = 0; i < 4; i++) {
        float v = t[tx][ty + 8 * i];
        __half h = __float2half_rn(v);
        const size_t o = (size_t)(n0 + ty + 8 * i) * HID + k0 + tx;
        *(uint16_t*)(Th + o) = *(uint16_t*)&h;
    }
}

// tiny dummy to shift ncu capture index so idx 3 = qkv GEMM
__global__ void dummy_kernel() {}

// ---------------------------------------------------------------------------
// GEMM (fp16 2-product): Y = (Ah+Al) * Bh^T. 256 thr / 8 warps, 2 CTAs/SM.
// BM=128, BN=128, BK=64 (128B rows, XOR swizzle phys_chunk = chunk ^ (row&7)).
// Stage = 48KB, TWO stages (96KB/CTA).
// modes: 0 fp32(+bias); 1 rope+hi/lo; 2 bias+hi/lo; 3 rope+hi; 4 bias+hi.
// ---------------------------------------------------------------------------
#define TG 16384                        // one tile: 128 rows x 128B
#define STGG (3*TG)                     // 49152: [Ah][Al][Bh]
#define GSMEMG (2*STGG)                 // 98304
#define NKC (HID / 64)                  // 32

__device__ __forceinline__ void gemm_2p_body(
    const __nv_bfloat16* __restrict__ Ah, const __nv_bfloat16* __restrict__ Al,
    const __nv_bfloat16* __restrict__ Bh,
    const float* __restrict__ bias,
    __nv_bfloat16* __restrict__ Yh, __nv_bfloat16* __restrict__ Yl,
    float* __restrict__ Yf, float oscale,
    const float* __restrict__ stab, const float* __restrict__ ctab, int mode)
{
    extern __shared__ __align__(128) char smem[];
    const uint32_t sb = smem_to_u32(smem);
    const int tid = threadIdx.x;
    const int wid = tid >> 5, lane = tid & 31;
    const int warp_m = wid & 3, warp_n = wid >> 2;   // 4 x 2 warps
    const int bm = blockIdx.y * 128, bn = blockIdx.x * 128;

    // loader: 2 threads/row, 4 chunks (16B) each; phys = chunk ^ (row&7)
    const int r2 = tid >> 1, cs = (tid & 1) * 4;
    const uint32_t xr = (uint32_t)r2 & 7;
    const uint32_t rowo = (uint32_t)r2 * 128;

    // ldsm lane constants
    const uint32_t arowi = (uint32_t)(warp_m * 32 + (lane & 15));
    const uint32_t axr = arowi & 7;
    const uint32_t arow = arowi * 128;
    const uint32_t hcA = (uint32_t)lane >> 4;
    const uint32_t browi = (uint32_t)(warp_n * 64 + ((lane >> 4) & 1) * 8 +
                                      (lane & 7));
    const uint32_t bxr = browi & 7;
    const uint32_t brow = browi * 128;
    const uint32_t hcB = ((uint32_t)lane >> 3) & 1;

    float acc[2][8][4];
#pragma unroll
    for (int mt = 0; mt < 2; mt++)
#pragma unroll
        for (int nt = 0; nt < 8; nt++)
#pragma unroll
            for (int e = 0; e < 4; e++) acc[mt][nt][e] = 0.0f;

    auto issue = [&](int c, int stg) {
        const int k0 = c << 6;
        const uint32_t so = sb + stg * STGG;
        const __nv_bfloat16* ahp = Ah + (size_t)(bm + r2) * HID + k0 + cs * 8;
        const __nv_bfloat16* alp = Al + (size_t)(bm + r2) * HID + k0 + cs * 8;
        const __nv_bfloat16* bhp = Bh + (size_t)(bn + r2) * HID + k0 + cs * 8;
#pragma unroll
        for (int i = 0; i < 4; i++) {
            const uint32_t pc = (uint32_t)((cs + i) ^ xr) << 4;
            cp16(so + rowo + pc,          ahp + i * 8);
            cp16(so + TG + rowo + pc,     alp + i * 8);
            cp16(so + 2 * TG + rowo + pc, bhp + i * 8);
        }
    };

    issue(0, 0);
    asm volatile("cp.async.commit_group;" ::: "memory");

    for (int c = 0; c < NKC; c++) {
        asm volatile("cp.async.wait_group 0;" ::: "memory");
        __syncthreads();   // publishes stage c&1; reads of (c+1)&1 done at c-1
        if (c + 1 < NKC) {
            issue(c + 1, (c + 1) & 1);
            asm volatile("cp.async.commit_group;" ::: "memory");
        }

        const uint32_t so = (c & 1) * STGG;
        const uint32_t aB = sb + so + arow;
        const uint32_t bB = sb + so + 2 * TG + brow;
#pragma unroll
        for (int ks = 0; ks < 4; ks++) {
            const uint32_t axc = (uint32_t)((2 * ks + hcA) ^ axr) << 4;
            const uint32_t bxc = (uint32_t)((2 * ks + hcB) ^ bxr) << 4;
            uint32_t ah[2][4], al[2][4];
#pragma unroll
            for (int mt = 0; mt < 2; mt++) {
                ldsm_x4(ah[mt], aB + mt * 2048 + axc);     // 16 rows * 128B
                ldsm_x4(al[mt], aB + TG + mt * 2048 + axc);
            }
#pragma unroll
            for (int ng = 0; ng < 4; ng++) {
                uint32_t bh4[4];
                ldsm_x4(bh4, bB + ng * 2048 + bxc);
#pragma unroll
                for (int mt = 0; mt < 2; mt++) {
                    mma_f16(acc[mt][2 * ng],     ah[mt], bh4[0], bh4[1]);
                    mma_f16(acc[mt][2 * ng],     al[mt], bh4[0], bh4[1]);
                    mma_f16(acc[mt][2 * ng + 1], ah[mt], bh4[2], bh4[3]);
                    mma_f16(acc[mt][2 * ng + 1], al[mt], bh4[2], bh4[3]);
                }
            }
        }
    }

    const int r0 = bm + warp_m * 32 + (lane >> 2);
    const int c0 = bn + warp_n * 64 + (lane & 3) * 2;
#pragma unroll
    for (int mt = 0; mt < 2; mt++) {
#pragma unroll
        for (int half = 0; half < 2; half++) {
            const int row = r0 + mt * 16 + half * 8;
            const int s = row & (SEQ - 1);
#pragma unroll
            for (int nt = 0; nt < 8; nt++) {
                const int col = c0 + nt * 8;
                float e  = acc[mt][nt][half * 2 + 0] + bias[col];
                float od = acc[mt][nt][half * 2 + 1] + bias[col + 1];
                if (mode == 1 || mode == 3) {
                    const int j = (col & (HD - 1)) >> 1;
                    const float sn = stab[(s << 6) + j];
                    const float cs2 = ctab[(s << 6) + j];
                    float re = e * cs2 - od * sn;
                    float ro = od * cs2 + e * sn;
                    e = re * oscale;
                    od = ro * oscale;
                }
                if (mode == 0) {
                    float2 r;
                    r.x = e; r.y = od;
                    *(float2*)(Yf + (size_t)row * HID + col) = r;
                } else if (mode == 3 || mode == 4) {
                    *(uint32_t*)(Yh + (size_t)row * HID + col) = pk2hf(e, od);
                } else {
                    __half h0, l0, h1, l1;
                    splith(e, h0, l0);
                    splith(od, h1, l1);
                    *(uint32_t*)(Yh + (size_t)row * HID + col) = pk2h(h0, h1);
                    *(uint32_t*)(Yl + (size_t)row * HID + col) = pk2h(l0, l1);
                }
            }
        }
    }
}

// Q scale folds softmax 1/sqrt(128) AND log2(e) (base-2 softmax)
#define QSCALE (0.08838834764831843f * 1.4426950408889634f)

__global__ void __launch_bounds__(256, 2) mma_gemm_qkv_kernel(
    const __nv_bfloat16* xh, const __nv_bfloat16* xl,
    const __nv_bfloat16* wqh, const __nv_bfloat16* wkh,
    const __nv_bfloat16* wvh,
    const float* bq, const float* bk, const float* bv,
    __nv_bfloat16* qh, __nv_bfloat16* ql,
    __nv_bfloat16* kh, __nv_bfloat16* vh,
    const float* stab, const float* ctab)
{
    if (blockIdx.z == 0)
        gemm_2p_body(xh, xl, wqh, bq, qh, ql, nullptr, QSCALE, stab, ctab, 1);
    else if (blockIdx.z == 1)
        gemm_2p_body(xh, xl, wkh, bk, kh, nullptr, nullptr, 1.0f, stab, ctab, 3);
    else
        gemm_2p_body(xh, xl, wvh, bv, vh, nullptr, nullptr, 1.0f, nullptr, nullptr, 4);
}

__global__ void __launch_bounds__(256, 2) mma_gemm_out_kernel(
    const __nv_bfloat16* ah, const __nv_bfloat16* al,
    const __nv_bfloat16* wh, const float* bo, float* Y)
{
    gemm_2p_body(ah, al, wh, bo, nullptr, nullptr, Y, 1.0f, nullptr, nullptr, 0);
}

// ---------------------------------------------------------------------------
// Flash attention v6: fp16 tensor-core.
// S = 2-product (qh+ql)*kh; PV = 1-product p*vh (V fp16-rounded, ~2.4e-4).
// Base-2 softmax, FMA-pipe exp. KV stage = [Kh][Vh] (34.8KB).
// ---------------------------------------------------------------------------
#define BR 128
#define BC 64
#define RQ 136
#define RB (RQ*2)
#define QBYTES (BR*RB)          // 34816
#define QTOT (2*QBYTES)         // 69632
#define KVT 17408               // one 64-row tile
#define KVSTG (2*KVT)           // 34816 : [Kh][Vh]
#define FL2_SMEM (QTOT + 2*KVSTG)   // 139264
#define NKT (SEQ/BC)            // 32

__global__ void __launch_bounds__(256, 1) flash2_kernel(
    const __nv_bfloat16* __restrict__ Qh, const __nv_bfloat16* __restrict__ Ql,
    const __nv_bfloat16* __restrict__ Kh,
    const __nv_bfloat16* __restrict__ Vh,
    __nv_bfloat16* __restrict__ CtxH, __nv_bfloat16* __restrict__ CtxL)
{
    extern __shared__ __align__(128) char smem[];
    const uint32_t sb = smem_to_u32(smem);
    const int tid = threadIdx.x;
    const int wid = tid >> 5, lane = tid & 31;
    const int bh = blockIdx.y;
    const int b = bh >> 4, h = bh & 15;
    const int q0 = blockIdx.x * BR;
    const size_t rowbase = (size_t)b * SEQ;
    const int coff = h * HD;

    {
        const int row = tid >> 1;
        const int ch0 = (tid & 1) * 8;
        const size_t gq = (rowbase + q0 + row) * HID + coff;
        const __nv_bfloat16* sh = Qh + gq;
        const __nv_bfloat16* sl = Ql + gq;
#pragma unroll
        for (int c = 0; c < 8; c++) {
            const int ch = ch0 + c;
            cp16(sb + row * RB + ch * 16, sh + ch * 8);
            cp16(sb + QBYTES + row * RB + ch * 16, sl + ch * 8);
        }
    }

    auto issue_kv = [&](int kt, int stg) {
        const int row = tid >> 2;
        const int cq = tid & 3;
        const size_t g = (rowbase + (size_t)kt * BC + row) * HID + coff;
        const uint32_t base = sb + QTOT + stg * KVSTG + row * RB;
#pragma unroll
        for (int c = 0; c < 4; c++) {
            const int ch = cq + c * 4;
            cp16(base + ch * 16,       Kh + g + ch * 8);
            cp16(base + KVT + ch * 16, Vh + g + ch * 8);
        }
    };

    issue_kv(0, 0);
    asm volatile("cp.async.commit_group;" ::: "memory");

    float m0 = -1e30f, m1 = -1e30f, l0 = 0.0f, l1 = 0.0f;
    float oacc[16][4];
#pragma unroll
    for (int nt = 0; nt < 16; nt++)
#pragma unroll
        for (int e = 0; e < 4; e++) oacc[nt][e] = 0.0f;

    const uint32_t qBh = sb + (wid * 16 + (lane & 15)) * RB + ((lane >> 4) * 8) * 2;
    const uint32_t qBl = qBh + QBYTES;
    const uint32_t kRel = (((lane >> 4) & 1) * 8 + (lane & 7)) * RB +
                          (((lane >> 3) & 1) * 8) * 2;
    const uint32_t vRel = (lane & 15) * RB + ((lane >> 4) * 8) * 2;

    for (int kt = 0; kt < NKT; kt++) {
        asm volatile("cp.async.wait_group 0;" ::: "memory");
        __syncthreads();
        if (kt + 1 < NKT) {
            issue_kv(kt + 1, (kt + 1) & 1);
            asm volatile("cp.async.commit_group;" ::: "memory");
        }

        const uint32_t kb = sb + QTOT + (kt & 1) * KVSTG;

        // ---- S = (Qh+Ql) Kh^T (fp16, 2 products); log2-domain scores ----
        float sacc[8][4];
#pragma unroll
        for (int nt = 0; nt < 8; nt++)
#pragma unroll
            for (int e = 0; e < 4; e++) sacc[nt][e] = 0.0f;

#pragma unroll
        for (int ks = 0; ks < 8; ks++) {
            uint32_t qa[4], ql4[4];
            ldsm_x4(qa, qBh + ks * 32);
            ldsm_x4(ql4, qBl + ks * 32);
#pragma unroll
            for (int ng = 0; ng < 4; ng++) {
                uint32_t bh4[4];
                const uint32_t ka = kb + kRel + ng * (16 * RB) + ks * 32;
                ldsm_x4(bh4, ka);
                mma_f16(sacc[2 * ng],     qa,  bh4[0], bh4[1]);
                mma_f16(sacc[2 * ng],     ql4, bh4[0], bh4[1]);
                mma_f16(sacc[2 * ng + 1], qa,  bh4[2], bh4[3]);
                mma_f16(sacc[2 * ng + 1], ql4, bh4[2], bh4[3]);
            }
        }

        // ---- row max + rescale ----
        float mx0 = -1e30f, mx1 = -1e30f;
#pragma unroll
        for (int nt = 0; nt < 8; nt++) {
            mx0 = fmaxf(mx0, fmaxf(sacc[nt][0], sacc[nt][1]));
            mx1 = fmaxf(mx1, fmaxf(sacc[nt][2], sacc[nt][3]));
        }
        mx0 = fmaxf(mx0, __shfl_xor_sync(0xffffffffu, mx0, 1));
        mx0 = fmaxf(mx0, __shfl_xor_sync(0xffffffffu, mx0, 2));
        mx1 = fmaxf(mx1, __shfl_xor_sync(0xffffffffu, mx1, 1));
        mx1 = fmaxf(mx1, __shfl_xor_sync(0xffffffffu, mx1, 2));

        const float mn0 = fmaxf(m0, mx0);
        const float mn1 = fmaxf(m1, mx1);
        const float corr0 = fexp2(m0 - mn0);
        const float corr1 = fexp2(m1 - mn1);
        m0 = mn0;
        m1 = mn1;
#pragma unroll
        for (int nt = 0; nt < 16; nt++) {
            oacc[nt][0] *= corr0;
            oacc[nt][1] *= corr0;
            oacc[nt][2] *= corr1;
            oacc[nt][3] *= corr1;
        }

        // ---- PV (fp16, 1 product: p*vh); exp interleaved ----
        const uint32_t vb = kb + KVT;
        float rs0 = 0.0f, rs1 = 0.0f;
#pragma unroll
        for (int ks2 = 0; ks2 < 4; ks2++) {
            uint32_t ah[4];
#pragma unroll
            for (int j = 0; j < 2; j++) {
                const int nt = 2 * ks2 + j;
                float p00 = fexp2(sacc[nt][0] - mn0);
                float p01 = fexp2(sacc[nt][1] - mn0);
                float p10 = fexp2(sacc[nt][2] - mn1);
                float p11 = fexp2(sacc[nt][3] - mn1);
                rs0 += p00 + p01;
                rs1 += p10 + p11;
                ah[2 * j]     = pk2hf(p00, p01);
                ah[2 * j + 1] = pk2hf(p10, p11);
            }
#pragma unroll
            for (int ng = 0; ng < 8; ng++) {
                uint32_t vh4[4];
                const uint32_t va = vb + vRel + ks2 * (16 * RB) + ng * 32;
                ldsm_x4_t(vh4, va);
                mma_f16(oacc[2 * ng],     ah, vh4[0], vh4[1]);
                mma_f16(oacc[2 * ng + 1], ah, vh4[2], vh4[3]);
            }
        }

        rs0 += __shfl_xor_sync(0xffffffffu, rs0, 1);
        rs0 += __shfl_xor_sync(0xffffffffu, rs0, 2);
        rs1 += __shfl_xor_sync(0xffffffffu, rs1, 1);
        rs1 += __shfl_xor_sync(0xffffffffu, rs1, 2);
        l0 = l0 * corr0 + rs0;
        l1 = l1 * corr1 + rs1;
    }

    const float inv0 = 1.0f / l0;
    const float inv1 = 1.0f / l1;
    const size_t row0 = rowbase + q0 + wid * 16 + (lane >> 2);
    const size_t row1 = row0 + 8;
    const int cb = coff + (lane & 3) * 2;
#pragma unroll
    for (int nt = 0; nt < 16; nt++) {
        const int col = cb + nt * 8;
        __half h0, lo0, h1, lo1;
        splith(oacc[nt][0] * inv0, h0, lo0);
        splith(oacc[nt][1] * inv0, h1, lo1);
        *(uint32_t*)(CtxH + row0 * HID + col) = pk2h(h0, h1);
        *(uint32_t*)(CtxL + row0 * HID + col) = pk2h(lo0, lo1);
        splith(oacc[nt][2] * inv1, h0, lo0);
        splith(oacc[nt][3] * inv1, h1, lo1);
        *(uint32_t*)(CtxH + row1 * HID + col) = pk2h(h0, h1);
        *(uint32_t*)(CtxL + row1 * HID + col) = pk2h(lo0, lo1);
    }
}

// ---------------------------------------------------------------------------
extern "C" void kernel_launch(void* const* d_in, const int* in_sizes, int n_in,
                              void* d_out, int out_size)
{
    const float* X  = (const float*)d_in[0];
    const float* Wq = (const float*)d_in[1];
    const float* bq = (const float*)d_in[2];
    const float* Wk = (const float*)d_in[3];
    const float* bk = (const float*)d_in[4];
    const float* Wv = (const float*)d_in[5];
    const float* bv = (const float*)d_in[6];
    const float* Wo = (const float*)d_in[7];
    const float* bo = (const float*)d_in[8];
    float* out = (float*)d_out;

    __nv_bfloat16 *xh, *xl, *wqh, *wkh, *wvh, *woh;
    __nv_bfloat16 *qh, *ql, *kh, *vh, *cxh, *cxl;
    float *stab, *ctab;
    cudaGetSymbolAddress((void**)&xh,  g_xh);
    cudaGetSymbolAddress((void**)&xl,  g_xl);
    cudaGetSymbolAddress((void**)&wqh, g_wqh);
    cudaGetSymbolAddress((void**)&wkh, g_wkh);
    cudaGetSymbolAddress((void**)&wvh, g_wvh);
    cudaGetSymbolAddress((void**)&woh, g_woh);
    cudaGetSymbolAddress((void**)&qh,  g_qh);
    cudaGetSymbolAddress((void**)&ql,  g_ql);
    cudaGetSymbolAddress((void**)&kh,  g_kh);
    cudaGetSymbolAddress((void**)&vh,  g_vh);
    cudaGetSymbolAddress((void**)&cxh, g_cxh);
    cudaGetSymbolAddress((void**)&cxl, g_cxl);
    cudaGetSymbolAddress((void**)&stab, g_sin);
    cudaGetSymbolAddress((void**)&ctab, g_cos);

    cudaFuncSetAttribute(mma_gemm_qkv_kernel,
                         cudaFuncAttributeMaxDynamicSharedMemorySize, GSMEMG);
    cudaFuncSetAttribute(mma_gemm_out_kernel,
                         cudaFuncAttributeMaxDynamicSharedMemorySize, GSMEMG);
    cudaFuncSetAttribute(flash2_kernel,
                         cudaFuncAttributeMaxDynamicSharedMemorySize, FL2_SMEM);

    // launch 0: RoPE table + X split fp16 (fused)
    prep0_kernel<<<512 + (int)(((size_t)M_ROWS * HID / 4) / 256), 256>>>(
        stab, ctab, (const float4*)X, (uint2*)xh, (uint2*)xl);

    // launch 1: transpose all 4 weights -> fp16 (hi only)
    {
        dim3 g(HID / 32, HID / 32, 4), blk(32, 8);
        wtrans4_kernel<<<g, blk>>>(Wq, wqh, Wk, wkh, Wv, wvh, Wo, woh);
    }

    // launch 2: dummy (keeps ncu capture idx 3 = qkv GEMM)
    dummy_kernel<<<1, 32>>>();

    // launch 3: QKV projections (fp16 2-product, BK=64) + bias + RoPE
    {
        dim3 grid(HID / 128, M_ROWS / 128, 3);
        mma_gemm_qkv_kernel<<<grid, 256, GSMEMG>>>(
            xh, xl, wqh, wkh, wvh, bq, bk, bv,
            qh, ql, kh, vh, stab, ctab);
    }

    // launch 4: flash attention (fp16, 2-product S, 1-product PV)
    {
        dim3 grid(SEQ / BR, BATCH * NH);
        flash2_kernel<<<grid, 256, FL2_SMEM>>>(qh, ql, kh, vh, cxh, cxl);
    }

    // launch 5: output projection (fp16 2-product, BK=64) + bias -> out
    {
        dim3 grid(HID / 128, M_ROWS / 128);
        mma_gemm_out_kernel<<<grid, 256, GSMEMG>>>(cxh, cxl, woh, bo, out);
    }
}

// round 17
// speedup vs baseline: 1.9532x; 1.0498x over previous
#include <cuda_runtime.h>
#include <cuda_bf16.h>
#include <cuda_fp16.h>
#include <cstdint>
#include <math.h>

#define HID 2048
#define SEQ 2048
#define NH  16
#define HD  128
#define BATCH 2
#define M_ROWS (BATCH*SEQ)   // 4096

// ---------------------------------------------------------------------------
// Scratch (__device__ globals). All split buffers hold PACKED FP16 bits.
// ---------------------------------------------------------------------------
__device__ __nv_bfloat16 g_xh[(size_t)M_ROWS * HID];
__device__ __nv_bfloat16 g_xl[(size_t)M_ROWS * HID];
__device__ __nv_bfloat16 g_wqh[(size_t)HID * HID];
__device__ __nv_bfloat16 g_wkh[(size_t)HID * HID];
__device__ __nv_bfloat16 g_wvh[(size_t)HID * HID];
__device__ __nv_bfloat16 g_woh[(size_t)HID * HID];
__device__ __nv_bfloat16 g_qh[(size_t)M_ROWS * HID];
__device__ __nv_bfloat16 g_ql[(size_t)M_ROWS * HID];
__device__ __nv_bfloat16 g_kh[(size_t)M_ROWS * HID];
__device__ __nv_bfloat16 g_vh[(size_t)M_ROWS * HID];
__device__ __nv_bfloat16 g_cxh[(size_t)M_ROWS * HID];
__device__ __nv_bfloat16 g_cxl[(size_t)M_ROWS * HID];
__device__ float g_sin[SEQ * (HD/2)];
__device__ float g_cos[SEQ * (HD/2)];

// ---------------------------------------------------------------------------
// helpers
// ---------------------------------------------------------------------------
__device__ __forceinline__ uint32_t smem_to_u32(const void* p) {
    uint32_t a;
    asm("{ .reg .u64 t; cvta.to.shared.u64 t, %1; cvt.u32.u64 %0, t; }"
        : "=r"(a) : "l"(p));
    return a;
}

__device__ __forceinline__ void cp16(uint32_t dst, const void* src) {
    asm volatile("cp.async.cg.shared.global [%0], [%1], 16;"
                 :: "r"(dst), "l"(src) : "memory");
}

__device__ __forceinline__ void ldsm_x4(uint32_t* r, uint32_t addr) {
    asm volatile("ldmatrix.sync.aligned.m8n8.x4.shared.b16 {%0,%1,%2,%3}, [%4];"
                 : "=r"(r[0]), "=r"(r[1]), "=r"(r[2]), "=r"(r[3]) : "r"(addr));
}

__device__ __forceinline__ void ldsm_x4_t(uint32_t* r, uint32_t addr) {
    asm volatile("ldmatrix.sync.aligned.m8n8.x4.trans.shared.b16 {%0,%1,%2,%3}, [%4];"
                 : "=r"(r[0]), "=r"(r[1]), "=r"(r[2]), "=r"(r[3]) : "r"(addr));
}

__device__ __forceinline__ void mma_f16(float* c, const uint32_t* a,
                                        uint32_t b0, uint32_t b1) {
    asm volatile(
        "mma.sync.aligned.m16n8k16.row.col.f32.f16.f16.f32 "
        "{%0,%1,%2,%3}, {%4,%5,%6,%7}, {%8,%9}, {%0,%1,%2,%3};"
        : "+f"(c[0]), "+f"(c[1]), "+f"(c[2]), "+f"(c[3])
        : "r"(a[0]), "r"(a[1]), "r"(a[2]), "r"(a[3]), "r"(b0), "r"(b1));
}

// fp16 split + pack
__device__ __forceinline__ void splith(float v, __half& h, __half& l) {
    h = __float2half_rn(v);
    l = __float2half_rn(v - __half2float(h));
}
__device__ __forceinline__ uint32_t pk2h(__half a, __half b) {
    __half2 t = __halves2half2(a, b);
    return *reinterpret_cast<uint32_t*>(&t);
}
__device__ __forceinline__ uint32_t pk2hf(float a, float b) {
    __half2 t = __floats2half2_rn(a, b);
    return *reinterpret_cast<uint32_t*>(&t);
}

// fast 2^t on the FMA pipe. t <= 0 expected; clamped at -30.
__device__ __forceinline__ float fexp2(float t) {
    t = fmaxf(t, -30.0f);
    const float fi = t + 12582912.0f;          // 1.5*2^23 round-to-int
    const float r  = fi - 12582912.0f;
    const float f  = t - r;
    float p = 1.3333558146e-3f;
    p = fmaf(p, f, 9.6181291076e-3f);
    p = fmaf(p, f, 5.5504108665e-2f);
    p = fmaf(p, f, 2.4022650696e-1f);
    p = fmaf(p, f, 6.9314718056e-1f);
    p = fmaf(p, f, 1.0f);
    const int e = __float_as_int(fi) - 0x4B400000;
    return __int_as_float(__float_as_int(p) + (e << 23));
}

// ---------------------------------------------------------------------------
// Prep kernel 0: RoPE table (blocks 0..511) + X split fp16 (blocks 512..)
// ---------------------------------------------------------------------------
__global__ void __launch_bounds__(256) prep0_kernel(
    float* __restrict__ st, float* __restrict__ ct,
    const float4* __restrict__ X, uint2* __restrict__ H, uint2* __restrict__ L)
{
    const int bid = blockIdx.x;
    if (bid < 512) {
        int idx = bid * 256 + threadIdx.x;   // SEQ*64 total
        int s = idx >> 6, j = idx & 63;
        double f = exp(-0.14391156831212787 * (double)j);  // 10000^(-2j/128)
        double sn, cs;
        sincos((double)s * f, &sn, &cs);
        st[idx] = (float)sn;
        ct[idx] = (float)cs;
    } else {
        size_t i = (size_t)(bid - 512) * 256 + threadIdx.x;
        float4 v = X[i];
        __half h0, l0, h1, l1, h2, l2, h3, l3;
        splith(v.x, h0, l0); splith(v.y, h1, l1);
        splith(v.z, h2, l2); splith(v.w, h3, l3);
        H[i] = make_uint2(pk2h(h0, h1), pk2h(h2, h3));
        L[i] = make_uint2(pk2h(l0, l1), pk2h(l2, l3));
    }
}

// Prep kernel 1: all four W [K][N] fp32 -> Wt [N][K] fp16 (hi only).
__global__ void __launch_bounds__(256) wtrans4_kernel(
    const float* __restrict__ W0, __nv_bfloat16* Th0,
    const float* __restrict__ W1, __nv_bfloat16* Th1,
    const float* __restrict__ W2, __nv_bfloat16* Th2,
    const float* __restrict__ W3, __nv_bfloat16* Th3)
{
    const float* W;
    __nv_bfloat16* Th;
    switch (blockIdx.z) {
        case 0:  W = W0; Th = Th0; break;
        case 1:  W = W1; Th = Th1; break;
        case 2:  W = W2; Th = Th2; break;
        default: W = W3; Th = Th3; break;
    }
    __shared__ float t[32][33];
    const int n0 = blockIdx.x * 32, k0 = blockIdx.y * 32;
    const int tx = threadIdx.x, ty = threadIdx.y;   // (32, 8)
#pragma unroll
    for (int i = 0; i < 4; i++)
        t[ty + 8 * i][tx] = W[(size_t)(k0 + ty + 8 * i) * HID + n0 + tx];
    __syncthreads();
#pragma unroll
    for (int i = 0; i < 4; i++) {
        float v = t[tx][ty + 8 * i];
        __half h = __float2half_rn(v);
        const size_t o = (size_t)(n0 + ty + 8 * i) * HID + k0 + tx;
        *(uint16_t*)(Th + o) = *(uint16_t*)&h;
    }
}

// tiny dummy to shift ncu capture index so idx 3 = qkv GEMM
__global__ void dummy_kernel() {}

// ---------------------------------------------------------------------------
// GEMM (fp16 2-product): Y = (Ah+Al) * Bh^T. 256 thr / 8 warps, 2 CTAs/SM.
// BM=128, BN=128, BK=32. Tiles [Ah][Al][Bh], 64B rows + XOR swizzle.
// Stage 24KB, FOUR stages, prefetch depth 3 (wait_group 2).   [R12 config]
// modes: 0 fp32(+bias); 1 rope+hi/lo; 2 bias+hi/lo; 3 rope+hi; 4 bias+hi.
// ---------------------------------------------------------------------------
#define TQ 8192
#define STGQ (3*TQ)                     // 24576
#define GSMEMQ (4*STGQ)                 // 98304
#define NKCHUNK (HID / 32)              // 64

__device__ __forceinline__ void gemm_2p_body(
    const __nv_bfloat16* __restrict__ Ah, const __nv_bfloat16* __restrict__ Al,
    const __nv_bfloat16* __restrict__ Bh,
    const float* __restrict__ bias,
    __nv_bfloat16* __restrict__ Yh, __nv_bfloat16* __restrict__ Yl,
    float* __restrict__ Yf, float oscale,
    const float* __restrict__ stab, const float* __restrict__ ctab, int mode)
{
    extern __shared__ __align__(128) char smem[];
    const uint32_t sb = smem_to_u32(smem);
    const int tid = threadIdx.x;
    const int wid = tid >> 5, lane = tid & 31;
    const int warp_m = wid & 3, warp_n = wid >> 2;   // 4 x 2 warps
    const int bm = blockIdx.y * 128, bn = blockIdx.x * 128;

    const int r2 = tid >> 1, seg = (tid & 1) * 2;
    const uint32_t xr2 = ((uint32_t)r2 >> 1) & 3;
    const uint32_t pc0 = ((uint32_t)(seg)     ^ xr2) << 4;
    const uint32_t pc1 = ((uint32_t)(seg | 1) ^ xr2) << 4;
    const uint32_t rowo = (uint32_t)r2 * 64;

    const uint32_t arow = (uint32_t)(warp_m * 32 + (lane & 15)) * 64;
    const uint32_t xrA = (((uint32_t)lane & 15) >> 1) & 3;
    const uint32_t hcA = (uint32_t)lane >> 4;
    const uint32_t axc0 = ((0 + hcA) ^ xrA) << 4;
    const uint32_t axc1 = ((2 + hcA) ^ xrA) << 4;
    const uint32_t brow = (uint32_t)(warp_n * 64 + ((lane >> 4) & 1) * 8 +
                                     (lane & 7)) * 64;
    const uint32_t xrB = (((uint32_t)lane & 7) >> 1) & 3;
    const uint32_t hcB = ((uint32_t)lane >> 3) & 1;
    const uint32_t bxc0 = ((0 + hcB) ^ xrB) << 4;
    const uint32_t bxc1 = ((2 + hcB) ^ xrB) << 4;

    float acc[2][8][4];
#pragma unroll
    for (int mt = 0; mt < 2; mt++)
#pragma unroll
        for (int nt = 0; nt < 8; nt++)
#pragma unroll
            for (int e = 0; e < 4; e++) acc[mt][nt][e] = 0.0f;

    auto issue = [&](int c, int stg) {
        const int k0 = c << 5;
        const uint32_t so = sb + stg * STGQ;
        const __nv_bfloat16* ahp = Ah + (size_t)(bm + r2) * HID + k0 + seg * 8;
        const __nv_bfloat16* alp = Al + (size_t)(bm + r2) * HID + k0 + seg * 8;
        const __nv_bfloat16* bhp = Bh + (size_t)(bn + r2) * HID + k0 + seg * 8;
        cp16(so + rowo + pc0,          ahp);
        cp16(so + rowo + pc1,          ahp + 8);
        cp16(so + TQ + rowo + pc0,     alp);
        cp16(so + TQ + rowo + pc1,     alp + 8);
        cp16(so + 2 * TQ + rowo + pc0, bhp);
        cp16(so + 2 * TQ + rowo + pc1, bhp + 8);
    };

#pragma unroll
    for (int s = 0; s < 3; s++) {
        issue(s, s);
        asm volatile("cp.async.commit_group;" ::: "memory");
    }

    for (int c = 0; c < NKCHUNK; c++) {
        asm volatile("cp.async.wait_group 2;" ::: "memory");
        __syncthreads();
        if (c + 3 < NKCHUNK) issue(c + 3, (c + 3) & 3);
        asm volatile("cp.async.commit_group;" ::: "memory");

        const uint32_t so = (c & 3) * STGQ;
        const uint32_t aB = sb + so + arow;
        const uint32_t bB = sb + so + 2 * TQ + brow;
#pragma unroll
        for (int ks = 0; ks < 2; ks++) {
            const uint32_t axc = ks ? axc1 : axc0;
            const uint32_t bxc = ks ? bxc1 : bxc0;
            uint32_t ah[2][4], al[2][4];
#pragma unroll
            for (int mt = 0; mt < 2; mt++) {
                ldsm_x4(ah[mt], aB + mt * 1024 + axc);
                ldsm_x4(al[mt], aB + TQ + mt * 1024 + axc);
            }
#pragma unroll
            for (int ng = 0; ng < 4; ng++) {
                uint32_t bh4[4];
                ldsm_x4(bh4, bB + ng * 1024 + bxc);
#pragma unroll
                for (int mt = 0; mt < 2; mt++) {
                    mma_f16(acc[mt][2 * ng],     ah[mt], bh4[0], bh4[1]);
                    mma_f16(acc[mt][2 * ng],     al[mt], bh4[0], bh4[1]);
                    mma_f16(acc[mt][2 * ng + 1], ah[mt], bh4[2], bh4[3]);
                    mma_f16(acc[mt][2 * ng + 1], al[mt], bh4[2], bh4[3]);
                }
            }
        }
    }

    const int r0 = bm + warp_m * 32 + (lane >> 2);
    const int c0 = bn + warp_n * 64 + (lane & 3) * 2;
#pragma unroll
    for (int mt = 0; mt < 2; mt++) {
#pragma unroll
        for (int half = 0; half < 2; half++) {
            const int row = r0 + mt * 16 + half * 8;
            const int s = row & (SEQ - 1);
#pragma unroll
            for (int nt = 0; nt < 8; nt++) {
                const int col = c0 + nt * 8;
                float e  = acc[mt][nt][half * 2 + 0] + bias[col];
                float od = acc[mt][nt][half * 2 + 1] + bias[col + 1];
                if (mode == 1 || mode == 3) {
                    const int j = (col & (HD - 1)) >> 1;
                    const float sn = stab[(s << 6) + j];
                    const float cs2 = ctab[(s << 6) + j];
                    float re = e * cs2 - od * sn;
                    float ro = od * cs2 + e * sn;
                    e = re * oscale;
                    od = ro * oscale;
                }
                if (mode == 0) {
                    float2 r;
                    r.x = e; r.y = od;
                    *(float2*)(Yf + (size_t)row * HID + col) = r;
                } else if (mode == 3 || mode == 4) {
                    *(uint32_t*)(Yh + (size_t)row * HID + col) = pk2hf(e, od);
                } else {
                    __half h0, l0, h1, l1;
                    splith(e, h0, l0);
                    splith(od, h1, l1);
                    *(uint32_t*)(Yh + (size_t)row * HID + col) = pk2h(h0, h1);
                    *(uint32_t*)(Yl + (size_t)row * HID + col) = pk2h(l0, l1);
                }
            }
        }
    }
}

// Q scale folds softmax 1/sqrt(128) AND log2(e) (base-2 softmax)
#define QSCALE (0.08838834764831843f * 1.4426950408889634f)

__global__ void __launch_bounds__(256, 2) mma_gemm_qkv_kernel(
    const __nv_bfloat16* xh, const __nv_bfloat16* xl,
    const __nv_bfloat16* wqh, const __nv_bfloat16* wkh,
    const __nv_bfloat16* wvh,
    const float* bq, const float* bk, const float* bv,
    __nv_bfloat16* qh, __nv_bfloat16* ql,
    __nv_bfloat16* kh, __nv_bfloat16* vh,
    const float* stab, const float* ctab)
{
    if (blockIdx.z == 0)
        gemm_2p_body(xh, xl, wqh, bq, qh, ql, nullptr, QSCALE, stab, ctab, 1);
    else if (blockIdx.z == 1)
        gemm_2p_body(xh, xl, wkh, bk, kh, nullptr, nullptr, 1.0f, stab, ctab, 3);
    else
        gemm_2p_body(xh, xl, wvh, bv, vh, nullptr, nullptr, 1.0f, nullptr, nullptr, 4);
}

__global__ void __launch_bounds__(256, 2) mma_gemm_out_kernel(
    const __nv_bfloat16* ah, const __nv_bfloat16* al,
    const __nv_bfloat16* wh, const float* bo, float* Y)
{
    gemm_2p_body(ah, al, wh, bo, nullptr, nullptr, Y, 1.0f, nullptr, nullptr, 0);
}

// ---------------------------------------------------------------------------
// Flash attention v6 (unchanged from R16): fp16 tensor-core.
// S = 2-product (qh+ql)*kh; PV = 1-product p*vh. Base-2 softmax.
// KV stage = [Kh][Vh] (34.8KB).
// ---------------------------------------------------------------------------
#define BR 128
#define BC 64
#define RQ 136
#define RB (RQ*2)
#define QBYTES (BR*RB)          // 34816
#define QTOT (2*QBYTES)         // 69632
#define KVT 17408               // one 64-row tile
#define KVSTG (2*KVT)           // 34816 : [Kh][Vh]
#define FL2_SMEM (QTOT + 2*KVSTG)   // 139264
#define NKT (SEQ/BC)            // 32

__global__ void __launch_bounds__(256, 1) flash2_kernel(
    const __nv_bfloat16* __restrict__ Qh, const __nv_bfloat16* __restrict__ Ql,
    const __nv_bfloat16* __restrict__ Kh,
    const __nv_bfloat16* __restrict__ Vh,
    __nv_bfloat16* __restrict__ CtxH, __nv_bfloat16* __restrict__ CtxL)
{
    extern __shared__ __align__(128) char smem[];
    const uint32_t sb = smem_to_u32(smem);
    const int tid = threadIdx.x;
    const int wid = tid >> 5, lane = tid & 31;
    const int bh = blockIdx.y;
    const int b = bh >> 4, h = bh & 15;
    const int q0 = blockIdx.x * BR;
    const size_t rowbase = (size_t)b * SEQ;
    const int coff = h * HD;

    {
        const int row = tid >> 1;
        const int ch0 = (tid & 1) * 8;
        const size_t gq = (rowbase + q0 + row) * HID + coff;
        const __nv_bfloat16* sh = Qh + gq;
        const __nv_bfloat16* sl = Ql + gq;
#pragma unroll
        for (int c = 0; c < 8; c++) {
            const int ch = ch0 + c;
            cp16(sb + row * RB + ch * 16, sh + ch * 8);
            cp16(sb + QBYTES + row * RB + ch * 16, sl + ch * 8);
        }
    }

    auto issue_kv = [&](int kt, int stg) {
        const int row = tid >> 2;
        const int cq = tid & 3;
        const size_t g = (rowbase + (size_t)kt * BC + row) * HID + coff;
        const uint32_t base = sb + QTOT + stg * KVSTG + row * RB;
#pragma unroll
        for (int c = 0; c < 4; c++) {
            const int ch = cq + c * 4;
            cp16(base + ch * 16,       Kh + g + ch * 8);
            cp16(base + KVT + ch * 16, Vh + g + ch * 8);
        }
    };

    issue_kv(0, 0);
    asm volatile("cp.async.commit_group;" ::: "memory");

    float m0 = -1e30f, m1 = -1e30f, l0 = 0.0f, l1 = 0.0f;
    float oacc[16][4];
#pragma unroll
    for (int nt = 0; nt < 16; nt++)
#pragma unroll
        for (int e = 0; e < 4; e++) oacc[nt][e] = 0.0f;

    const uint32_t qBh = sb + (wid * 16 + (lane & 15)) * RB + ((lane >> 4) * 8) * 2;
    const uint32_t qBl = qBh + QBYTES;
    const uint32_t kRel = (((lane >> 4) & 1) * 8 + (lane & 7)) * RB +
                          (((lane >> 3) & 1) * 8) * 2;
    const uint32_t vRel = (lane & 15) * RB + ((lane >> 4) * 8) * 2;

    for (int kt = 0; kt < NKT; kt++) {
        asm volatile("cp.async.wait_group 0;" ::: "memory");
        __syncthreads();
        if (kt + 1 < NKT) {
            issue_kv(kt + 1, (kt + 1) & 1);
            asm volatile("cp.async.commit_group;" ::: "memory");
        }

        const uint32_t kb = sb + QTOT + (kt & 1) * KVSTG;

        float sacc[8][4];
#pragma unroll
        for (int nt = 0; nt < 8; nt++)
#pragma unroll
            for (int e = 0; e < 4; e++) sacc[nt][e] = 0.0f;

#pragma unroll
        for (int ks = 0; ks < 8; ks++) {
            uint32_t qa[4], ql4[4];
            ldsm_x4(qa, qBh + ks * 32);
            ldsm_x4(ql4, qBl + ks * 32);
#pragma unroll
            for (int ng = 0; ng < 4; ng++) {
                uint32_t bh4[4];
                const uint32_t ka = kb + kRel + ng * (16 * RB) + ks * 32;
                ldsm_x4(bh4, ka);
                mma_f16(sacc[2 * ng],     qa,  bh4[0], bh4[1]);
                mma_f16(sacc[2 * ng],     ql4, bh4[0], bh4[1]);
                mma_f16(sacc[2 * ng + 1], qa,  bh4[2], bh4[3]);
                mma_f16(sacc[2 * ng + 1], ql4, bh4[2], bh4[3]);
            }
        }

        float mx0 = -1e30f, mx1 = -1e30f;
#pragma unroll
        for (int nt = 0; nt < 8; nt++) {
            mx0 = fmaxf(mx0, fmaxf(sacc[nt][0], sacc[nt][1]));
            mx1 = fmaxf(mx1, fmaxf(sacc[nt][2], sacc[nt][3]));
        }
        mx0 = fmaxf(mx0, __shfl_xor_sync(0xffffffffu, mx0, 1));
        mx0 = fmaxf(mx0, __shfl_xor_sync(0xffffffffu, mx0, 2));
        mx1 = fmaxf(mx1, __shfl_xor_sync(0xffffffffu, mx1, 1));
        mx1 = fmaxf(mx1, __shfl_xor_sync(0xffffffffu, mx1, 2));

        const float mn0 = fmaxf(m0, mx0);
        const float mn1 = fmaxf(m1, mx1);
        const float corr0 = fexp2(m0 - mn0);
        const float corr1 = fexp2(m1 - mn1);
        m0 = mn0;
        m1 = mn1;
#pragma unroll
        for (int nt = 0; nt < 16; nt++) {
            oacc[nt][0] *= corr0;
            oacc[nt][1] *= corr0;
            oacc[nt][2] *= corr1;
            oacc[nt][3] *= corr1;
        }

        const uint32_t vb = kb + KVT;
        float rs0 = 0.0f, rs1 = 0.0f;
#pragma unroll
        for (int ks2 = 0; ks2 < 4; ks2++) {
            uint32_t ah[4];
#pragma unroll
            for (int j = 0; j < 2; j++) {
                const int nt = 2 * ks2 + j;
                float p00 = fexp2(sacc[nt][0] - mn0);
                float p01 = fexp2(sacc[nt][1] - mn0);
                float p10 = fexp2(sacc[nt][2] - mn1);
                float p11 = fexp2(sacc[nt][3] - mn1);
                rs0 += p00 + p01;
                rs1 += p10 + p11;
                ah[2 * j]     = pk2hf(p00, p01);
                ah[2 * j + 1] = pk2hf(p10, p11);
            }
#pragma unroll
            for (int ng = 0; ng < 8; ng++) {
                uint32_t vh4[4];
                const uint32_t va = vb + vRel + ks2 * (16 * RB) + ng * 32;
                ldsm_x4_t(vh4, va);
                mma_f16(oacc[2 * ng],     ah, vh4[0], vh4[1]);
                mma_f16(oacc[2 * ng + 1], ah, vh4[2], vh4[3]);
            }
        }

        rs0 += __shfl_xor_sync(0xffffffffu, rs0, 1);
        rs0 += __shfl_xor_sync(0xffffffffu, rs0, 2);
        rs1 += __shfl_xor_sync(0xffffffffu, rs1, 1);
        rs1 += __shfl_xor_sync(0xffffffffu, rs1, 2);
        l0 = l0 * corr0 + rs0;
        l1 = l1 * corr1 + rs1;
    }

    const float inv0 = 1.0f / l0;
    const float inv1 = 1.0f / l1;
    const size_t row0 = rowbase + q0 + wid * 16 + (lane >> 2);
    const size_t row1 = row0 + 8;
    const int cb = coff + (lane & 3) * 2;
#pragma unroll
    for (int nt = 0; nt < 16; nt++) {
        const int col = cb + nt * 8;
        __half h0, lo0, h1, lo1;
        splith(oacc[nt][0] * inv0, h0, lo0);
        splith(oacc[nt][1] * inv0, h1, lo1);
        *(uint32_t*)(CtxH + row0 * HID + col) = pk2h(h0, h1);
        *(uint32_t*)(CtxL + row0 * HID + col) = pk2h(lo0, lo1);
        splith(oacc[nt][2] * inv1, h0, lo0);
        splith(oacc[nt][3] * inv1, h1, lo1);
        *(uint32_t*)(CtxH + row1 * HID + col) = pk2h(h0, h1);
        *(uint32_t*)(CtxL + row1 * HID + col) = pk2h(lo0, lo1);
    }
}

// ---------------------------------------------------------------------------
extern "C" void kernel_launch(void* const* d_in, const int* in_sizes, int n_in,
                              void* d_out, int out_size)
{
    const float* X  = (const float*)d_in[0];
    const float* Wq = (const float*)d_in[1];
    const float* bq = (const float*)d_in[2];
    const float* Wk = (const float*)d_in[3];
    const float* bk = (const float*)d_in[4];
    const float* Wv = (const float*)d_in[5];
    const float* bv = (const float*)d_in[6];
    const float* Wo = (const float*)d_in[7];
    const float* bo = (const float*)d_in[8];
    float* out = (float*)d_out;

    __nv_bfloat16 *xh, *xl, *wqh, *wkh, *wvh, *woh;
    __nv_bfloat16 *qh, *ql, *kh, *vh, *cxh, *cxl;
    float *stab, *ctab;
    cudaGetSymbolAddress((void**)&xh,  g_xh);
    cudaGetSymbolAddress((void**)&xl,  g_xl);
    cudaGetSymbolAddress((void**)&wqh, g_wqh);
    cudaGetSymbolAddress((void**)&wkh, g_wkh);
    cudaGetSymbolAddress((void**)&wvh, g_wvh);
    cudaGetSymbolAddress((void**)&woh, g_woh);
    cudaGetSymbolAddress((void**)&qh,  g_qh);
    cudaGetSymbolAddress((void**)&ql,  g_ql);
    cudaGetSymbolAddress((void**)&kh,  g_kh);
    cudaGetSymbolAddress((void**)&vh,  g_vh);
    cudaGetSymbolAddress((void**)&cxh, g_cxh);
    cudaGetSymbolAddress((void**)&cxl, g_cxl);
    cudaGetSymbolAddress((void**)&stab, g_sin);
    cudaGetSymbolAddress((void**)&ctab, g_cos);

    cudaFuncSetAttribute(mma_gemm_qkv_kernel,
                         cudaFuncAttributeMaxDynamicSharedMemorySize, GSMEMQ);
    cudaFuncSetAttribute(mma_gemm_out_kernel,
                         cudaFuncAttributeMaxDynamicSharedMemorySize, GSMEMQ);
    cudaFuncSetAttribute(flash2_kernel,
                         cudaFuncAttributeMaxDynamicSharedMemorySize, FL2_SMEM);

    // launch 0: RoPE table + X split fp16 (fused)
    prep0_kernel<<<512 + (int)(((size_t)M_ROWS * HID / 4) / 256), 256>>>(
        stab, ctab, (const float4*)X, (uint2*)xh, (uint2*)xl);

    // launch 1: transpose all 4 weights -> fp16 (hi only)
    {
        dim3 g(HID / 32, HID / 32, 4), blk(32, 8);
        wtrans4_kernel<<<g, blk>>>(Wq, wqh, Wk, wkh, Wv, wvh, Wo, woh);
    }

    // launch 2: dummy (keeps ncu capture idx 3 = qkv GEMM)
    dummy_kernel<<<1, 32>>>();

    // launch 3: QKV projections (fp16 2-product, BK=32/4-stage) + bias + RoPE
    {
        dim3 grid(HID / 128, M_ROWS / 128, 3);
        mma_gemm_qkv_kernel<<<grid, 256, GSMEMQ>>>(
            xh, xl, wqh, wkh, wvh, bq, bk, bv,
            qh, ql, kh, vh, stab, ctab);
    }

    // launch 4: flash attention (fp16, 2-product S, 1-product PV)
    {
        dim3 grid(SEQ / BR, BATCH * NH);
        flash2_kernel<<<grid, 256, FL2_SMEM>>>(qh, ql, kh, vh, cxh, cxl);
    }

    // launch 5: output projection (fp16 2-product, BK=32/4-stage) + bias -> out
    {
        dim3 grid(HID / 128, M_ROWS / 128);
        mma_gemm_out_kernel<<<grid, 256, GSMEMQ>>>(cxh, cxl, woh, bo, out);
    }
}